// round 4
// baseline (speedup 1.0000x reference)
#include <cuda_runtime.h>
#include <math.h>

#define NT 256
#define PAD 68
#define XTSZ (128 * PAD)           // 8704 floats per activation buffer
#define SMEM_FLOATS 50176
#define SMEM_BYTES (SMEM_FLOATS * 4)

// ---------------- folded-weight scratch ----------------
__device__ float g_A1[128 * 128];
__device__ float g_A2[128 * 128];
__device__ float g_b1[128];

__global__ void prep_kernel(const float* __restrict__ npW, const float* __restrict__ npb,
                            const float* __restrict__ epW, const float* __restrict__ epb,
                            const float* __restrict__ im1W, const float* __restrict__ im1b)
{
    const int i = blockIdx.x;
    const int o = threadIdx.x;
    float s1 = 0.f, s2 = 0.f;
    for (int h = 0; h < 128; ++h) {
        s1 += npW[i * 128 + h] * im1W[h * 128 + o];
        s2 += epW[i * 128 + h] * im1W[(128 + h) * 128 + o];
    }
    g_A1[i * 128 + o] = s1;
    g_A2[i * 128 + o] = s2;
    if (i == 0) {
        float sb = im1b[o];
        for (int h = 0; h < 128; ++h)
            sb += npb[h] * im1W[h * 128 + o] + epb[h] * im1W[(128 + h) * 128 + o];
        g_b1[o] = sb;
    }
}

struct Params {
    const float *src, *dst, *edge;
    const float *im2W, *im2b, *mp1W, *mp1b, *mp2W, *mp2b;
    const float *qW, *qb, *kW, *kb, *vW, *vb;
    const float *ntcW, *ntcb, *ctoW, *ctob, *outW, *outb;
    float* out;
    int B;
};

// ---------------- f32x2 helpers ----------------
union F2U { float2 f; unsigned long long u; };

__device__ __forceinline__ unsigned long long dup2(float x) {
    F2U u; u.f.x = x; u.f.y = x; return u.u;
}

#define FMA2(d, a, b) asm("fma.rn.f32x2 %0, %1, %2, %0;" : "+l"(d) : "l"(a), "l"(b))

// ---------------- global -> transposed smem tile ----------------
__device__ __forceinline__ void load_tile(float* __restrict__ XT, const float* __restrict__ g,
                                          int rows, int tid)
{
#pragma unroll
    for (int i = 0; i < 8; ++i) {
        int f4 = tid + i * NT;                 // 2048 float4 = 64x128
        int r = f4 >> 5;
        int cc = (f4 & 31) << 2;
        float4 v = make_float4(0.f, 0.f, 0.f, 0.f);
        if (r < rows) v = *(const float4*)(g + r * 128 + cc);
        XT[(cc + 0) * PAD + r] = v.x;
        XT[(cc + 1) * PAD + r] = v.y;
        XT[(cc + 2) * PAD + r] = v.z;
        XT[(cc + 3) * PAD + r] = v.w;
    }
}

// ---------------- weight staging (duplicated f32x2 pairs), double-buffered ----------------
__device__ __forceinline__ void stg_store(unsigned long long* __restrict__ buf,
                                          const float4* __restrict__ pv, int tid)
{
#pragma unroll
    for (int i = 0; i < 4; ++i) {
        int e = tid + i * NT;                  // 1024 float4 = 32x128 chunk
        int k = e >> 5;
        int c4 = (e & 31) << 2;
        float4 v = pv[i];
        ulonglong2 d0; d0.x = dup2(v.x); d0.y = dup2(v.y);
        ulonglong2 d1; d1.x = dup2(v.z); d1.y = dup2(v.w);
        *(ulonglong2*)(buf + k * 128 + c4)     = d0;
        *(ulonglong2*)(buf + k * 128 + c4 + 2) = d1;
    }
}

__device__ __forceinline__ void init_bias2(unsigned long long acc[8][2],
                                           const float* __restrict__ bg, int cl2)
{
    unsigned long long b0 = dup2(__ldg(bg + cl2));
    unsigned long long b1 = dup2(__ldg(bg + cl2 + 1));
#pragma unroll
    for (int p = 0; p < 8; ++p) { acc[p][0] = b0; acc[p][1] = b1; }
}

__device__ __forceinline__ void init_zero2(unsigned long long acc[8][2])
{
#pragma unroll
    for (int p = 0; p < 8; ++p) { acc[p][0] = 0ull; acc[p][1] = 0ull; }
}

// acc += XT[64x128]^T-layout @ Wg[128x128] ; packed rows (f32x2), dup'd B
__device__ __forceinline__ void gemm_acc2(unsigned long long acc[8][2],
                                          const float* __restrict__ XT,
                                          const float* __restrict__ Wg,
                                          unsigned long long* __restrict__ WSH2,
                                          int tid, int rg16, int cl2)
{
    float4 pv[4];
#pragma unroll
    for (int i = 0; i < 4; ++i)
        pv[i] = *(const float4*)(Wg + (tid + i * NT) * 4);
    stg_store(WSH2, pv, tid);
    __syncthreads();

#pragma unroll
    for (int ch = 0; ch < 4; ++ch) {
        if (ch < 3) {
#pragma unroll
            for (int i = 0; i < 4; ++i)
                pv[i] = *(const float4*)(Wg + (ch + 1) * 32 * 128 + (tid + i * NT) * 4);
        }
        const unsigned long long* buf = WSH2 + (ch & 1) * 4096;
        const float* xb = XT + ch * 32 * PAD + rg16;
#pragma unroll 4
        for (int kk = 0; kk < 32; ++kk) {
            const float* xk = xb + kk * PAD;
            ulonglong2 a0 = *(const ulonglong2*)(xk);
            ulonglong2 a1 = *(const ulonglong2*)(xk + 4);
            ulonglong2 a2 = *(const ulonglong2*)(xk + 8);
            ulonglong2 a3 = *(const ulonglong2*)(xk + 12);
            ulonglong2 b  = *(const ulonglong2*)(buf + kk * 128 + cl2);
            FMA2(acc[0][0], a0.x, b.x); FMA2(acc[0][1], a0.x, b.y);
            FMA2(acc[1][0], a0.y, b.x); FMA2(acc[1][1], a0.y, b.y);
            FMA2(acc[2][0], a1.x, b.x); FMA2(acc[2][1], a1.x, b.y);
            FMA2(acc[3][0], a1.y, b.x); FMA2(acc[3][1], a1.y, b.y);
            FMA2(acc[4][0], a2.x, b.x); FMA2(acc[4][1], a2.x, b.y);
            FMA2(acc[5][0], a2.y, b.x); FMA2(acc[5][1], a2.y, b.y);
            FMA2(acc[6][0], a3.x, b.x); FMA2(acc[6][1], a3.x, b.y);
            FMA2(acc[7][0], a3.y, b.x); FMA2(acc[7][1], a3.y, b.y);
        }
        if (ch < 3) {
            stg_store(WSH2 + ((ch + 1) & 1) * 4096, pv, tid);
            __syncthreads();
        }
    }
    __syncthreads();
}

__device__ __forceinline__ void store_act2(const unsigned long long acc[8][2],
                                           float* __restrict__ Out, int rg16, int cl2, bool relu)
{
#pragma unroll
    for (int p = 0; p < 8; ++p) {
        int rb = rg16 + 2 * p;
#pragma unroll
        for (int c = 0; c < 2; ++c) {
            F2U u; u.u = acc[p][c];
            float2 f = u.f;
            if (relu) { f.x = fmaxf(f.x, 0.f); f.y = fmaxf(f.y, 0.f); }
            *(float2*)(Out + (cl2 + c) * PAD + rb) = f;
        }
    }
}

// ---------------- small 128->16 GEMMs ----------------
__device__ __forceinline__ void small_stage(float* __restrict__ WS, const float* __restrict__ Wg,
                                            int tid)
{
    for (int e = tid; e < 2048; e += NT)
        WS[(e >> 4) * 17 + (e & 15)] = Wg[e];
}

__device__ __forceinline__ void small_compute(float* __restrict__ Out, const float* __restrict__ XT,
                                              const float* __restrict__ WS,
                                              const float* __restrict__ bg, int tid, bool do_tanh)
{
    const int r = tid >> 2;
    const int cb = (tid & 3) * 4;
    float a0 = __ldg(bg + cb + 0);
    float a1 = __ldg(bg + cb + 1);
    float a2 = __ldg(bg + cb + 2);
    float a3 = __ldg(bg + cb + 3);
#pragma unroll 4
    for (int k = 0; k < 128; ++k) {
        float x = XT[k * PAD + r];
        const float* w = WS + k * 17 + cb;
        a0 = fmaf(x, w[0], a0);
        a1 = fmaf(x, w[1], a1);
        a2 = fmaf(x, w[2], a2);
        a3 = fmaf(x, w[3], a3);
    }
    if (do_tanh) { a0 = tanhf(a0); a1 = tanhf(a1); a2 = tanhf(a2); a3 = tanhf(a3); }
    float* o = Out + r * 16 + cb;
    o[0] = a0; o[1] = a1; o[2] = a2; o[3] = a3;
}

// ---------------- per-row metric + clifford products ----------------
__device__ __forceinline__ void clifford_row(int r, const float* __restrict__ M16s,
                                             float* __restrict__ SCs, float* __restrict__ DCs,
                                             float* __restrict__ IPs, float* __restrict__ SCO,
                                             const float* __restrict__ GSt,
                                             const float* __restrict__ WTt)
{
    float m[4][4];
#pragma unroll
    for (int a = 0; a < 4; ++a)
#pragma unroll
        for (int b = 0; b < 4; ++b) m[a][b] = M16s[r * 16 + a * 4 + b];

    float L[4][4];
#pragma unroll
    for (int a = 0; a < 4; ++a)
#pragma unroll
        for (int b = 0; b < 4; ++b) {
            if (a > b)       L[a][b] = m[a][b];
            else if (a == b) L[a][b] = log1pf(expf(m[a][a])) + 1e-6f;
            else             L[a][b] = 0.f;
        }
    float met[4][4];
#pragma unroll
    for (int a = 0; a < 4; ++a)
#pragma unroll
        for (int b = 0; b < 4; ++b) {
            float s = 0.f;
#pragma unroll
            for (int c = 0; c < 4; ++c) s = fmaf(L[a][c], L[b][c], s);
            met[a][b] = s;
        }

    const int VI[4] = {1, 2, 4, 8};
#pragma unroll
    for (int t = 0; t < 2; ++t) {
        float* X = t ? DCs : SCs;
        float vin[4], vo[4];
#pragma unroll
        for (int a = 0; a < 4; ++a) vin[a] = X[r * 16 + VI[a]];
#pragma unroll
        for (int a = 0; a < 4; ++a) {
            float s = 0.f;
#pragma unroll
            for (int b = 0; b < 4; ++b) s = fmaf(met[a][b], vin[b], s);
            vo[a] = s;
        }
#pragma unroll
        for (int a = 0; a < 4; ++a) X[r * 16 + VI[a]] = vo[a];
    }

    float enh = 0.f;
    for (int k = 0; k < 16; ++k) {
        float gpk = 0.f, gprk = 0.f, opk = 0.f;
        for (int i = 0; i < 16; ++i) {
            int j = i ^ k;
            float si = SCs[r * 16 + i], sj = SCs[r * 16 + j];
            float di = DCs[r * 16 + i], dj = DCs[r * 16 + j];
            float gs = GSt[i * 16 + j];
            gpk  = fmaf(gs, si * dj, gpk);
            gprk = fmaf(gs, di * sj, gprk);
            opk  = fmaf(WTt[i * 16 + j], si * dj, opk);
        }
        IPs[r * 16 + k] = 0.5f * (gpk + gprk);
        enh += gpk + opk;
    }
#pragma unroll
    for (int h = 0; h < 8; ++h) SCO[r * 8 + h] = enh;
}

// ---------------- fused kernel ----------------
__global__ __launch_bounds__(NT) void fused_kernel(Params p)
{
    extern __shared__ float sm[];
    float* XT_S = sm;                       // src -> att
    float* XT_E = sm + XTSZ;                // edge -> h2 -> dst
    float* XT_B = sm + 2 * XTSZ;            // h1 -> h3 -> Q
    unsigned long long* WSH2 = (unsigned long long*)(sm + 26112);   // 2 x 4096 ull
    float* WS   = (float*)WSH2;             // reuse for small-W staging
    float* CTOs = sm + 42496;               // 16x128
    float* M16s = sm + 44544;               // 64x16
    float* SCs  = sm + 45568;
    float* DCs  = sm + 46592;
    float* IPs  = sm + 47616;
    float* SCO  = sm + 48640;               // 64x8
    float* W8s  = sm + 49152;               // 64x8
    float* GSt  = sm + 49664;               // 16x16
    float* WTt  = sm + 49920;               // 16x16

    const int tid = threadIdx.x;
    const int rg16 = (tid >> 6) * 16;       // 4 row groups of 16 rows
    const int cl = tid & 63;                // 64 col-pairs
    const int cl2 = cl * 2;
    const int row0 = blockIdx.x * 64;
    const int rows = min(64, p.B - row0);

    // sign tables (MSB-first convention)
    {
        int i = tid >> 4, j = tid & 15;
        if (tid < 256) {
            float s = 1.f;
#pragma unroll
            for (int k = 0; k < 4; ++k)
                if ((j >> (3 - k)) & 1)
                    if (__popc(i >> (4 - k)) & 1) s = -s;
            GSt[tid] = s;
            float w = 0.f;
            if ((i & j) == 0) {
                int inv = 0;
#pragma unroll
                for (int k = 0; k < 4; ++k)
                    if ((i >> (3 - k)) & 1) inv += __popc(j & ((1 << (3 - k)) - 1));
                w = (inv & 1) ? -1.f : 1.f;
            }
            WTt[tid] = w;
        }
    }
    for (int e = tid; e < 2048; e += NT) CTOs[e] = p.ctoW[e];
    for (int e = tid; e < 512; e += NT) SCO[e] = 0.f;

    load_tile(XT_S, p.src  + (size_t)row0 * 128, rows, tid);
    load_tile(XT_E, p.edge + (size_t)row0 * 128, rows, tid);

    unsigned long long acc[8][2];

    // h1 = relu(src@A1 + edge@A2 + b1) -> XT_B
    init_bias2(acc, g_b1, cl2);
    gemm_acc2(acc, XT_S, g_A1, WSH2, tid, rg16, cl2);
    gemm_acc2(acc, XT_E, g_A2, WSH2, tid, rg16, cl2);
    store_act2(acc, XT_B, rg16, cl2, true);

    // h2 = relu(h1@im2W + b) -> XT_E
    init_bias2(acc, p.im2b, cl2);
    gemm_acc2(acc, XT_B, p.im2W, WSH2, tid, rg16, cl2);
    store_act2(acc, XT_E, rg16, cl2, true);

    // h3 = relu(h2@mp1W + b) -> XT_B
    init_bias2(acc, p.mp1b, cl2);
    gemm_acc2(acc, XT_E, p.mp1W, WSH2, tid, rg16, cl2);
    store_act2(acc, XT_B, rg16, cl2, true);
    __syncthreads();

    // m16 = tanh(h3@mp2W + b)
    small_stage(WS, p.mp2W, tid);
    __syncthreads();
    small_compute(M16s, XT_B, WS, p.mp2b, tid, true);
    // dst -> XT_E (h2 dead)
    load_tile(XT_E, p.dst + (size_t)row0 * 128, rows, tid);
    __syncthreads();

    // sc = src@ntcW + b ; dc = dst@ntcW + b
    small_stage(WS, p.ntcW, tid);
    __syncthreads();
    small_compute(SCs, XT_S, WS, p.ntcb, tid, false);
    small_compute(DCs, XT_E, WS, p.ntcb, tid, false);
    __syncthreads();

    if (tid < 64 && tid < rows)
        clifford_row(tid, M16s, SCs, DCs, IPs, SCO, GSt, WTt);
    __syncthreads();

    // Q = src@qW + b -> XT_B (h3 dead)
    init_bias2(acc, p.qb, cl2);
    gemm_acc2(acc, XT_S, p.qW, WSH2, tid, rg16, cl2);
    store_act2(acc, XT_B, rg16, cl2, false);

    // K GEMM with fused Q.K score epilogue
    init_bias2(acc, p.kb, cl2);
    gemm_acc2(acc, XT_E, p.kW, WSH2, tid, rg16, cl2);
    {
        const int h = cl >> 3;               // 16 cols per head, 2 cols/thread
#pragma unroll
        for (int pp = 0; pp < 8; ++pp) {
            int rb = rg16 + 2 * pp;
            float2 q0 = *(const float2*)(XT_B + (cl2 + 0) * PAD + rb);
            float2 q1 = *(const float2*)(XT_B + (cl2 + 1) * PAD + rb);
            F2U k0; k0.u = acc[pp][0];
            F2U k1; k1.u = acc[pp][1];
            float de = fmaf(k0.f.x, q0.x, k1.f.x * q1.x);
            float do_ = fmaf(k0.f.y, q0.y, k1.f.y * q1.y);
            atomicAdd(&SCO[rb * 8 + h], 0.25f * de);
            atomicAdd(&SCO[(rb + 1) * 8 + h], 0.25f * do_);
        }
    }
    __syncthreads();

    // softmax over 8 heads
    if (tid < 64) {
        float s0[8];
        float mx = -1e30f;
#pragma unroll
        for (int h = 0; h < 8; ++h) { s0[h] = SCO[tid * 8 + h]; mx = fmaxf(mx, s0[h]); }
        float sum = 0.f;
#pragma unroll
        for (int h = 0; h < 8; ++h) { s0[h] = expf(s0[h] - mx); sum += s0[h]; }
        float inv = 1.f / sum;
#pragma unroll
        for (int h = 0; h < 8; ++h) W8s[tid * 8 + h] = s0[h] * inv;
    }
    __syncthreads();

    // V GEMM with fused attention weights -> att in XT_S (src dead)
    init_bias2(acc, p.vb, cl2);
    gemm_acc2(acc, XT_E, p.vW, WSH2, tid, rg16, cl2);
    {
        const int h = cl >> 3;
#pragma unroll
        for (int pp = 0; pp < 8; ++pp) {
            int rb = rg16 + 2 * pp;
            float w0 = W8s[rb * 8 + h];
            float w1 = W8s[(rb + 1) * 8 + h];
#pragma unroll
            for (int c = 0; c < 2; ++c) {
                F2U u; u.u = acc[pp][c];
                float2 o; o.x = u.f.x * w0; o.y = u.f.y * w1;
                *(float2*)(XT_S + (cl2 + c) * PAD + rb) = o;
            }
        }
    }
    __syncthreads();

    // out = att@outW + out_b + ip@ctoW + cto_b
    init_zero2(acc);
    gemm_acc2(acc, XT_S, p.outW, WSH2, tid, rg16, cl2);
    {
        float bc[2], ct[2][16];
#pragma unroll
        for (int c = 0; c < 2; ++c) {
            bc[c] = __ldg(p.outb + cl2 + c) + __ldg(p.ctob + cl2 + c);
#pragma unroll
            for (int k = 0; k < 16; ++k) ct[c][k] = CTOs[k * 128 + cl2 + c];
        }
#pragma unroll
        for (int pp = 0; pp < 8; ++pp) {
            int rb = rg16 + 2 * pp;
            float ip0[16], ip1[16];
#pragma unroll
            for (int k = 0; k < 16; ++k) {
                ip0[k] = IPs[rb * 16 + k];
                ip1[k] = IPs[(rb + 1) * 16 + k];
            }
#pragma unroll
            for (int c = 0; c < 2; ++c) {
                F2U u; u.u = acc[pp][c];
                float v0 = u.f.x + bc[c];
                float v1 = u.f.y + bc[c];
#pragma unroll
                for (int k = 0; k < 16; ++k) {
                    v0 = fmaf(ip0[k], ct[c][k], v0);
                    v1 = fmaf(ip1[k], ct[c][k], v1);
                }
                if (rb < rows)     p.out[(size_t)(row0 + rb) * 128 + cl2 + c] = v0;
                if (rb + 1 < rows) p.out[(size_t)(row0 + rb + 1) * 128 + cl2 + c] = v1;
            }
        }
    }
}

// ---------------- launch ----------------
extern "C" void kernel_launch(void* const* d_in, const int* in_sizes, int n_in,
                              void* d_out, int out_size)
{
    const float* src  = (const float*)d_in[0];
    const float* dst  = (const float*)d_in[1];
    const float* edge = (const float*)d_in[2];
    const float* npW  = (const float*)d_in[3];
    const float* npb  = (const float*)d_in[4];
    const float* epW  = (const float*)d_in[5];
    const float* epb  = (const float*)d_in[6];
    const float* im1W = (const float*)d_in[7];
    const float* im1b = (const float*)d_in[8];
    const float* im2W = (const float*)d_in[9];
    const float* im2b = (const float*)d_in[10];
    const float* mp1W = (const float*)d_in[11];
    const float* mp1b = (const float*)d_in[12];
    const float* mp2W = (const float*)d_in[13];
    const float* mp2b = (const float*)d_in[14];
    const float* qW   = (const float*)d_in[15];
    const float* qb   = (const float*)d_in[16];
    const float* kW   = (const float*)d_in[17];
    const float* kb   = (const float*)d_in[18];
    const float* vW   = (const float*)d_in[19];
    const float* vb   = (const float*)d_in[20];
    const float* ntcW = (const float*)d_in[21];
    const float* ntcb = (const float*)d_in[22];
    const float* ctoW = (const float*)d_in[23];
    const float* ctob = (const float*)d_in[24];
    const float* outW = (const float*)d_in[25];
    const float* outb = (const float*)d_in[26];

    const int B = in_sizes[0] / 128;

    cudaFuncSetAttribute(fused_kernel, cudaFuncAttributeMaxDynamicSharedMemorySize, SMEM_BYTES);

    prep_kernel<<<128, 128>>>(npW, npb, epW, epb, im1W, im1b);

    Params p;
    p.src = src; p.dst = dst; p.edge = edge;
    p.im2W = im2W; p.im2b = im2b; p.mp1W = mp1W; p.mp1b = mp1b;
    p.mp2W = mp2W; p.mp2b = mp2b;
    p.qW = qW; p.qb = qb; p.kW = kW; p.kb = kb; p.vW = vW; p.vb = vb;
    p.ntcW = ntcW; p.ntcb = ntcb; p.ctoW = ctoW; p.ctob = ctob;
    p.outW = outW; p.outb = outb;
    p.out = (float*)d_out; p.B = B;

    fused_kernel<<<(B + 63) / 64, NT, SMEM_BYTES>>>(p);
}

// round 6
// speedup vs baseline: 3.2940x; 3.2940x over previous
#include <cuda_runtime.h>
#include <cuda_bf16.h>
#include <math.h>
#include <stdint.h>

#define STRIDE 152                  // bf16 elems per tile row (incl. ip cols + pad)
// ---- smem byte offsets ----
#define TSH 0
#define TSL 19456
#define TDH 38912
#define TDL 58368
#define TXH 77824
#define TXL 97280
#define RING0 116736
#define RING1 153600
#define SMW_NTC 190464              // ntc frag hi(4096)+lo(4096)
#define SMW_MP2 198656              // mp2 frag hi+lo
#define BIA_B 207872                // 928 floats
#define SCO_B 211584                // 64x8 f32
#define GST_B 213632                // 256 f32
#define SCS_B 214656                // 64x16 f32
#define DCS_B 218752
#define M16_B 222848
#define SMEM_BYTES 226944

// ---- gmem weight buffer layout ----
// slots 0..6 (A1,A2,im2,mp1,qW,kW,vW): g*65536 {hi 32768, lo 32768}
// slot 7 (outW+ctoW, 9 ktiles): 458752 {hi 36864, lo 36864}
// ntc frags: 532480 {hi 4096, lo 4096}; mp2: 540672 {hi, lo}
__device__ float g_A1[128 * 128];
__device__ float g_A2[128 * 128];
__device__ float g_b1[128];
__device__ __align__(128) unsigned char g_wb[548864];

// ---------- helpers ----------
__device__ __forceinline__ uint32_t smem_u32(const void* p) {
    uint32_t a;
    asm("{ .reg .u64 t; cvta.to.shared.u64 t, %1; cvt.u32.u64 %0, t; }" : "=r"(a) : "l"(p));
    return a;
}
template<int N> __device__ __forceinline__ void cp_wait() {
    asm volatile("cp.async.wait_group %0;" :: "n"(N));
}
__device__ __forceinline__ void stage_fn(uint32_t dsm, uint64_t gsrc, int bytes, int tid) {
    for (int o = tid * 16; o < bytes; o += 4096)
        asm volatile("cp.async.cg.shared.global [%0], [%1], 16;" :: "r"(dsm + o), "l"(gsrc + o) : "memory");
    asm volatile("cp.async.commit_group;" ::: "memory");
}
__device__ __forceinline__ void mma16816(float* c, uint32_t a0, uint32_t a1, uint32_t a2, uint32_t a3,
                                         uint32_t b0, uint32_t b1) {
    asm volatile("mma.sync.aligned.m16n8k16.row.col.f32.bf16.bf16.f32 "
                 "{%0,%1,%2,%3}, {%4,%5,%6,%7}, {%8,%9}, {%0,%1,%2,%3};"
                 : "+f"(c[0]), "+f"(c[1]), "+f"(c[2]), "+f"(c[3])
                 : "r"(a0), "r"(a1), "r"(a2), "r"(a3), "r"(b0), "r"(b1));
}
__device__ __host__ __forceinline__ uint32_t frag_off(int k, int n, int ntiles) {
    int kt = k >> 4, kk = k & 15;
    int reg = kk >> 3, r8 = kk & 7, m = r8 >> 1, half = r8 & 1;
    int nt = n >> 3, ln = (n & 7) * 4 + m;
    return (uint32_t)((kt * ntiles + nt) * 32 + ln) * 8u + (uint32_t)reg * 4u + (uint32_t)half * 2u;
}
__device__ __forceinline__ uint32_t pack_bf2(float a, float b) {
    __nv_bfloat162 t;
    t.x = __float2bfloat16_rn(a);
    t.y = __float2bfloat16_rn(b);
    return *(uint32_t*)&t;
}
__device__ __forceinline__ void split_bf(float v, float& hi, float& lo) {
    __nv_bfloat16 h = __float2bfloat16_rn(v);
    hi = __bfloat162float(h);
    lo = v - hi;
}

// ---------- prep kernels ----------
__global__ void prep1(const float* __restrict__ npW, const float* __restrict__ npb,
                      const float* __restrict__ epW, const float* __restrict__ epb,
                      const float* __restrict__ im1W, const float* __restrict__ im1b)
{
    const int i = blockIdx.x, o = threadIdx.x;
    float s1 = 0.f, s2 = 0.f;
    for (int h = 0; h < 128; ++h) {
        s1 += npW[i * 128 + h] * im1W[h * 128 + o];
        s2 += epW[i * 128 + h] * im1W[(128 + h) * 128 + o];
    }
    g_A1[i * 128 + o] = s1;
    g_A2[i * 128 + o] = s2;
    if (i == 0) {
        float sb = im1b[o];
        for (int h = 0; h < 128; ++h)
            sb += npb[h] * im1W[h * 128 + o] + epb[h] * im1W[(128 + h) * 128 + o];
        g_b1[o] = sb;
    }
}

struct PrepPtrs { const float *im2W, *mp1W, *qW, *kW, *vW, *outW, *ctoW, *mp2W, *ntcW; };

__global__ void prep2(PrepPtrs pp)
{
    const int b = blockIdx.x;
    if (b < 7) {
        const float* W = nullptr;
        switch (b) { case 2: W = pp.im2W; break; case 3: W = pp.mp1W; break;
                     case 4: W = pp.qW; break; case 5: W = pp.kW; break;
                     case 6: W = pp.vW; break; default: break; }
        unsigned char* base = g_wb + b * 65536;
        for (int idx = threadIdx.x; idx < 16384; idx += blockDim.x) {
            int k = idx >> 7, n = idx & 127;
            float v = (b == 0) ? g_A1[idx] : (b == 1) ? g_A2[idx] : W[idx];
            float h, l; split_bf(v, h, l);
            uint32_t off = frag_off(k, n, 16);
            *(__nv_bfloat16*)(base + off) = __float2bfloat16_rn(h);
            *(__nv_bfloat16*)(base + 32768 + off) = __float2bfloat16_rn(l);
        }
    } else if (b == 7) {
        unsigned char* base = g_wb + 458752;
        for (int idx = threadIdx.x; idx < 144 * 128; idx += blockDim.x) {
            int k = idx >> 7, n = idx & 127;
            float v = (k < 128) ? pp.outW[k * 128 + n] : pp.ctoW[(k - 128) * 128 + n];
            float h, l; split_bf(v, h, l);
            uint32_t off = frag_off(k, n, 16);
            *(__nv_bfloat16*)(base + off) = __float2bfloat16_rn(h);
            *(__nv_bfloat16*)(base + 36864 + off) = __float2bfloat16_rn(l);
        }
    } else {
        const float* W = (b == 8) ? pp.ntcW : pp.mp2W;
        unsigned char* base = g_wb + ((b == 8) ? 532480 : 540672);
        for (int idx = threadIdx.x; idx < 2048; idx += blockDim.x) {
            int k = idx >> 4, n = idx & 15;
            float v = W[idx];
            float h, l; split_bf(v, h, l);
            uint32_t off = frag_off(k, n, 2);
            *(__nv_bfloat16*)(base + off) = __float2bfloat16_rn(h);
            *(__nv_bfloat16*)(base + 4096 + off) = __float2bfloat16_rn(l);
        }
    }
}

// ---------- GEMM pieces ----------
template<int NKT>
__device__ __forceinline__ void gemm_pass(float (&acc)[8][4], const char* A, const char* slot,
                                          int wm, int wn, int lane)
{
    const int r1 = wm * 16 + (lane >> 2);
    const int m2 = (lane & 3) * 2;
#pragma unroll
    for (int kt = 0; kt < NKT; ++kt) {
        const char* Ar = A + (r1 * STRIDE + kt * 16 + m2) * 2;
        uint32_t a0 = *(const uint32_t*)(Ar);
        uint32_t a1 = *(const uint32_t*)(Ar + 8 * STRIDE * 2);
        uint32_t a2 = *(const uint32_t*)(Ar + 16);
        uint32_t a3 = *(const uint32_t*)(Ar + 8 * STRIDE * 2 + 16);
        const char* Bp = slot + ((kt * 16 + wn * 8) * 32 + lane) * 8;
#pragma unroll
        for (int nt = 0; nt < 8; ++nt) {
            uint2 b = *(const uint2*)(Bp + nt * 256);
            mma16816(acc[nt], a0, a1, a2, a3, b.x, b.y);
        }
    }
}
__device__ __forceinline__ void small_pass(float (&acc)[2][4], const char* A, const char* slot,
                                           int wm, int lane)
{
    const int r1 = wm * 16 + (lane >> 2);
    const int m2 = (lane & 3) * 2;
#pragma unroll
    for (int kt = 0; kt < 8; ++kt) {
        const char* Ar = A + (r1 * STRIDE + kt * 16 + m2) * 2;
        uint32_t a0 = *(const uint32_t*)(Ar);
        uint32_t a1 = *(const uint32_t*)(Ar + 8 * STRIDE * 2);
        uint32_t a2 = *(const uint32_t*)(Ar + 16);
        uint32_t a3 = *(const uint32_t*)(Ar + 8 * STRIDE * 2 + 16);
        const char* Bp = slot + (kt * 2 * 32 + lane) * 8;
#pragma unroll
        for (int nt = 0; nt < 2; ++nt) {
            uint2 b = *(const uint2*)(Bp + nt * 256);
            mma16816(acc[nt], a0, a1, a2, a3, b.x, b.y);
        }
    }
}
__device__ __forceinline__ void zero8(float (&a)[8][4]) {
#pragma unroll
    for (int i = 0; i < 8; ++i)
#pragma unroll
        for (int j = 0; j < 4; ++j) a[i][j] = 0.f;
}
__device__ __forceinline__ void store_tile(const float (&acc)[8][4], char* SM, int tH, int tL,
                                           const float* bias, bool relu, int wm, int wn, int lane)
{
    const int r1 = wm * 16 + (lane >> 2), r2 = r1 + 8;
    const int m2 = (lane & 3) * 2;
#pragma unroll
    for (int nt = 0; nt < 8; ++nt) {
        int cb = wn * 64 + nt * 8 + m2;
        float b0 = bias[cb], b1 = bias[cb + 1];
        float v0 = acc[nt][0] + b0, v1 = acc[nt][1] + b1;
        float v2 = acc[nt][2] + b0, v3 = acc[nt][3] + b1;
        if (relu) { v0 = fmaxf(v0, 0.f); v1 = fmaxf(v1, 0.f); v2 = fmaxf(v2, 0.f); v3 = fmaxf(v3, 0.f); }
        float h0, l0, h1, l1;
        split_bf(v0, h0, l0); split_bf(v1, h1, l1);
        *(uint32_t*)(SM + tH + (r1 * STRIDE + cb) * 2) = pack_bf2(h0, h1);
        *(uint32_t*)(SM + tL + (r1 * STRIDE + cb) * 2) = pack_bf2(l0, l1);
        split_bf(v2, h0, l0); split_bf(v3, h1, l1);
        *(uint32_t*)(SM + tH + (r2 * STRIDE + cb) * 2) = pack_bf2(h0, h1);
        *(uint32_t*)(SM + tL + (r2 * STRIDE + cb) * 2) = pack_bf2(l0, l1);
    }
}
__device__ __forceinline__ void store_small(const float (&acc)[2][4], float* out,
                                            const float* bias, bool dot, int wm, int lane)
{
    const int r1 = wm * 16 + (lane >> 2), r2 = r1 + 8;
    const int m2 = (lane & 3) * 2;
#pragma unroll
    for (int nt = 0; nt < 2; ++nt) {
        int c = nt * 8 + m2;
        float b0 = bias[c], b1 = bias[c + 1];
        float v0 = acc[nt][0] + b0, v1 = acc[nt][1] + b1;
        float v2 = acc[nt][2] + b0, v3 = acc[nt][3] + b1;
        if (dot) { v0 = tanhf(v0); v1 = tanhf(v1); v2 = tanhf(v2); v3 = tanhf(v3); }
        *(float2*)(out + r1 * 16 + c) = make_float2(v0, v1);
        *(float2*)(out + r2 * 16 + c) = make_float2(v2, v3);
    }
}
__device__ __forceinline__ void convert_tile(char* SM, int tH, int tL,
                                             const float* __restrict__ g, int rows, int tid)
{
#pragma unroll
    for (int i = 0; i < 8; ++i) {
        int f4 = tid + i * 256;
        int r = f4 >> 5, c4 = (f4 & 31) << 2;
        float4 v = make_float4(0.f, 0.f, 0.f, 0.f);
        if (r < rows) v = *(const float4*)(g + (size_t)r * 128 + c4);
        float h0, l0, h1, l1, h2, l2, h3, l3;
        split_bf(v.x, h0, l0); split_bf(v.y, h1, l1);
        split_bf(v.z, h2, l2); split_bf(v.w, h3, l3);
        uint2 uh, ul;
        uh.x = pack_bf2(h0, h1); uh.y = pack_bf2(h2, h3);
        ul.x = pack_bf2(l0, l1); ul.y = pack_bf2(l2, l3);
        *(uint2*)(SM + tH + (r * STRIDE + c4) * 2) = uh;
        *(uint2*)(SM + tL + (r * STRIDE + c4) * 2) = ul;
    }
}

struct Params {
    const float *src, *dst, *edge;
    const float *im2b, *mp1b, *mp2b, *qb, *kb, *vb, *ntcb, *ctob, *outb;
    float* out;
    int B;
};

__global__ __launch_bounds__(256, 1) void fused_kernel(Params p)
{
    extern __shared__ __align__(16) char SM[];
    const int tid = threadIdx.x, lane = tid & 31, wid = tid >> 5;
    const int wm = wid & 3, wn = wid >> 2;
    const int row0 = blockIdx.x * 64;
    const int rows = min(64, p.B - row0);
    const uint32_t sbase = smem_u32(SM);
    const uint64_t gaddr = (uint64_t)__cvta_generic_to_global((void*)g_wb);
    float* BIA = (float*)(SM + BIA_B);
    float* SCO = (float*)(SM + SCO_B);
    float* GST = (float*)(SM + GST_B);

#define STAGE(slot, goff, bytes) stage_fn(sbase + (slot), gaddr + (goff), (bytes), tid)

    STAGE(SMW_NTC, 532480, 16384);          // group: small frag weights
    STAGE(RING0, 0, 32768);                 // group: A1 hi

    if (tid < 128) {
        BIA[tid] = g_b1[tid];          BIA[128 + tid] = p.im2b[tid];
        BIA[256 + tid] = p.mp1b[tid];  BIA[384 + tid] = p.qb[tid];
        BIA[512 + tid] = p.kb[tid];    BIA[640 + tid] = p.vb[tid];
        BIA[768 + tid] = p.outb[tid] + p.ctob[tid];
    }
    if (tid < 16) { BIA[896 + tid] = p.mp2b[tid]; BIA[912 + tid] = p.ntcb[tid]; }
    {   // geometric-product sign table (MSB-first bit convention)
        int i = tid >> 4, j = tid & 15;
        float s = 1.f;
#pragma unroll
        for (int k = 0; k < 4; ++k)
            if ((j >> (3 - k)) & 1)
                if (__popc(i >> (4 - k)) & 1) s = -s;
        GST[tid] = s;
    }
    convert_tile(SM, TSH, TSL, p.src  + (size_t)row0 * 128, rows, tid);
    convert_tile(SM, TXH, TXL, p.edge + (size_t)row0 * 128, rows, tid);
    convert_tile(SM, TDH, TDL, p.dst  + (size_t)row0 * 128, rows, tid);
    cp_wait<1>();
    __syncthreads();                        // small weights + tiles ready

    // ---- sc (wn=0) / dc (wn=1): 128->16 via mma ----
    {
        float a2[2][4] = {};
        const char* AH = SM + ((wn == 0) ? TSH : TDH);
        const char* AL = SM + ((wn == 0) ? TSL : TDL);
        small_pass(a2, AH, SM + SMW_NTC, wm, lane);
        small_pass(a2, AL, SM + SMW_NTC, wm, lane);
        small_pass(a2, AH, SM + SMW_NTC + 4096, wm, lane);
        store_small(a2, (float*)(SM + ((wn == 0) ? SCS_B : DCS_B)), BIA + 912, false, wm, lane);
    }

    float acc[8][4];
    zero8(acc);
    // ---- G1: h1 = relu(src@A1 + edge@A2 + b1) ----
    STAGE(RING1, 32768, 32768);  cp_wait<1>(); __syncthreads();
    gemm_pass<8>(acc, SM + TSH, SM + RING0, wm, wn, lane);
    gemm_pass<8>(acc, SM + TSL, SM + RING0, wm, wn, lane);
    __syncthreads();
    STAGE(RING0, 65536, 32768);  cp_wait<1>(); __syncthreads();
    gemm_pass<8>(acc, SM + TSH, SM + RING1, wm, wn, lane);
    __syncthreads();
    STAGE(RING1, 98304, 32768);  cp_wait<1>(); __syncthreads();
    gemm_pass<8>(acc, SM + TXH, SM + RING0, wm, wn, lane);
    gemm_pass<8>(acc, SM + TXL, SM + RING0, wm, wn, lane);
    __syncthreads();
    STAGE(RING0, 131072, 32768); cp_wait<1>(); __syncthreads();
    gemm_pass<8>(acc, SM + TXH, SM + RING1, wm, wn, lane);
    __syncthreads();
    store_tile(acc, SM, TXH, TXL, BIA + 0, true, wm, wn, lane);
    __syncthreads();

    // ---- G2: h2 = relu(h1@im2) ----
    zero8(acc);
    STAGE(RING1, 163840, 32768); cp_wait<1>(); __syncthreads();
    gemm_pass<8>(acc, SM + TXH, SM + RING0, wm, wn, lane);
    gemm_pass<8>(acc, SM + TXL, SM + RING0, wm, wn, lane);
    __syncthreads();
    STAGE(RING0, 196608, 32768); cp_wait<1>(); __syncthreads();
    gemm_pass<8>(acc, SM + TXH, SM + RING1, wm, wn, lane);
    __syncthreads();
    store_tile(acc, SM, TXH, TXL, BIA + 128, true, wm, wn, lane);
    __syncthreads();

    // ---- G3: h3 = relu(h2@mp1) ----
    zero8(acc);
    STAGE(RING1, 229376, 32768); cp_wait<1>(); __syncthreads();
    gemm_pass<8>(acc, SM + TXH, SM + RING0, wm, wn, lane);
    gemm_pass<8>(acc, SM + TXL, SM + RING0, wm, wn, lane);
    __syncthreads();
    STAGE(RING0, 262144, 32768); cp_wait<1>(); __syncthreads();
    gemm_pass<8>(acc, SM + TXH, SM + RING1, wm, wn, lane);
    __syncthreads();
    store_tile(acc, SM, TXH, TXL, BIA + 256, true, wm, wn, lane);
    __syncthreads();

    // ---- m16 = tanh(h3@mp2 + b) (wn=0 warps) ----
    if (wn == 0) {
        float a2[2][4] = {};
        small_pass(a2, SM + TXH, SM + SMW_MP2, wm, lane);
        small_pass(a2, SM + TXL, SM + SMW_MP2, wm, lane);
        small_pass(a2, SM + TXH, SM + SMW_MP2 + 4096, wm, lane);
        store_small(a2, (float*)(SM + M16_B), BIA + 896, true, wm, lane);
    }
    __syncthreads();

    // ---- clifford: metric + adapted inner product -> ip into TX cols 128..143 ----
    if (tid < 64) {
        const float* M16 = (float*)(SM + M16_B);
        const float* SCS = (float*)(SM + SCS_B);
        const float* DCS = (float*)(SM + DCS_B);
        int r = tid;
        float m[16], s[16], d[16];
#pragma unroll
        for (int k = 0; k < 16; ++k) {
            m[k] = M16[r * 16 + k];
            s[k] = SCS[r * 16 + k];
            d[k] = DCS[r * 16 + k];
        }
        float L[4][4];
#pragma unroll
        for (int a = 0; a < 4; ++a)
#pragma unroll
            for (int b = 0; b < 4; ++b) {
                float mv = m[a * 4 + b];
                L[a][b] = (a > b) ? mv : (a == b) ? (log1pf(expf(mv)) + 1e-6f) : 0.f;
            }
        float met[4][4];
#pragma unroll
        for (int a = 0; a < 4; ++a)
#pragma unroll
            for (int b = 0; b < 4; ++b) {
                float q = 0.f;
#pragma unroll
                for (int c = 0; c < 4; ++c) q = fmaf(L[a][c], L[b][c], q);
                met[a][b] = q;
            }
        const int VI[4] = {1, 2, 4, 8};
        float sv[4], dv[4];
#pragma unroll
        for (int a = 0; a < 4; ++a) {
            float qs = 0.f, qd = 0.f;
#pragma unroll
            for (int b = 0; b < 4; ++b) {
                qs = fmaf(met[a][b], s[VI[b]], qs);
                qd = fmaf(met[a][b], d[VI[b]], qd);
            }
            sv[a] = qs; dv[a] = qd;
        }
#pragma unroll
        for (int a = 0; a < 4; ++a) { s[VI[a]] = sv[a]; d[VI[a]] = dv[a]; }
#pragma unroll
        for (int k = 0; k < 16; ++k) {
            float q = 0.f;
#pragma unroll
            for (int i = 0; i < 16; ++i) {
                int j = i ^ k;
                q = fmaf(GST[i * 16 + j], fmaf(s[i], d[j], d[i] * s[j]), q);
            }
            float ip = 0.5f * q, h, l;
            split_bf(ip, h, l);
            *(__nv_bfloat16*)(SM + TXH + (r * STRIDE + 128 + k) * 2) = __float2bfloat16_rn(h);
            *(__nv_bfloat16*)(SM + TXL + (r * STRIDE + 128 + k) * 2) = __float2bfloat16_rn(l);
        }
    }
    __syncthreads();

    // ---- Q = src@qW (kept in registers) ----
    float accQ[8][4];
    zero8(accQ);
    STAGE(RING1, 294912, 32768); cp_wait<1>(); __syncthreads();
    gemm_pass<8>(accQ, SM + TSH, SM + RING0, wm, wn, lane);
    gemm_pass<8>(accQ, SM + TSL, SM + RING0, wm, wn, lane);
    __syncthreads();
    STAGE(RING0, 327680, 32768); cp_wait<1>(); __syncthreads();
    gemm_pass<8>(accQ, SM + TSH, SM + RING1, wm, wn, lane);
    __syncthreads();

    // ---- K = dst@kW ----
    float accK[8][4];
    zero8(accK);
    STAGE(RING1, 360448, 32768); cp_wait<1>(); __syncthreads();
    gemm_pass<8>(accK, SM + TDH, SM + RING0, wm, wn, lane);
    gemm_pass<8>(accK, SM + TDL, SM + RING0, wm, wn, lane);
    __syncthreads();
    STAGE(RING0, 393216, 32768); cp_wait<1>(); __syncthreads();
    gemm_pass<8>(accK, SM + TDH, SM + RING1, wm, wn, lane);

    // ---- scores = (Q+qb).(K+kb)/4 per head (enh cancels in softmax) ----
    {
        const int r1 = wm * 16 + (lane >> 2), r2 = r1 + 8;
        const int m = lane & 3, m2 = m * 2;
#pragma unroll
        for (int e = 0; e < 4; ++e) {
            float p1 = 0.f, p2 = 0.f;
#pragma unroll
            for (int t2 = 0; t2 < 2; ++t2) {
                int nt = 2 * e + t2, cb = wn * 64 + nt * 8 + m2;
                float qb0 = BIA[384 + cb], qb1 = BIA[384 + cb + 1];
                float kb0 = BIA[512 + cb], kb1 = BIA[512 + cb + 1];
                p1 += (accQ[nt][0] + qb0) * (accK[nt][0] + kb0) + (accQ[nt][1] + qb1) * (accK[nt][1] + kb1);
                p2 += (accQ[nt][2] + qb0) * (accK[nt][2] + kb0) + (accQ[nt][3] + qb1) * (accK[nt][3] + kb1);
            }
            p1 += __shfl_xor_sync(0xFFFFFFFFu, p1, 1);
            p1 += __shfl_xor_sync(0xFFFFFFFFu, p1, 2);
            p2 += __shfl_xor_sync(0xFFFFFFFFu, p2, 1);
            p2 += __shfl_xor_sync(0xFFFFFFFFu, p2, 2);
            if (m == 0) {
                int h = wn * 4 + e;
                SCO[r1 * 8 + h] = 0.25f * p1;
                SCO[r2 * 8 + h] = 0.25f * p2;
            }
        }
    }
    __syncthreads();
    if (tid < 64) {
        float s0[8], mx = -1e30f;
#pragma unroll
        for (int h = 0; h < 8; ++h) { s0[h] = SCO[tid * 8 + h]; mx = fmaxf(mx, s0[h]); }
        float sum = 0.f;
#pragma unroll
        for (int h = 0; h < 8; ++h) { s0[h] = expf(s0[h] - mx); sum += s0[h]; }
        float inv = 1.f / sum;
#pragma unroll
        for (int h = 0; h < 8; ++h) SCO[tid * 8 + h] = s0[h] * inv;
    }
    __syncthreads();

    // ---- V = dst@vW ; att = w8*(V+vb) -> TX ----
    zero8(acc);
    STAGE(RING1, 425984, 32768); cp_wait<1>(); __syncthreads();
    gemm_pass<8>(acc, SM + TDH, SM + RING0, wm, wn, lane);
    gemm_pass<8>(acc, SM + TDL, SM + RING0, wm, wn, lane);
    __syncthreads();
    STAGE(RING0, 458752, 36864); cp_wait<1>(); __syncthreads();
    gemm_pass<8>(acc, SM + TDH, SM + RING1, wm, wn, lane);
    __syncthreads();
    {
        const int r1 = wm * 16 + (lane >> 2), r2 = r1 + 8;
        const int m2 = (lane & 3) * 2;
#pragma unroll
        for (int nt = 0; nt < 8; ++nt) {
            int cb = wn * 64 + nt * 8 + m2;
            int h = wn * 4 + (nt >> 1);
            float w1 = SCO[r1 * 8 + h], w2 = SCO[r2 * 8 + h];
            float b0 = BIA[640 + cb], b1 = BIA[640 + cb + 1];
            float v0 = (acc[nt][0] + b0) * w1, v1 = (acc[nt][1] + b1) * w1;
            float v2 = (acc[nt][2] + b0) * w2, v3 = (acc[nt][3] + b1) * w2;
            float h0, l0, h1, l1;
            split_bf(v0, h0, l0); split_bf(v1, h1, l1);
            *(uint32_t*)(SM + TXH + (r1 * STRIDE + cb) * 2) = pack_bf2(h0, h1);
            *(uint32_t*)(SM + TXL + (r1 * STRIDE + cb) * 2) = pack_bf2(l0, l1);
            split_bf(v2, h0, l0); split_bf(v3, h1, l1);
            *(uint32_t*)(SM + TXH + (r2 * STRIDE + cb) * 2) = pack_bf2(h0, h1);
            *(uint32_t*)(SM + TXL + (r2 * STRIDE + cb) * 2) = pack_bf2(l0, l1);
        }
    }
    __syncthreads();

    // ---- out = [att|ip]@[outW;ctoW] + (outb+ctob), 9 k-tiles ----
    zero8(acc);
    STAGE(RING1, 495616, 36864); cp_wait<1>(); __syncthreads();
    gemm_pass<9>(acc, SM + TXH, SM + RING0, wm, wn, lane);
    gemm_pass<9>(acc, SM + TXL, SM + RING0, wm, wn, lane);
    __syncthreads();
    cp_wait<0>(); __syncthreads();
    gemm_pass<9>(acc, SM + TXH, SM + RING1, wm, wn, lane);
    {
        const int r1 = wm * 16 + (lane >> 2), r2 = r1 + 8;
        const int m2 = (lane & 3) * 2;
#pragma unroll
        for (int nt = 0; nt < 8; ++nt) {
            int cb = wn * 64 + nt * 8 + m2;
            float b0 = BIA[768 + cb], b1 = BIA[768 + cb + 1];
            if (r1 < rows)
                *(float2*)(p.out + (size_t)(row0 + r1) * 128 + cb) =
                    make_float2(acc[nt][0] + b0, acc[nt][1] + b1);
            if (r2 < rows)
                *(float2*)(p.out + (size_t)(row0 + r2) * 128 + cb) =
                    make_float2(acc[nt][2] + b0, acc[nt][3] + b1);
        }
    }
}

// ---------- launch ----------
extern "C" void kernel_launch(void* const* d_in, const int* in_sizes, int n_in,
                              void* d_out, int out_size)
{
    Params p;
    p.src = (const float*)d_in[0];
    p.dst = (const float*)d_in[1];
    p.edge = (const float*)d_in[2];
    p.im2b = (const float*)d_in[10];
    p.mp1b = (const float*)d_in[12];
    p.mp2b = (const float*)d_in[14];
    p.qb   = (const float*)d_in[16];
    p.kb   = (const float*)d_in[18];
    p.vb   = (const float*)d_in[20];
    p.ntcb = (const float*)d_in[22];
    p.ctob = (const float*)d_in[24];
    p.outb = (const float*)d_in[26];
    p.out = (float*)d_out;
    p.B = in_sizes[0] / 128;

    PrepPtrs pp;
    pp.im2W = (const float*)d_in[9];
    pp.mp1W = (const float*)d_in[11];
    pp.qW   = (const float*)d_in[15];
    pp.kW   = (const float*)d_in[17];
    pp.vW   = (const float*)d_in[19];
    pp.outW = (const float*)d_in[25];
    pp.ctoW = (const float*)d_in[23];
    pp.mp2W = (const float*)d_in[13];
    pp.ntcW = (const float*)d_in[21];

    cudaFuncSetAttribute(fused_kernel, cudaFuncAttributeMaxDynamicSharedMemorySize, SMEM_BYTES);

    prep1<<<128, 128>>>((const float*)d_in[3], (const float*)d_in[4],
                        (const float*)d_in[5], (const float*)d_in[6],
                        (const float*)d_in[7], (const float*)d_in[8]);
    prep2<<<10, 256>>>(pp);
    fused_kernel<<<(p.B + 63) / 64, 256, SMEM_BYTES>>>(p);
}

// round 8
// speedup vs baseline: 3.5140x; 1.0668x over previous
#include <cuda_runtime.h>
#include <cuda_bf16.h>
#include <math.h>
#include <stdint.h>

#define STRIDE 152                  // bf16 elems per tile row (incl. ip cols + pad)
// ---- smem byte offsets ----
#define TSH 0
#define TSL 19456
#define TDH 38912
#define TDL 58368
#define TXH 77824
#define TXL 97280
#define RING0 116736
#define RING1 153600
#define SMW_NTC 190464              // ntc frag hi(4096)+lo(4096)
#define SMW_MP2 198656              // mp2 frag hi+lo
#define BIA_B 207872                // 928 floats
#define SCO_B 211584                // 64x8 f32
#define GST_B 213632                // 256 f32
#define SCS_B 214656                // 64x16 f32
#define DCS_B 218752
#define M16_B 222848
#define SMEM_BYTES 226944

// ---- gmem weight buffer layout ----
__device__ float g_A1[128 * 128];
__device__ float g_A2[128 * 128];
__device__ float g_b1[128];
__device__ __align__(128) unsigned char g_wb[548864];

// ---------- helpers ----------
__device__ __forceinline__ uint32_t smem_u32(const void* p) {
    uint32_t a;
    asm("{ .reg .u64 t; cvta.to.shared.u64 t, %1; cvt.u32.u64 %0, t; }" : "=r"(a) : "l"(p));
    return a;
}
template<int N> __device__ __forceinline__ void cp_wait() {
    asm volatile("cp.async.wait_group %0;" :: "n"(N));
}
__device__ __forceinline__ void stage_fn(uint32_t dsm, uint64_t gsrc, int bytes, int tid) {
    for (int o = tid * 16; o < bytes; o += 4096)
        asm volatile("cp.async.cg.shared.global [%0], [%1], 16;" :: "r"(dsm + o), "l"(gsrc + o) : "memory");
    asm volatile("cp.async.commit_group;" ::: "memory");
}
__device__ __forceinline__ void mma16816(float* c, uint32_t a0, uint32_t a1, uint32_t a2, uint32_t a3,
                                         uint32_t b0, uint32_t b1) {
    asm volatile("mma.sync.aligned.m16n8k16.row.col.f32.bf16.bf16.f32 "
                 "{%0,%1,%2,%3}, {%4,%5,%6,%7}, {%8,%9}, {%0,%1,%2,%3};"
                 : "+f"(c[0]), "+f"(c[1]), "+f"(c[2]), "+f"(c[3])
                 : "r"(a0), "r"(a1), "r"(a2), "r"(a3), "r"(b0), "r"(b1));
}
__device__ __host__ __forceinline__ uint32_t frag_off(int k, int n, int ntiles) {
    int kt = k >> 4, kk = k & 15;
    int reg = kk >> 3, r8 = kk & 7, m = r8 >> 1, half = r8 & 1;
    int nt = n >> 3, ln = (n & 7) * 4 + m;
    return (uint32_t)((kt * ntiles + nt) * 32 + ln) * 8u + (uint32_t)reg * 4u + (uint32_t)half * 2u;
}
__device__ __forceinline__ uint32_t pack_bf2(float a, float b) {
    __nv_bfloat162 t;
    t.x = __float2bfloat16_rn(a);
    t.y = __float2bfloat16_rn(b);
    return *(uint32_t*)&t;
}
__device__ __forceinline__ void split_bf(float v, float& hi, float& lo) {
    __nv_bfloat16 h = __float2bfloat16_rn(v);
    hi = __bfloat162float(h);
    lo = v - hi;
}

// ---------- prep kernels ----------
__global__ void prep1(const float* __restrict__ npW, const float* __restrict__ npb,
                      const float* __restrict__ epW, const float* __restrict__ epb,
                      const float* __restrict__ im1W, const float* __restrict__ im1b)
{
    const int i = blockIdx.x, o = threadIdx.x;
    float s1 = 0.f, s2 = 0.f;
#pragma unroll 8
    for (int h = 0; h < 128; ++h) {
        s1 = fmaf(__ldg(npW + i * 128 + h), __ldg(im1W + h * 128 + o), s1);
        s2 = fmaf(__ldg(epW + i * 128 + h), __ldg(im1W + (128 + h) * 128 + o), s2);
    }
    g_A1[i * 128 + o] = s1;
    g_A2[i * 128 + o] = s2;
    if (i == 0) {
        float sb = im1b[o];
#pragma unroll 8
        for (int h = 0; h < 128; ++h)
            sb += npb[h] * im1W[h * 128 + o] + epb[h] * im1W[(128 + h) * 128 + o];
        g_b1[o] = sb;
    }
}

struct PrepPtrs { const float *im2W, *mp1W, *qW, *kW, *vW, *outW, *ctoW, *mp2W, *ntcW; };

__global__ void prep2(PrepPtrs pp)
{
    const int b = blockIdx.x;
    if (b < 7) {
        const float* W = nullptr;
        switch (b) { case 2: W = pp.im2W; break; case 3: W = pp.mp1W; break;
                     case 4: W = pp.qW; break; case 5: W = pp.kW; break;
                     case 6: W = pp.vW; break; default: break; }
        unsigned char* base = g_wb + b * 65536;
        for (int idx = threadIdx.x; idx < 16384; idx += blockDim.x) {
            int k = idx >> 7, n = idx & 127;
            float v = (b == 0) ? g_A1[idx] : (b == 1) ? g_A2[idx] : W[idx];
            float h, l; split_bf(v, h, l);
            uint32_t off = frag_off(k, n, 16);
            *(__nv_bfloat16*)(base + off) = __float2bfloat16_rn(h);
            *(__nv_bfloat16*)(base + 32768 + off) = __float2bfloat16_rn(l);
        }
    } else if (b == 7) {
        unsigned char* base = g_wb + 458752;
        for (int idx = threadIdx.x; idx < 144 * 128; idx += blockDim.x) {
            int k = idx >> 7, n = idx & 127;
            float v = (k < 128) ? pp.outW[k * 128 + n] : pp.ctoW[(k - 128) * 128 + n];
            float h, l; split_bf(v, h, l);
            uint32_t off = frag_off(k, n, 16);
            *(__nv_bfloat16*)(base + off) = __float2bfloat16_rn(h);
            *(__nv_bfloat16*)(base + 36864 + off) = __float2bfloat16_rn(l);
        }
    } else {
        const float* W = (b == 8) ? pp.ntcW : pp.mp2W;
        unsigned char* base = g_wb + ((b == 8) ? 532480 : 540672);
        for (int idx = threadIdx.x; idx < 2048; idx += blockDim.x) {
            int k = idx >> 4, n = idx & 15;
            float v = W[idx];
            float h, l; split_bf(v, h, l);
            uint32_t off = frag_off(k, n, 2);
            *(__nv_bfloat16*)(base + off) = __float2bfloat16_rn(h);
            *(__nv_bfloat16*)(base + 4096 + off) = __float2bfloat16_rn(l);
        }
    }
}

// ---------- GEMM pieces (warp tile 32 rows x 32 cols; wm in {0,1}, wn in {0..3}) ----------
// fused pass: A-hi and A-lo share each B fragment (W_hi slot)
template<int NKT>
__device__ __forceinline__ void gemm_f(float (&acc)[2][4][4], const char* AH, const char* AL,
                                       const char* slot, int wm, int wn, int lane)
{
    const int rb = wm * 32 + (lane >> 2);
    const int m2 = (lane & 3) * 2;
#pragma unroll
    for (int kt = 0; kt < NKT; ++kt) {
        uint32_t ah[2][4], al[2][4];
#pragma unroll
        for (int t = 0; t < 2; ++t) {
            const char* Ar = AH + ((rb + t * 16) * STRIDE + kt * 16 + m2) * 2;
            ah[t][0] = *(const uint32_t*)(Ar);
            ah[t][1] = *(const uint32_t*)(Ar + 8 * STRIDE * 2);
            ah[t][2] = *(const uint32_t*)(Ar + 16);
            ah[t][3] = *(const uint32_t*)(Ar + 8 * STRIDE * 2 + 16);
            const char* Al = AL + ((rb + t * 16) * STRIDE + kt * 16 + m2) * 2;
            al[t][0] = *(const uint32_t*)(Al);
            al[t][1] = *(const uint32_t*)(Al + 8 * STRIDE * 2);
            al[t][2] = *(const uint32_t*)(Al + 16);
            al[t][3] = *(const uint32_t*)(Al + 8 * STRIDE * 2 + 16);
        }
        const char* Bp = slot + ((kt * 16 + wn * 4) * 32 + lane) * 8;
#pragma unroll
        for (int nt = 0; nt < 4; ++nt) {
            uint2 b = *(const uint2*)(Bp + nt * 256);
#pragma unroll
            for (int t = 0; t < 2; ++t) {
                mma16816(acc[t][nt], ah[t][0], ah[t][1], ah[t][2], ah[t][3], b.x, b.y);
                mma16816(acc[t][nt], al[t][0], al[t][1], al[t][2], al[t][3], b.x, b.y);
            }
        }
    }
}
// hi-only pass (W_lo slot)
template<int NKT>
__device__ __forceinline__ void gemm_h(float (&acc)[2][4][4], const char* AH,
                                       const char* slot, int wm, int wn, int lane)
{
    const int rb = wm * 32 + (lane >> 2);
    const int m2 = (lane & 3) * 2;
#pragma unroll
    for (int kt = 0; kt < NKT; ++kt) {
        uint32_t ah[2][4];
#pragma unroll
        for (int t = 0; t < 2; ++t) {
            const char* Ar = AH + ((rb + t * 16) * STRIDE + kt * 16 + m2) * 2;
            ah[t][0] = *(const uint32_t*)(Ar);
            ah[t][1] = *(const uint32_t*)(Ar + 8 * STRIDE * 2);
            ah[t][2] = *(const uint32_t*)(Ar + 16);
            ah[t][3] = *(const uint32_t*)(Ar + 8 * STRIDE * 2 + 16);
        }
        const char* Bp = slot + ((kt * 16 + wn * 4) * 32 + lane) * 8;
#pragma unroll
        for (int nt = 0; nt < 4; ++nt) {
            uint2 b = *(const uint2*)(Bp + nt * 256);
#pragma unroll
            for (int t = 0; t < 2; ++t)
                mma16816(acc[t][nt], ah[t][0], ah[t][1], ah[t][2], ah[t][3], b.x, b.y);
        }
    }
}
__device__ __forceinline__ void small_pass(float (&acc)[2][4], const char* A, const char* slot,
                                           int wm4, int lane)
{
    const int r1 = wm4 * 16 + (lane >> 2);
    const int m2 = (lane & 3) * 2;
#pragma unroll
    for (int kt = 0; kt < 8; ++kt) {
        const char* Ar = A + (r1 * STRIDE + kt * 16 + m2) * 2;
        uint32_t a0 = *(const uint32_t*)(Ar);
        uint32_t a1 = *(const uint32_t*)(Ar + 8 * STRIDE * 2);
        uint32_t a2 = *(const uint32_t*)(Ar + 16);
        uint32_t a3 = *(const uint32_t*)(Ar + 8 * STRIDE * 2 + 16);
        const char* Bp = slot + (kt * 2 * 32 + lane) * 8;
#pragma unroll
        for (int nt = 0; nt < 2; ++nt) {
            uint2 b = *(const uint2*)(Bp + nt * 256);
            mma16816(acc[nt], a0, a1, a2, a3, b.x, b.y);
        }
    }
}
__device__ __forceinline__ void zero24(float (&a)[2][4][4]) {
#pragma unroll
    for (int t = 0; t < 2; ++t)
#pragma unroll
        for (int i = 0; i < 4; ++i)
#pragma unroll
            for (int j = 0; j < 4; ++j) a[t][i][j] = 0.f;
}
__device__ __forceinline__ void store_tile(const float (&acc)[2][4][4], char* SM, int tH, int tL,
                                           const float* bias, bool relu, int wm, int wn, int lane)
{
    const int rb = wm * 32 + (lane >> 2);
    const int m2 = (lane & 3) * 2;
#pragma unroll
    for (int t = 0; t < 2; ++t) {
        const int r1 = rb + t * 16, r2 = r1 + 8;
#pragma unroll
        for (int nt = 0; nt < 4; ++nt) {
            int cb = wn * 32 + nt * 8 + m2;
            float b0 = bias[cb], b1 = bias[cb + 1];
            float v0 = acc[t][nt][0] + b0, v1 = acc[t][nt][1] + b1;
            float v2 = acc[t][nt][2] + b0, v3 = acc[t][nt][3] + b1;
            if (relu) { v0 = fmaxf(v0, 0.f); v1 = fmaxf(v1, 0.f); v2 = fmaxf(v2, 0.f); v3 = fmaxf(v3, 0.f); }
            float h0, l0, h1, l1;
            split_bf(v0, h0, l0); split_bf(v1, h1, l1);
            *(uint32_t*)(SM + tH + (r1 * STRIDE + cb) * 2) = pack_bf2(h0, h1);
            *(uint32_t*)(SM + tL + (r1 * STRIDE + cb) * 2) = pack_bf2(l0, l1);
            split_bf(v2, h0, l0); split_bf(v3, h1, l1);
            *(uint32_t*)(SM + tH + (r2 * STRIDE + cb) * 2) = pack_bf2(h0, h1);
            *(uint32_t*)(SM + tL + (r2 * STRIDE + cb) * 2) = pack_bf2(l0, l1);
        }
    }
}
__device__ __forceinline__ void store_small(const float (&acc)[2][4], float* out,
                                            const float* bias, bool dot, int wm4, int lane)
{
    const int r1 = wm4 * 16 + (lane >> 2), r2 = r1 + 8;
    const int m2 = (lane & 3) * 2;
#pragma unroll
    for (int nt = 0; nt < 2; ++nt) {
        int c = nt * 8 + m2;
        float b0 = bias[c], b1 = bias[c + 1];
        float v0 = acc[nt][0] + b0, v1 = acc[nt][1] + b1;
        float v2 = acc[nt][2] + b0, v3 = acc[nt][3] + b1;
        if (dot) { v0 = tanhf(v0); v1 = tanhf(v1); v2 = tanhf(v2); v3 = tanhf(v3); }
        *(float2*)(out + r1 * 16 + c) = make_float2(v0, v1);
        *(float2*)(out + r2 * 16 + c) = make_float2(v2, v3);
    }
}
__device__ __forceinline__ void convert_tile(char* SM, int tH, int tL,
                                             const float* __restrict__ g, int rows, int tid)
{
#pragma unroll
    for (int i = 0; i < 8; ++i) {
        int f4 = tid + i * 256;
        int r = f4 >> 5, c4 = (f4 & 31) << 2;
        float4 v = make_float4(0.f, 0.f, 0.f, 0.f);
        if (r < rows) v = *(const float4*)(g + (size_t)r * 128 + c4);
        float h0, l0, h1, l1, h2, l2, h3, l3;
        split_bf(v.x, h0, l0); split_bf(v.y, h1, l1);
        split_bf(v.z, h2, l2); split_bf(v.w, h3, l3);
        uint2 uh, ul;
        uh.x = pack_bf2(h0, h1); uh.y = pack_bf2(h2, h3);
        ul.x = pack_bf2(l0, l1); ul.y = pack_bf2(l2, l3);
        *(uint2*)(SM + tH + (r * STRIDE + c4) * 2) = uh;
        *(uint2*)(SM + tL + (r * STRIDE + c4) * 2) = ul;
    }
}

struct Params {
    const float *src, *dst, *edge;
    const float *im2b, *mp1b, *mp2b, *qb, *kb, *vb, *ntcb, *ctob, *outb;
    float* out;
    int B;
};

__global__ __launch_bounds__(256, 1) void fused_kernel(Params p)
{
    extern __shared__ __align__(16) char SM[];
    const int tid = threadIdx.x, lane = tid & 31, wid = tid >> 5;
    const int wm = wid & 1, wn = wid >> 1;          // big-GEMM mapping (32x32 warp tiles)
    const int wm4 = wid & 3, wn2 = wid >> 2;        // small-GEMM mapping
    const int row0 = blockIdx.x * 64;
    const int rows = min(64, p.B - row0);
    const uint32_t sbase = smem_u32(SM);
    const uint64_t gaddr = (uint64_t)__cvta_generic_to_global((void*)g_wb);
    float* BIA = (float*)(SM + BIA_B);
    float* SCO = (float*)(SM + SCO_B);
    float* GST = (float*)(SM + GST_B);

#define STAGE(slot, goff, bytes) stage_fn(sbase + (slot), gaddr + (goff), (bytes), tid)

    STAGE(SMW_NTC, 532480, 16384);          // group: small frag weights
    STAGE(RING0, 0, 32768);                 // group: A1 hi

    if (tid < 128) {
        BIA[tid] = g_b1[tid];          BIA[128 + tid] = p.im2b[tid];
        BIA[256 + tid] = p.mp1b[tid];  BIA[384 + tid] = p.qb[tid];
        BIA[512 + tid] = p.kb[tid];    BIA[640 + tid] = p.vb[tid];
        BIA[768 + tid] = p.outb[tid] + p.ctob[tid];
    }
    if (tid < 16) { BIA[896 + tid] = p.mp2b[tid]; BIA[912 + tid] = p.ntcb[tid]; }
    {   // geometric-product sign table (MSB-first bit convention)
        int i = tid >> 4, j = tid & 15;
        float s = 1.f;
#pragma unroll
        for (int k = 0; k < 4; ++k)
            if ((j >> (3 - k)) & 1)
                if (__popc(i >> (4 - k)) & 1) s = -s;
        GST[tid] = s;
    }
    convert_tile(SM, TSH, TSL, p.src  + (size_t)row0 * 128, rows, tid);
    convert_tile(SM, TXH, TXL, p.edge + (size_t)row0 * 128, rows, tid);
    convert_tile(SM, TDH, TDL, p.dst  + (size_t)row0 * 128, rows, tid);
    cp_wait<1>();
    __syncthreads();                        // small weights + tiles ready

    // ---- sc (wn2=0) / dc (wn2=1): 128->16 via mma ----
    {
        float a2[2][4] = {};
        const char* AH = SM + ((wn2 == 0) ? TSH : TDH);
        const char* AL = SM + ((wn2 == 0) ? TSL : TDL);
        small_pass(a2, AH, SM + SMW_NTC, wm4, lane);
        small_pass(a2, AL, SM + SMW_NTC, wm4, lane);
        small_pass(a2, AH, SM + SMW_NTC + 4096, wm4, lane);
        store_small(a2, (float*)(SM + ((wn2 == 0) ? SCS_B : DCS_B)), BIA + 912, false, wm4, lane);
    }

    float acc[2][4][4];
    zero24(acc);
    // ---- G1: h1 = relu(src@A1 + edge@A2 + b1) ----
    STAGE(RING1, 32768, 32768);  cp_wait<1>(); __syncthreads();
    gemm_f<8>(acc, SM + TSH, SM + TSL, SM + RING0, wm, wn, lane);
    __syncthreads();
    STAGE(RING0, 65536, 32768);  cp_wait<1>(); __syncthreads();
    gemm_h<8>(acc, SM + TSH, SM + RING1, wm, wn, lane);
    __syncthreads();
    STAGE(RING1, 98304, 32768);  cp_wait<1>(); __syncthreads();
    gemm_f<8>(acc, SM + TXH, SM + TXL, SM + RING0, wm, wn, lane);
    __syncthreads();
    STAGE(RING0, 131072, 32768); cp_wait<1>(); __syncthreads();
    gemm_h<8>(acc, SM + TXH, SM + RING1, wm, wn, lane);
    __syncthreads();
    store_tile(acc, SM, TXH, TXL, BIA + 0, true, wm, wn, lane);
    __syncthreads();

    // ---- G2: h2 = relu(h1@im2) ----
    zero24(acc);
    STAGE(RING1, 163840, 32768); cp_wait<1>(); __syncthreads();
    gemm_f<8>(acc, SM + TXH, SM + TXL, SM + RING0, wm, wn, lane);
    __syncthreads();
    STAGE(RING0, 196608, 32768); cp_wait<1>(); __syncthreads();
    gemm_h<8>(acc, SM + TXH, SM + RING1, wm, wn, lane);
    __syncthreads();
    store_tile(acc, SM, TXH, TXL, BIA + 128, true, wm, wn, lane);
    __syncthreads();

    // ---- G3: h3 = relu(h2@mp1) ----
    zero24(acc);
    STAGE(RING1, 229376, 32768); cp_wait<1>(); __syncthreads();
    gemm_f<8>(acc, SM + TXH, SM + TXL, SM + RING0, wm, wn, lane);
    __syncthreads();
    STAGE(RING0, 262144, 32768); cp_wait<1>(); __syncthreads();
    gemm_h<8>(acc, SM + TXH, SM + RING1, wm, wn, lane);
    __syncthreads();
    store_tile(acc, SM, TXH, TXL, BIA + 256, true, wm, wn, lane);
    __syncthreads();

    // ---- m16 = tanh(h3@mp2 + b) (wn2=0 warps) ----
    if (wn2 == 0) {
        float a2[2][4] = {};
        small_pass(a2, SM + TXH, SM + SMW_MP2, wm4, lane);
        small_pass(a2, SM + TXL, SM + SMW_MP2, wm4, lane);
        small_pass(a2, SM + TXH, SM + SMW_MP2 + 4096, wm4, lane);
        store_small(a2, (float*)(SM + M16_B), BIA + 896, true, wm4, lane);
    }
    __syncthreads();

    // ---- clifford: metric + adapted inner product -> ip into TX cols 128..143 ----
    if (tid < 64) {
        const float* M16 = (float*)(SM + M16_B);
        const float* SCS = (float*)(SM + SCS_B);
        const float* DCS = (float*)(SM + DCS_B);
        int r = tid;
        float m[16], s[16], d[16];
#pragma unroll
        for (int k = 0; k < 16; ++k) {
            m[k] = M16[r * 16 + k];
            s[k] = SCS[r * 16 + k];
            d[k] = DCS[r * 16 + k];
        }
        float L[4][4];
#pragma unroll
        for (int a = 0; a < 4; ++a)
#pragma unroll
            for (int b = 0; b < 4; ++b) {
                float mv = m[a * 4 + b];
                L[a][b] = (a > b) ? mv : (a == b) ? (log1pf(expf(mv)) + 1e-6f) : 0.f;
            }
        float met[4][4];
#pragma unroll
        for (int a = 0; a < 4; ++a)
#pragma unroll
            for (int b = 0; b < 4; ++b) {
                float q = 0.f;
#pragma unroll
                for (int c = 0; c < 4; ++c) q = fmaf(L[a][c], L[b][c], q);
                met[a][b] = q;
            }
        const int VI[4] = {1, 2, 4, 8};
        float sv[4], dv[4];
#pragma unroll
        for (int a = 0; a < 4; ++a) {
            float qs = 0.f, qd = 0.f;
#pragma unroll
            for (int b = 0; b < 4; ++b) {
                qs = fmaf(met[a][b], s[VI[b]], qs);
                qd = fmaf(met[a][b], d[VI[b]], qd);
            }
            sv[a] = qs; dv[a] = qd;
        }
#pragma unroll
        for (int a = 0; a < 4; ++a) { s[VI[a]] = sv[a]; d[VI[a]] = dv[a]; }
#pragma unroll
        for (int k = 0; k < 16; ++k) {
            float q = 0.f;
#pragma unroll
            for (int i = 0; i < 16; ++i) {
                int j = i ^ k;
                q = fmaf(GST[i * 16 + j], fmaf(s[i], d[j], d[i] * s[j]), q);
            }
            float ip = 0.5f * q, h, l;
            split_bf(ip, h, l);
            *(__nv_bfloat16*)(SM + TXH + (r * STRIDE + 128 + k) * 2) = __float2bfloat16_rn(h);
            *(__nv_bfloat16*)(SM + TXL + (r * STRIDE + 128 + k) * 2) = __float2bfloat16_rn(l);
        }
    }
    __syncthreads();

    // ---- Q = src@qW (kept in registers) ----
    float accQ[2][4][4];
    zero24(accQ);
    STAGE(RING1, 294912, 32768); cp_wait<1>(); __syncthreads();
    gemm_f<8>(accQ, SM + TSH, SM + TSL, SM + RING0, wm, wn, lane);
    __syncthreads();
    STAGE(RING0, 327680, 32768); cp_wait<1>(); __syncthreads();
    gemm_h<8>(accQ, SM + TSH, SM + RING1, wm, wn, lane);
    __syncthreads();

    // ---- K = dst@kW ----
    float accK[2][4][4];
    zero24(accK);
    STAGE(RING1, 360448, 32768); cp_wait<1>(); __syncthreads();
    gemm_f<8>(accK, SM + TDH, SM + TDL, SM + RING0, wm, wn, lane);
    __syncthreads();
    STAGE(RING0, 393216, 32768); cp_wait<1>(); __syncthreads();
    gemm_h<8>(accK, SM + TDH, SM + RING1, wm, wn, lane);

    // ---- scores = (Q+qb).(K+kb)/4 per head (enh cancels in softmax) ----
    {
        const int rb = wm * 32 + (lane >> 2);
        const int m = lane & 3, m2 = m * 2;
#pragma unroll
        for (int e = 0; e < 2; ++e) {
            float pr[4];
#pragma unroll
            for (int t = 0; t < 2; ++t) {
                float pa = 0.f, pb = 0.f;
#pragma unroll
                for (int u = 0; u < 2; ++u) {
                    int nt = 2 * e + u, cb = wn * 32 + nt * 8 + m2;
                    float qb0 = BIA[384 + cb], qb1 = BIA[384 + cb + 1];
                    float kb0 = BIA[512 + cb], kb1 = BIA[512 + cb + 1];
                    pa += (accQ[t][nt][0] + qb0) * (accK[t][nt][0] + kb0)
                        + (accQ[t][nt][1] + qb1) * (accK[t][nt][1] + kb1);
                    pb += (accQ[t][nt][2] + qb0) * (accK[t][nt][2] + kb0)
                        + (accQ[t][nt][3] + qb1) * (accK[t][nt][3] + kb1);
                }
                pr[t * 2] = pa; pr[t * 2 + 1] = pb;
            }
#pragma unroll
            for (int j = 0; j < 4; ++j) {
                pr[j] += __shfl_xor_sync(0xFFFFFFFFu, pr[j], 1);
                pr[j] += __shfl_xor_sync(0xFFFFFFFFu, pr[j], 2);
            }
            if (m == 0) {
                int h = wn * 2 + e;
                SCO[rb * 8 + h]        = 0.25f * pr[0];
                SCO[(rb + 8) * 8 + h]  = 0.25f * pr[1];
                SCO[(rb + 16) * 8 + h] = 0.25f * pr[2];
                SCO[(rb + 24) * 8 + h] = 0.25f * pr[3];
            }
        }
    }
    __syncthreads();
    if (tid < 64) {
        float s0[8], mx = -1e30f;
#pragma unroll
        for (int h = 0; h < 8; ++h) { s0[h] = SCO[tid * 8 + h]; mx = fmaxf(mx, s0[h]); }
        float sum = 0.f;
#pragma unroll
        for (int h = 0; h < 8; ++h) { s0[h] = expf(s0[h] - mx); sum += s0[h]; }
        float inv = 1.f / sum;
#pragma unroll
        for (int h = 0; h < 8; ++h) SCO[tid * 8 + h] = s0[h] * inv;
    }
    __syncthreads();

    // ---- V = dst@vW ; att = w8*(V+vb) -> TX ----
    zero24(acc);
    STAGE(RING1, 425984, 32768); cp_wait<1>(); __syncthreads();
    gemm_f<8>(acc, SM + TDH, SM + TDL, SM + RING0, wm, wn, lane);
    __syncthreads();
    STAGE(RING0, 458752, 36864); cp_wait<1>(); __syncthreads();
    gemm_h<8>(acc, SM + TDH, SM + RING1, wm, wn, lane);
    __syncthreads();
    {
        const int rb = wm * 32 + (lane >> 2);
        const int m2 = (lane & 3) * 2;
#pragma unroll
        for (int t = 0; t < 2; ++t) {
            const int r1 = rb + t * 16, r2 = r1 + 8;
#pragma unroll
            for (int nt = 0; nt < 4; ++nt) {
                int cb = wn * 32 + nt * 8 + m2;
                int h = wn * 2 + (nt >> 1);
                float w1 = SCO[r1 * 8 + h], w2 = SCO[r2 * 8 + h];
                float b0 = BIA[640 + cb], b1 = BIA[640 + cb + 1];
                float v0 = (acc[t][nt][0] + b0) * w1, v1 = (acc[t][nt][1] + b1) * w1;
                float v2 = (acc[t][nt][2] + b0) * w2, v3 = (acc[t][nt][3] + b1) * w2;
                float h0, l0, h1, l1;
                split_bf(v0, h0, l0); split_bf(v1, h1, l1);
                *(uint32_t*)(SM + TXH + (r1 * STRIDE + cb) * 2) = pack_bf2(h0, h1);
                *(uint32_t*)(SM + TXL + (r1 * STRIDE + cb) * 2) = pack_bf2(l0, l1);
                split_bf(v2, h0, l0); split_bf(v3, h1, l1);
                *(uint32_t*)(SM + TXH + (r2 * STRIDE + cb) * 2) = pack_bf2(h0, h1);
                *(uint32_t*)(SM + TXL + (r2 * STRIDE + cb) * 2) = pack_bf2(l0, l1);
            }
        }
    }
    __syncthreads();

    // ---- out = [att|ip]@[outW;ctoW] + (outb+ctob), 9 k-tiles ----
    zero24(acc);
    STAGE(RING1, 495616, 36864); cp_wait<1>(); __syncthreads();
    gemm_f<9>(acc, SM + TXH, SM + TXL, SM + RING0, wm, wn, lane);
    __syncthreads();
    cp_wait<0>(); __syncthreads();
    gemm_h<9>(acc, SM + TXH, SM + RING1, wm, wn, lane);
    {
        const int rb = wm * 32 + (lane >> 2);
        const int m2 = (lane & 3) * 2;
#pragma unroll
        for (int t = 0; t < 2; ++t) {
            const int r1 = rb + t * 16, r2 = r1 + 8;
#pragma unroll
            for (int nt = 0; nt < 4; ++nt) {
                int cb = wn * 32 + nt * 8 + m2;
                float b0 = BIA[768 + cb], b1 = BIA[768 + cb + 1];
                if (r1 < rows)
                    *(float2*)(p.out + (size_t)(row0 + r1) * 128 + cb) =
                        make_float2(acc[t][nt][0] + b0, acc[t][nt][1] + b1);
                if (r2 < rows)
                    *(float2*)(p.out + (size_t)(row0 + r2) * 128 + cb) =
                        make_float2(acc[t][nt][2] + b0, acc[t][nt][3] + b1);
            }
        }
    }
}

// ---------- launch ----------
extern "C" void kernel_launch(void* const* d_in, const int* in_sizes, int n_in,
                              void* d_out, int out_size)
{
    Params p;
    p.src = (const float*)d_in[0];
    p.dst = (const float*)d_in[1];
    p.edge = (const float*)d_in[2];
    p.im2b = (const float*)d_in[10];
    p.mp1b = (const float*)d_in[12];
    p.mp2b = (const float*)d_in[14];
    p.qb   = (const float*)d_in[16];
    p.kb   = (const float*)d_in[18];
    p.vb   = (const float*)d_in[20];
    p.ntcb = (const float*)d_in[22];
    p.ctob = (const float*)d_in[24];
    p.outb = (const float*)d_in[26];
    p.out = (float*)d_out;
    p.B = in_sizes[0] / 128;

    PrepPtrs pp;
    pp.im2W = (const float*)d_in[9];
    pp.mp1W = (const float*)d_in[11];
    pp.qW   = (const float*)d_in[15];
    pp.kW   = (const float*)d_in[17];
    pp.vW   = (const float*)d_in[19];
    pp.outW = (const float*)d_in[25];
    pp.ctoW = (const float*)d_in[23];
    pp.mp2W = (const float*)d_in[13];
    pp.ntcW = (const float*)d_in[21];

    cudaFuncSetAttribute(fused_kernel, cudaFuncAttributeMaxDynamicSharedMemorySize, SMEM_BYTES);

    prep1<<<128, 128>>>((const float*)d_in[3], (const float*)d_in[4],
                        (const float*)d_in[5], (const float*)d_in[6],
                        (const float*)d_in[7], (const float*)d_in[8]);
    prep2<<<10, 256>>>(pp);
    fused_kernel<<<(p.B + 63) / 64, 256, SMEM_BYTES>>>(p);
}

// round 10
// speedup vs baseline: 5.0787x; 1.4453x over previous
#include <cuda_runtime.h>
#include <cuda_fp16.h>
#include <math.h>
#include <stdint.h>

#define STRIDE 152                  // fp16 elems per tile row (incl. ip cols + pad)
// ---- smem byte offsets ----
#define TSH 0
#define TSL 19456
#define TDH 38912
#define TDL 58368
#define TXH 77824
#define TXL 97280
#define RING0 116736
#define RING1 153600
#define SMW_NTC 190464              // ntc frag hi (4096)
#define SMW_MP2 194560              // mp2 frag hi (4096)
#define BIA_B 207872                // 928 floats
#define SCO_B 211584                // 64x8 f32
#define GST_B 213632                // 256 f32
#define SCS_B 214656                // 64x16 f32
#define DCS_B 218752
#define M16_B 222848
#define SMEM_BYTES 226944

// ---- gmem weight buffer layout (fp16 hi-only fragments) ----
// slots 0..6 (A1,A2,im2,mp1,qW,kW,vW): b*32768
// slot 7 (outW|ctoW, 9 ktiles): 229376 (36864)
// ntc: 266240 (4096); mp2: 270336 (4096)
__device__ float g_A1[128 * 128];
__device__ float g_A2[128 * 128];
__device__ float g_b1[128];
__device__ __align__(128) unsigned char g_wb[274432];

// ---------- helpers ----------
__device__ __forceinline__ uint32_t smem_u32(const void* p) {
    uint32_t a;
    asm("{ .reg .u64 t; cvta.to.shared.u64 t, %1; cvt.u32.u64 %0, t; }" : "=r"(a) : "l"(p));
    return a;
}
template<int N> __device__ __forceinline__ void cp_wait() {
    asm volatile("cp.async.wait_group %0;" :: "n"(N));
}
__device__ __forceinline__ void stage_fn(uint32_t dsm, uint64_t gsrc, int bytes, int tid) {
    for (int o = tid * 16; o < bytes; o += 4096)
        asm volatile("cp.async.cg.shared.global [%0], [%1], 16;" :: "r"(dsm + o), "l"(gsrc + o) : "memory");
    asm volatile("cp.async.commit_group;" ::: "memory");
}
__device__ __forceinline__ void mma16816(float* c, uint32_t a0, uint32_t a1, uint32_t a2, uint32_t a3,
                                         uint32_t b0, uint32_t b1) {
    asm volatile("mma.sync.aligned.m16n8k16.row.col.f32.f16.f16.f32 "
                 "{%0,%1,%2,%3}, {%4,%5,%6,%7}, {%8,%9}, {%0,%1,%2,%3};"
                 : "+f"(c[0]), "+f"(c[1]), "+f"(c[2]), "+f"(c[3])
                 : "r"(a0), "r"(a1), "r"(a2), "r"(a3), "r"(b0), "r"(b1));
}
__device__ __host__ __forceinline__ uint32_t frag_off(int k, int n, int ntiles) {
    int kt = k >> 4, kk = k & 15;
    int reg = kk >> 3, r8 = kk & 7, m = r8 >> 1, half = r8 & 1;
    int nt = n >> 3, ln = (n & 7) * 4 + m;
    return (uint32_t)((kt * ntiles + nt) * 32 + ln) * 8u + (uint32_t)reg * 4u + (uint32_t)half * 2u;
}
__device__ __forceinline__ uint32_t pack_h2(float a, float b) {
    __half2 t;
    t.x = __float2half_rn(a);
    t.y = __float2half_rn(b);
    return *(uint32_t*)&t;
}
__device__ __forceinline__ void split_h(float v, float& hi, float& lo) {
    __half h = __float2half_rn(v);
    hi = __half2float(h);
    lo = v - hi;
}

// ---------- prep kernels ----------
__global__ void prep1(const float* __restrict__ npW, const float* __restrict__ npb,
                      const float* __restrict__ epW, const float* __restrict__ epb,
                      const float* __restrict__ im1W, const float* __restrict__ im1b)
{
    const int i = blockIdx.x, o = threadIdx.x;
    float s1 = 0.f, s2 = 0.f;
#pragma unroll 16
    for (int h = 0; h < 128; ++h) {
        s1 = fmaf(__ldg(npW + i * 128 + h), __ldg(im1W + h * 128 + o), s1);
        s2 = fmaf(__ldg(epW + i * 128 + h), __ldg(im1W + (128 + h) * 128 + o), s2);
    }
    g_A1[i * 128 + o] = s1;
    g_A2[i * 128 + o] = s2;
    if (i == 0) {
        float sb = im1b[o];
#pragma unroll 16
        for (int h = 0; h < 128; ++h)
            sb += npb[h] * im1W[h * 128 + o] + epb[h] * im1W[(128 + h) * 128 + o];
        g_b1[o] = sb;
    }
}

struct PrepPtrs { const float *im2W, *mp1W, *qW, *kW, *vW, *outW, *ctoW, *mp2W, *ntcW; };

__global__ void prep2(PrepPtrs pp)
{
    const int b = blockIdx.x;
    if (b < 7) {
        const float* W = nullptr;
        switch (b) { case 2: W = pp.im2W; break; case 3: W = pp.mp1W; break;
                     case 4: W = pp.qW; break; case 5: W = pp.kW; break;
                     case 6: W = pp.vW; break; default: break; }
        unsigned char* base = g_wb + b * 32768;
        for (int idx = threadIdx.x; idx < 16384; idx += blockDim.x) {
            int k = idx >> 7, n = idx & 127;
            float v = (b == 0) ? g_A1[idx] : (b == 1) ? g_A2[idx] : W[idx];
            *(__half*)(base + frag_off(k, n, 16)) = __float2half_rn(v);
        }
    } else if (b == 7) {
        unsigned char* base = g_wb + 229376;
        for (int idx = threadIdx.x; idx < 144 * 128; idx += blockDim.x) {
            int k = idx >> 7, n = idx & 127;
            float v = (k < 128) ? pp.outW[k * 128 + n] : pp.ctoW[(k - 128) * 128 + n];
            *(__half*)(base + frag_off(k, n, 16)) = __float2half_rn(v);
        }
    } else {
        const float* W = (b == 8) ? pp.ntcW : pp.mp2W;
        unsigned char* base = g_wb + ((b == 8) ? 266240 : 270336);
        for (int idx = threadIdx.x; idx < 2048; idx += blockDim.x) {
            int k = idx >> 4, n = idx & 15;
            *(__half*)(base + frag_off(k, n, 2)) = __float2half_rn(W[idx]);
        }
    }
}

// ---------- GEMM pieces (warp tile 32x32; wm in {0,1}, wn in {0..3}) ----------
// fused 2-pass: A-hi and A-lo share each B fragment
template<int NKT>
__device__ __forceinline__ void gemm_f(float (&acc)[2][4][4], const char* AH, const char* AL,
                                       const char* slot, int wm, int wn, int lane)
{
    const int rb = wm * 32 + (lane >> 2);
    const int m2 = (lane & 3) * 2;
#pragma unroll
    for (int kt = 0; kt < NKT; ++kt) {
        uint32_t ah[2][4], al[2][4];
#pragma unroll
        for (int t = 0; t < 2; ++t) {
            const char* Ar = AH + ((rb + t * 16) * STRIDE + kt * 16 + m2) * 2;
            ah[t][0] = *(const uint32_t*)(Ar);
            ah[t][1] = *(const uint32_t*)(Ar + 8 * STRIDE * 2);
            ah[t][2] = *(const uint32_t*)(Ar + 16);
            ah[t][3] = *(const uint32_t*)(Ar + 8 * STRIDE * 2 + 16);
            const char* Al = AL + ((rb + t * 16) * STRIDE + kt * 16 + m2) * 2;
            al[t][0] = *(const uint32_t*)(Al);
            al[t][1] = *(const uint32_t*)(Al + 8 * STRIDE * 2);
            al[t][2] = *(const uint32_t*)(Al + 16);
            al[t][3] = *(const uint32_t*)(Al + 8 * STRIDE * 2 + 16);
        }
        const char* Bp = slot + ((kt * 16 + wn * 4) * 32 + lane) * 8;
#pragma unroll
        for (int nt = 0; nt < 4; ++nt) {
            uint2 b = *(const uint2*)(Bp + nt * 256);
#pragma unroll
            for (int t = 0; t < 2; ++t) {
                mma16816(acc[t][nt], ah[t][0], ah[t][1], ah[t][2], ah[t][3], b.x, b.y);
                mma16816(acc[t][nt], al[t][0], al[t][1], al[t][2], al[t][3], b.x, b.y);
            }
        }
    }
}
__device__ __forceinline__ void small_pass(float (&acc)[2][4], const char* A, const char* slot,
                                           int wm4, int lane)
{
    const int r1 = wm4 * 16 + (lane >> 2);
    const int m2 = (lane & 3) * 2;
#pragma unroll
    for (int kt = 0; kt < 8; ++kt) {
        const char* Ar = A + (r1 * STRIDE + kt * 16 + m2) * 2;
        uint32_t a0 = *(const uint32_t*)(Ar);
        uint32_t a1 = *(const uint32_t*)(Ar + 8 * STRIDE * 2);
        uint32_t a2 = *(const uint32_t*)(Ar + 16);
        uint32_t a3 = *(const uint32_t*)(Ar + 8 * STRIDE * 2 + 16);
        const char* Bp = slot + (kt * 2 * 32 + lane) * 8;
#pragma unroll
        for (int nt = 0; nt < 2; ++nt) {
            uint2 b = *(const uint2*)(Bp + nt * 256);
            mma16816(acc[nt], a0, a1, a2, a3, b.x, b.y);
        }
    }
}
__device__ __forceinline__ void zero24(float (&a)[2][4][4]) {
#pragma unroll
    for (int t = 0; t < 2; ++t)
#pragma unroll
        for (int i = 0; i < 4; ++i)
#pragma unroll
            for (int j = 0; j < 4; ++j) a[t][i][j] = 0.f;
}
__device__ __forceinline__ void store_tile(const float (&acc)[2][4][4], char* SM, int tH, int tL,
                                           const float* bias, bool relu, int wm, int wn, int lane)
{
    const int rb = wm * 32 + (lane >> 2);
    const int m2 = (lane & 3) * 2;
#pragma unroll
    for (int t = 0; t < 2; ++t) {
        const int r1 = rb + t * 16, r2 = r1 + 8;
#pragma unroll
        for (int nt = 0; nt < 4; ++nt) {
            int cb = wn * 32 + nt * 8 + m2;
            float b0 = bias[cb], b1 = bias[cb + 1];
            float v0 = acc[t][nt][0] + b0, v1 = acc[t][nt][1] + b1;
            float v2 = acc[t][nt][2] + b0, v3 = acc[t][nt][3] + b1;
            if (relu) { v0 = fmaxf(v0, 0.f); v1 = fmaxf(v1, 0.f); v2 = fmaxf(v2, 0.f); v3 = fmaxf(v3, 0.f); }
            float h0, l0, h1, l1;
            split_h(v0, h0, l0); split_h(v1, h1, l1);
            *(uint32_t*)(SM + tH + (r1 * STRIDE + cb) * 2) = pack_h2(h0, h1);
            *(uint32_t*)(SM + tL + (r1 * STRIDE + cb) * 2) = pack_h2(l0, l1);
            split_h(v2, h0, l0); split_h(v3, h1, l1);
            *(uint32_t*)(SM + tH + (r2 * STRIDE + cb) * 2) = pack_h2(h0, h1);
            *(uint32_t*)(SM + tL + (r2 * STRIDE + cb) * 2) = pack_h2(l0, l1);
        }
    }
}
__device__ __forceinline__ void store_small(const float (&acc)[2][4], float* out,
                                            const float* bias, bool dot, int wm4, int lane)
{
    const int r1 = wm4 * 16 + (lane >> 2), r2 = r1 + 8;
    const int m2 = (lane & 3) * 2;
#pragma unroll
    for (int nt = 0; nt < 2; ++nt) {
        int c = nt * 8 + m2;
        float b0 = bias[c], b1 = bias[c + 1];
        float v0 = acc[nt][0] + b0, v1 = acc[nt][1] + b1;
        float v2 = acc[nt][2] + b0, v3 = acc[nt][3] + b1;
        if (dot) { v0 = tanhf(v0); v1 = tanhf(v1); v2 = tanhf(v2); v3 = tanhf(v3); }
        *(float2*)(out + r1 * 16 + c) = make_float2(v0, v1);
        *(float2*)(out + r2 * 16 + c) = make_float2(v2, v3);
    }
}
__device__ __forceinline__ void convert_tile(char* SM, int tH, int tL,
                                             const float* __restrict__ g, int rows, int tid)
{
#pragma unroll
    for (int i = 0; i < 8; ++i) {
        int f4 = tid + i * 256;
        int r = f4 >> 5, c4 = (f4 & 31) << 2;
        float4 v = make_float4(0.f, 0.f, 0.f, 0.f);
        if (r < rows) v = *(const float4*)(g + (size_t)r * 128 + c4);
        float h0, l0, h1, l1, h2, l2, h3, l3;
        split_h(v.x, h0, l0); split_h(v.y, h1, l1);
        split_h(v.z, h2, l2); split_h(v.w, h3, l3);
        uint2 uh, ul;
        uh.x = pack_h2(h0, h1); uh.y = pack_h2(h2, h3);
        ul.x = pack_h2(l0, l1); ul.y = pack_h2(l2, l3);
        *(uint2*)(SM + tH + (r * STRIDE + c4) * 2) = uh;
        *(uint2*)(SM + tL + (r * STRIDE + c4) * 2) = ul;
    }
}

struct Params {
    const float *src, *dst, *edge;
    const float *im2b, *mp1b, *mp2b, *qb, *kb, *vb, *ntcb, *ctob, *outb;
    float* out;
    int B;
};

__global__ __launch_bounds__(256, 1) void fused_kernel(Params p)
{
    extern __shared__ __align__(16) char SM[];
    const int tid = threadIdx.x, lane = tid & 31, wid = tid >> 5;
    const int wm = wid & 1, wn = wid >> 1;          // big-GEMM mapping
    const int wm4 = wid & 3, wn2 = wid >> 2;        // small-GEMM mapping
    const int row0 = blockIdx.x * 64;
    const int rows = min(64, p.B - row0);
    const uint32_t sbase = smem_u32(SM);
    const uint64_t gaddr = (uint64_t)__cvta_generic_to_global((void*)g_wb);
    float* BIA = (float*)(SM + BIA_B);
    float* SCO = (float*)(SM + SCO_B);
    float* GST = (float*)(SM + GST_B);

#define STAGE(slot, goff, bytes) stage_fn(sbase + (slot), gaddr + (goff), (bytes), tid)

    STAGE(SMW_NTC, 266240, 8192);           // ntc + mp2 frags (contiguous)
    STAGE(RING0, 0, 32768);                 // A1

    if (tid < 128) {
        BIA[tid] = g_b1[tid];          BIA[128 + tid] = p.im2b[tid];
        BIA[256 + tid] = p.mp1b[tid];  BIA[384 + tid] = p.qb[tid];
        BIA[512 + tid] = p.kb[tid];    BIA[640 + tid] = p.vb[tid];
        BIA[768 + tid] = p.outb[tid] + p.ctob[tid];
    }
    if (tid < 16) { BIA[896 + tid] = p.mp2b[tid]; BIA[912 + tid] = p.ntcb[tid]; }
    {   // geometric-product sign table (MSB-first bit convention)
        int i = tid >> 4, j = tid & 15;
        float s = 1.f;
#pragma unroll
        for (int k = 0; k < 4; ++k)
            if ((j >> (3 - k)) & 1)
                if (__popc(i >> (4 - k)) & 1) s = -s;
        GST[tid] = s;
    }
    convert_tile(SM, TSH, TSL, p.src  + (size_t)row0 * 128, rows, tid);
    convert_tile(SM, TXH, TXL, p.edge + (size_t)row0 * 128, rows, tid);
    convert_tile(SM, TDH, TDL, p.dst  + (size_t)row0 * 128, rows, tid);
    cp_wait<1>();
    __syncthreads();                        // small weights + tiles ready

    // ---- sc (wn2=0) / dc (wn2=1): 128->16, 2-pass ----
    {
        float a2[2][4] = {};
        const char* AH = SM + ((wn2 == 0) ? TSH : TDH);
        const char* AL = SM + ((wn2 == 0) ? TSL : TDL);
        small_pass(a2, AH, SM + SMW_NTC, wm4, lane);
        small_pass(a2, AL, SM + SMW_NTC, wm4, lane);
        store_small(a2, (float*)(SM + ((wn2 == 0) ? SCS_B : DCS_B)), BIA + 912, false, wm4, lane);
    }

    float acc[2][4][4];
    zero24(acc);
    // ---- G1: h1 = relu(src@A1 + edge@A2 + b1) ----
    STAGE(RING1, 32768, 32768);  cp_wait<1>(); __syncthreads();
    gemm_f<8>(acc, SM + TSH, SM + TSL, SM + RING0, wm, wn, lane);
    __syncthreads();
    STAGE(RING0, 65536, 32768);  cp_wait<1>(); __syncthreads();
    gemm_f<8>(acc, SM + TXH, SM + TXL, SM + RING1, wm, wn, lane);
    __syncthreads();
    store_tile(acc, SM, TXH, TXL, BIA + 0, true, wm, wn, lane);
    __syncthreads();

    // ---- G2: h2 = relu(h1@im2) ----
    zero24(acc);
    STAGE(RING1, 98304, 32768);  cp_wait<1>(); __syncthreads();
    gemm_f<8>(acc, SM + TXH, SM + TXL, SM + RING0, wm, wn, lane);
    __syncthreads();
    store_tile(acc, SM, TXH, TXL, BIA + 128, true, wm, wn, lane);
    __syncthreads();

    // ---- G3: h3 = relu(h2@mp1) ----
    zero24(acc);
    STAGE(RING0, 131072, 32768); cp_wait<1>(); __syncthreads();
    gemm_f<8>(acc, SM + TXH, SM + TXL, SM + RING1, wm, wn, lane);
    __syncthreads();
    store_tile(acc, SM, TXH, TXL, BIA + 256, true, wm, wn, lane);
    __syncthreads();

    // ---- m16 = tanh(h3@mp2 + b) (wn2=0 warps), 2-pass ----
    if (wn2 == 0) {
        float a2[2][4] = {};
        small_pass(a2, SM + TXH, SM + SMW_MP2, wm4, lane);
        small_pass(a2, SM + TXL, SM + SMW_MP2, wm4, lane);
        store_small(a2, (float*)(SM + M16_B), BIA + 896, true, wm4, lane);
    }
    __syncthreads();

    // ---- clifford: metric + adapted inner product -> ip into TX cols 128..143 ----
    if (tid < 64) {
        const float* M16 = (float*)(SM + M16_B);
        const float* SCS = (float*)(SM + SCS_B);
        const float* DCS = (float*)(SM + DCS_B);
        int r = tid;
        float m[16], s[16], d[16];
#pragma unroll
        for (int k = 0; k < 16; ++k) {
            m[k] = M16[r * 16 + k];
            s[k] = SCS[r * 16 + k];
            d[k] = DCS[r * 16 + k];
        }
        float L[4][4];
#pragma unroll
        for (int a = 0; a < 4; ++a)
#pragma unroll
            for (int b = 0; b < 4; ++b) {
                float mv = m[a * 4 + b];
                L[a][b] = (a > b) ? mv : (a == b) ? (log1pf(expf(mv)) + 1e-6f) : 0.f;
            }
        float met[4][4];
#pragma unroll
        for (int a = 0; a < 4; ++a)
#pragma unroll
            for (int b = 0; b < 4; ++b) {
                float q = 0.f;
#pragma unroll
                for (int c = 0; c < 4; ++c) q = fmaf(L[a][c], L[b][c], q);
                met[a][b] = q;
            }
        const int VI[4] = {1, 2, 4, 8};
        float sv[4], dv[4];
#pragma unroll
        for (int a = 0; a < 4; ++a) {
            float qs = 0.f, qd = 0.f;
#pragma unroll
            for (int b = 0; b < 4; ++b) {
                qs = fmaf(met[a][b], s[VI[b]], qs);
                qd = fmaf(met[a][b], d[VI[b]], qd);
            }
            sv[a] = qs; dv[a] = qd;
        }
#pragma unroll
        for (int a = 0; a < 4; ++a) { s[VI[a]] = sv[a]; d[VI[a]] = dv[a]; }
#pragma unroll
        for (int k = 0; k < 16; ++k) {
            float q = 0.f;
#pragma unroll
            for (int i = 0; i < 16; ++i) {
                int j = i ^ k;
                q = fmaf(GST[i * 16 + j], fmaf(s[i], d[j], d[i] * s[j]), q);
            }
            float ip = 0.5f * q, h, l;
            split_h(ip, h, l);
            *(__half*)(SM + TXH + (r * STRIDE + 128 + k) * 2) = __float2half_rn(h);
            *(__half*)(SM + TXL + (r * STRIDE + 128 + k) * 2) = __float2half_rn(l);
        }
    }
    __syncthreads();

    // ---- Q = src@qW (kept in registers) ----
    float accQ[2][4][4];
    zero24(accQ);
    STAGE(RING1, 163840, 32768); cp_wait<1>(); __syncthreads();
    gemm_f<8>(accQ, SM + TSH, SM + TSL, SM + RING0, wm, wn, lane);
    __syncthreads();

    // ---- K = dst@kW ----
    float accK[2][4][4];
    zero24(accK);
    STAGE(RING0, 196608, 32768); cp_wait<1>(); __syncthreads();
    gemm_f<8>(accK, SM + TDH, SM + TDL, SM + RING1, wm, wn, lane);

    // ---- scores = (Q+qb).(K+kb)/4 per head (enh cancels in softmax) ----
    {
        const int rb = wm * 32 + (lane >> 2);
        const int m = lane & 3, m2 = m * 2;
#pragma unroll
        for (int e = 0; e < 2; ++e) {
            float pr[4];
#pragma unroll
            for (int t = 0; t < 2; ++t) {
                float pa = 0.f, pb = 0.f;
#pragma unroll
                for (int u = 0; u < 2; ++u) {
                    int nt = 2 * e + u, cb = wn * 32 + nt * 8 + m2;
                    float qb0 = BIA[384 + cb], qb1 = BIA[384 + cb + 1];
                    float kb0 = BIA[512 + cb], kb1 = BIA[512 + cb + 1];
                    pa += (accQ[t][nt][0] + qb0) * (accK[t][nt][0] + kb0)
                        + (accQ[t][nt][1] + qb1) * (accK[t][nt][1] + kb1);
                    pb += (accQ[t][nt][2] + qb0) * (accK[t][nt][2] + kb0)
                        + (accQ[t][nt][3] + qb1) * (accK[t][nt][3] + kb1);
                }
                pr[t * 2] = pa; pr[t * 2 + 1] = pb;
            }
#pragma unroll
            for (int j = 0; j < 4; ++j) {
                pr[j] += __shfl_xor_sync(0xFFFFFFFFu, pr[j], 1);
                pr[j] += __shfl_xor_sync(0xFFFFFFFFu, pr[j], 2);
            }
            if (m == 0) {
                int h = wn * 2 + e;
                SCO[rb * 8 + h]        = 0.25f * pr[0];
                SCO[(rb + 8) * 8 + h]  = 0.25f * pr[1];
                SCO[(rb + 16) * 8 + h] = 0.25f * pr[2];
                SCO[(rb + 24) * 8 + h] = 0.25f * pr[3];
            }
        }
    }
    __syncthreads();
    if (tid < 64) {
        float s0[8], mx = -1e30f;
#pragma unroll
        for (int h = 0; h < 8; ++h) { s0[h] = SCO[tid * 8 + h]; mx = fmaxf(mx, s0[h]); }
        float sum = 0.f;
#pragma unroll
        for (int h = 0; h < 8; ++h) { s0[h] = expf(s0[h] - mx); sum += s0[h]; }
        float inv = 1.f / sum;
#pragma unroll
        for (int h = 0; h < 8; ++h) SCO[tid * 8 + h] = s0[h] * inv;
    }
    __syncthreads();

    // ---- V = dst@vW ; att = w8*(V+vb) -> TX ----
    zero24(acc);
    STAGE(RING1, 229376, 36864); cp_wait<1>(); __syncthreads();
    gemm_f<8>(acc, SM + TDH, SM + TDL, SM + RING0, wm, wn, lane);
    __syncthreads();
    {
        const int rb = wm * 32 + (lane >> 2);
        const int m2 = (lane & 3) * 2;
#pragma unroll
        for (int t = 0; t < 2; ++t) {
            const int r1 = rb + t * 16, r2 = r1 + 8;
#pragma unroll
            for (int nt = 0; nt < 4; ++nt) {
                int cb = wn * 32 + nt * 8 + m2;
                int h = wn * 2 + (nt >> 1);
                float w1 = SCO[r1 * 8 + h], w2 = SCO[r2 * 8 + h];
                float b0 = BIA[640 + cb], b1 = BIA[640 + cb + 1];
                float v0 = (acc[t][nt][0] + b0) * w1, v1 = (acc[t][nt][1] + b1) * w1;
                float v2 = (acc[t][nt][2] + b0) * w2, v3 = (acc[t][nt][3] + b1) * w2;
                float h0, l0, h1, l1;
                split_h(v0, h0, l0); split_h(v1, h1, l1);
                *(uint32_t*)(SM + TXH + (r1 * STRIDE + cb) * 2) = pack_h2(h0, h1);
                *(uint32_t*)(SM + TXL + (r1 * STRIDE + cb) * 2) = pack_h2(l0, l1);
                split_h(v2, h0, l0); split_h(v3, h1, l1);
                *(uint32_t*)(SM + TXH + (r2 * STRIDE + cb) * 2) = pack_h2(h0, h1);
                *(uint32_t*)(SM + TXL + (r2 * STRIDE + cb) * 2) = pack_h2(l0, l1);
            }
        }
    }
    __syncthreads();

    // ---- out = [att|ip]@[outW;ctoW] + (outb+ctob), 9 k-tiles ----
    zero24(acc);
    cp_wait<0>(); __syncthreads();
    gemm_f<9>(acc, SM + TXH, SM + TXL, SM + RING1, wm, wn, lane);
    {
        const int rb = wm * 32 + (lane >> 2);
        const int m2 = (lane & 3) * 2;
#pragma unroll
        for (int t = 0; t < 2; ++t) {
            const int r1 = rb + t * 16, r2 = r1 + 8;
#pragma unroll
            for (int nt = 0; nt < 4; ++nt) {
                int cb = wn * 32 + nt * 8 + m2;
                float b0 = BIA[768 + cb], b1 = BIA[768 + cb + 1];
                if (r1 < rows)
                    *(float2*)(p.out + (size_t)(row0 + r1) * 128 + cb) =
                        make_float2(acc[t][nt][0] + b0, acc[t][nt][1] + b1);
                if (r2 < rows)
                    *(float2*)(p.out + (size_t)(row0 + r2) * 128 + cb) =
                        make_float2(acc[t][nt][2] + b0, acc[t][nt][3] + b1);
            }
        }
    }
}

// ---------- launch ----------
extern "C" void kernel_launch(void* const* d_in, const int* in_sizes, int n_in,
                              void* d_out, int out_size)
{
    Params p;
    p.src = (const float*)d_in[0];
    p.dst = (const float*)d_in[1];
    p.edge = (const float*)d_in[2];
    p.im2b = (const float*)d_in[10];
    p.mp1b = (const float*)d_in[12];
    p.mp2b = (const float*)d_in[14];
    p.qb   = (const float*)d_in[16];
    p.kb   = (const float*)d_in[18];
    p.vb   = (const float*)d_in[20];
    p.ntcb = (const float*)d_in[22];
    p.ctob = (const float*)d_in[24];
    p.outb = (const float*)d_in[26];
    p.out = (float*)d_out;
    p.B = in_sizes[0] / 128;

    PrepPtrs pp;
    pp.im2W = (const float*)d_in[9];
    pp.mp1W = (const float*)d_in[11];
    pp.qW   = (const float*)d_in[15];
    pp.kW   = (const float*)d_in[17];
    pp.vW   = (const float*)d_in[19];
    pp.outW = (const float*)d_in[25];
    pp.ctoW = (const float*)d_in[23];
    pp.mp2W = (const float*)d_in[13];
    pp.ntcW = (const float*)d_in[21];

    cudaFuncSetAttribute(fused_kernel, cudaFuncAttributeMaxDynamicSharedMemorySize, SMEM_BYTES);

    prep1<<<128, 128>>>((const float*)d_in[3], (const float*)d_in[4],
                        (const float*)d_in[5], (const float*)d_in[6],
                        (const float*)d_in[7], (const float*)d_in[8]);
    prep2<<<10, 256>>>(pp);
    fused_kernel<<<(p.B + 63) / 64, 256, SMEM_BYTES>>>(p);
}

// round 11
// speedup vs baseline: 5.1097x; 1.0061x over previous
#include <cuda_runtime.h>
#include <cuda_fp16.h>
#include <math.h>
#include <stdint.h>

#define STRIDE 152                  // fp16 elems per tile row (incl. ip cols + pad)
// ---- smem byte offsets ----
#define TSH 0
#define TSL 19456
#define TDH 38912
#define TDL 58368
#define TXH 77824
#define TXL 97280
#define RING0 116736
#define RING1 153600
#define SMW_NTC 190464              // ntc frag hi (4096)
#define SMW_MP2 194560              // mp2 frag hi (4096)
#define BIA_B 207872                // 928 floats
#define SCO_B 211584                // 64x8 f32
#define GST_B 213632                // 256 f32
#define SCS_B 214656                // 64x16 f32
#define DCS_B 218752
#define M16_B 222848
#define SMEM_BYTES 226944

// ---- gmem weight buffer layout (fp16 hi-only fragments) ----
// slots 0..6 (A1,A2,im2,mp1,qW,kW,vW): b*32768
// slot 7 (outW|ctoW, 9 ktiles): 229376 (36864)
// ntc: 266240 (4096); mp2: 270336 (4096)
__device__ float g_A1[128 * 128];
__device__ float g_A2[128 * 128];
__device__ float g_b1[128];
__device__ __align__(128) unsigned char g_wb[274432];

// ---------- helpers ----------
__device__ __forceinline__ uint32_t smem_u32(const void* p) {
    uint32_t a;
    asm("{ .reg .u64 t; cvta.to.shared.u64 t, %1; cvt.u32.u64 %0, t; }" : "=r"(a) : "l"(p));
    return a;
}
template<int N> __device__ __forceinline__ void cp_wait() {
    asm volatile("cp.async.wait_group %0;" :: "n"(N));
}
__device__ __forceinline__ void stage_fn(uint32_t dsm, uint64_t gsrc, int bytes, int tid) {
    for (int o = tid * 16; o < bytes; o += 4096)
        asm volatile("cp.async.cg.shared.global [%0], [%1], 16;" :: "r"(dsm + o), "l"(gsrc + o) : "memory");
    asm volatile("cp.async.commit_group;" ::: "memory");
}
__device__ __forceinline__ void mma16816(float* c, uint32_t a0, uint32_t a1, uint32_t a2, uint32_t a3,
                                         uint32_t b0, uint32_t b1) {
    asm volatile("mma.sync.aligned.m16n8k16.row.col.f32.f16.f16.f32 "
                 "{%0,%1,%2,%3}, {%4,%5,%6,%7}, {%8,%9}, {%0,%1,%2,%3};"
                 : "+f"(c[0]), "+f"(c[1]), "+f"(c[2]), "+f"(c[3])
                 : "r"(a0), "r"(a1), "r"(a2), "r"(a3), "r"(b0), "r"(b1));
}
#define LDSM4(r0, r1, r2, r3, addr) \
    asm volatile("ldmatrix.sync.aligned.m8n8.x4.shared.b16 {%0,%1,%2,%3}, [%4];" \
                 : "=r"(r0), "=r"(r1), "=r"(r2), "=r"(r3) : "r"(addr))

__device__ __host__ __forceinline__ uint32_t frag_off(int k, int n, int ntiles) {
    int kt = k >> 4, kk = k & 15;
    int reg = kk >> 3, r8 = kk & 7, m = r8 >> 1, half = r8 & 1;
    int nt = n >> 3, ln = (n & 7) * 4 + m;
    return (uint32_t)((kt * ntiles + nt) * 32 + ln) * 8u + (uint32_t)reg * 4u + (uint32_t)half * 2u;
}
__device__ __forceinline__ uint32_t pack_h2(float a, float b) {
    __half2 t;
    t.x = __float2half_rn(a);
    t.y = __float2half_rn(b);
    return *(uint32_t*)&t;
}
__device__ __forceinline__ void split_h(float v, float& hi, float& lo) {
    __half h = __float2half_rn(v);
    hi = __half2float(h);
    lo = v - hi;
}

// ---------- prep kernels ----------
__global__ void prep1(const float* __restrict__ npW, const float* __restrict__ npb,
                      const float* __restrict__ epW, const float* __restrict__ epb,
                      const float* __restrict__ im1W, const float* __restrict__ im1b)
{
    __shared__ float red[1024];
    const int i = blockIdx.x;
    const int o = threadIdx.x & 127, q = threadIdx.x >> 7;   // 4-way h split
    float s1 = 0.f, s2 = 0.f;
#pragma unroll 8
    for (int h = q * 32; h < q * 32 + 32; ++h) {
        s1 = fmaf(__ldg(npW + i * 128 + h), __ldg(im1W + h * 128 + o), s1);
        s2 = fmaf(__ldg(epW + i * 128 + h), __ldg(im1W + (128 + h) * 128 + o), s2);
    }
    red[q * 128 + o] = s1;
    red[512 + q * 128 + o] = s2;
    __syncthreads();
    if (q == 0) {
        g_A1[i * 128 + o] = red[o] + red[128 + o] + red[256 + o] + red[384 + o];
        g_A2[i * 128 + o] = red[512 + o] + red[640 + o] + red[768 + o] + red[896 + o];
        if (i == 0) {
            float sb = im1b[o];
#pragma unroll 8
            for (int h = 0; h < 128; ++h)
                sb += npb[h] * im1W[h * 128 + o] + epb[h] * im1W[(128 + h) * 128 + o];
            g_b1[o] = sb;
        }
    }
}

struct PrepPtrs { const float *im2W, *mp1W, *qW, *kW, *vW, *outW, *ctoW, *mp2W, *ntcW; };

__global__ void prep2(PrepPtrs pp)
{
    const int b = blockIdx.x;
    if (b < 7) {
        const float* W = nullptr;
        switch (b) { case 2: W = pp.im2W; break; case 3: W = pp.mp1W; break;
                     case 4: W = pp.qW; break; case 5: W = pp.kW; break;
                     case 6: W = pp.vW; break; default: break; }
        unsigned char* base = g_wb + b * 32768;
        for (int idx = threadIdx.x; idx < 16384; idx += blockDim.x) {
            int k = idx >> 7, n = idx & 127;
            float v = (b == 0) ? g_A1[idx] : (b == 1) ? g_A2[idx] : W[idx];
            *(__half*)(base + frag_off(k, n, 16)) = __float2half_rn(v);
        }
    } else if (b == 7) {
        unsigned char* base = g_wb + 229376;
        for (int idx = threadIdx.x; idx < 144 * 128; idx += blockDim.x) {
            int k = idx >> 7, n = idx & 127;
            float v = (k < 128) ? pp.outW[k * 128 + n] : pp.ctoW[(k - 128) * 128 + n];
            *(__half*)(base + frag_off(k, n, 16)) = __float2half_rn(v);
        }
    } else {
        const float* W = (b == 8) ? pp.ntcW : pp.mp2W;
        unsigned char* base = g_wb + ((b == 8) ? 266240 : 270336);
        for (int idx = threadIdx.x; idx < 2048; idx += blockDim.x) {
            int k = idx >> 4, n = idx & 15;
            *(__half*)(base + frag_off(k, n, 2)) = __float2half_rn(W[idx]);
        }
    }
}

// ---------- GEMM pieces (warp tile 32x32; wm in {0,1}, wn in {0..3}) ----------
// fused 2-pass: A-hi and A-lo share each B fragment; A via ldmatrix.x4
template<int NKT>
__device__ __forceinline__ void gemm_f(float (&acc)[2][4][4], uint32_t aH, uint32_t aL,
                                       const char* slot, int wn, int lane)
{
#pragma unroll
    for (int kt = 0; kt < NKT; ++kt) {
        uint32_t ah[2][4], al[2][4];
#pragma unroll
        for (int t = 0; t < 2; ++t) {
            LDSM4(ah[t][0], ah[t][1], ah[t][2], ah[t][3], aH + t * (16 * STRIDE * 2) + kt * 32);
            LDSM4(al[t][0], al[t][1], al[t][2], al[t][3], aL + t * (16 * STRIDE * 2) + kt * 32);
        }
        const char* Bp = slot + ((kt * 16 + wn * 4) * 32 + lane) * 8;
#pragma unroll
        for (int nt = 0; nt < 4; ++nt) {
            uint2 b = *(const uint2*)(Bp + nt * 256);
#pragma unroll
            for (int t = 0; t < 2; ++t) {
                mma16816(acc[t][nt], ah[t][0], ah[t][1], ah[t][2], ah[t][3], b.x, b.y);
                mma16816(acc[t][nt], al[t][0], al[t][1], al[t][2], al[t][3], b.x, b.y);
            }
        }
    }
}
__device__ __forceinline__ void small_pass(float (&acc)[2][4], uint32_t aaddr, const char* slot,
                                           int lane)
{
#pragma unroll
    for (int kt = 0; kt < 8; ++kt) {
        uint32_t a0, a1, a2, a3;
        LDSM4(a0, a1, a2, a3, aaddr + kt * 32);
        const char* Bp = slot + (kt * 2 * 32 + lane) * 8;
#pragma unroll
        for (int nt = 0; nt < 2; ++nt) {
            uint2 b = *(const uint2*)(Bp + nt * 256);
            mma16816(acc[nt], a0, a1, a2, a3, b.x, b.y);
        }
    }
}
__device__ __forceinline__ void zero24(float (&a)[2][4][4]) {
#pragma unroll
    for (int t = 0; t < 2; ++t)
#pragma unroll
        for (int i = 0; i < 4; ++i)
#pragma unroll
            for (int j = 0; j < 4; ++j) a[t][i][j] = 0.f;
}
__device__ __forceinline__ void store_tile(const float (&acc)[2][4][4], char* SM, int tH, int tL,
                                           const float* bias, bool relu, int wm, int wn, int lane)
{
    const int rb = wm * 32 + (lane >> 2);
    const int m2 = (lane & 3) * 2;
#pragma unroll
    for (int t = 0; t < 2; ++t) {
        const int r1 = rb + t * 16, r2 = r1 + 8;
#pragma unroll
        for (int nt = 0; nt < 4; ++nt) {
            int cb = wn * 32 + nt * 8 + m2;
            float b0 = bias[cb], b1 = bias[cb + 1];
            float v0 = acc[t][nt][0] + b0, v1 = acc[t][nt][1] + b1;
            float v2 = acc[t][nt][2] + b0, v3 = acc[t][nt][3] + b1;
            if (relu) { v0 = fmaxf(v0, 0.f); v1 = fmaxf(v1, 0.f); v2 = fmaxf(v2, 0.f); v3 = fmaxf(v3, 0.f); }
            float h0, l0, h1, l1;
            split_h(v0, h0, l0); split_h(v1, h1, l1);
            *(uint32_t*)(SM + tH + (r1 * STRIDE + cb) * 2) = pack_h2(h0, h1);
            *(uint32_t*)(SM + tL + (r1 * STRIDE + cb) * 2) = pack_h2(l0, l1);
            split_h(v2, h0, l0); split_h(v3, h1, l1);
            *(uint32_t*)(SM + tH + (r2 * STRIDE + cb) * 2) = pack_h2(h0, h1);
            *(uint32_t*)(SM + tL + (r2 * STRIDE + cb) * 2) = pack_h2(l0, l1);
        }
    }
}
__device__ __forceinline__ void store_small(const float (&acc)[2][4], float* out,
                                            const float* bias, bool dot, int wm4, int lane)
{
    const int r1 = wm4 * 16 + (lane >> 2), r2 = r1 + 8;
    const int m2 = (lane & 3) * 2;
#pragma unroll
    for (int nt = 0; nt < 2; ++nt) {
        int c = nt * 8 + m2;
        float b0 = bias[c], b1 = bias[c + 1];
        float v0 = acc[nt][0] + b0, v1 = acc[nt][1] + b1;
        float v2 = acc[nt][2] + b0, v3 = acc[nt][3] + b1;
        if (dot) { v0 = tanhf(v0); v1 = tanhf(v1); v2 = tanhf(v2); v3 = tanhf(v3); }
        *(float2*)(out + r1 * 16 + c) = make_float2(v0, v1);
        *(float2*)(out + r2 * 16 + c) = make_float2(v2, v3);
    }
}
__device__ __forceinline__ void convert_tile(char* SM, int tH, int tL,
                                             const float* __restrict__ g, int rows, int tid)
{
#pragma unroll
    for (int i = 0; i < 8; ++i) {
        int f4 = tid + i * 256;
        int r = f4 >> 5, c4 = (f4 & 31) << 2;
        float4 v = make_float4(0.f, 0.f, 0.f, 0.f);
        if (r < rows) v = *(const float4*)(g + (size_t)r * 128 + c4);
        float h0, l0, h1, l1, h2, l2, h3, l3;
        split_h(v.x, h0, l0); split_h(v.y, h1, l1);
        split_h(v.z, h2, l2); split_h(v.w, h3, l3);
        uint2 uh, ul;
        uh.x = pack_h2(h0, h1); uh.y = pack_h2(h2, h3);
        ul.x = pack_h2(l0, l1); ul.y = pack_h2(l2, l3);
        *(uint2*)(SM + tH + (r * STRIDE + c4) * 2) = uh;
        *(uint2*)(SM + tL + (r * STRIDE + c4) * 2) = ul;
    }
}

struct Params {
    const float *src, *dst, *edge;
    const float *im2b, *mp1b, *mp2b, *qb, *kb, *vb, *ntcb, *ctob, *outb;
    float* out;
    int B;
};

__global__ __launch_bounds__(256, 1) void fused_kernel(Params p)
{
    extern __shared__ __align__(16) char SM[];
    const int tid = threadIdx.x, lane = tid & 31, wid = tid >> 5;
    const int wm = wid & 1, wn = wid >> 1;          // big-GEMM mapping
    const int wm4 = wid & 3, wn2 = wid >> 2;        // small-GEMM mapping
    const int row0 = blockIdx.x * 64;
    const int rows = min(64, p.B - row0);
    const uint32_t sbase = smem_u32(SM);
    const uint64_t gaddr = (uint64_t)__cvta_generic_to_global((void*)g_wb);
    float* BIA = (float*)(SM + BIA_B);
    float* SCO = (float*)(SM + SCO_B);
    float* GST = (float*)(SM + GST_B);

    // per-thread ldmatrix base offsets (row = lane&15, col-half = lane>>4)
    const uint32_t aoff  = sbase + (uint32_t)(((wm * 32 + (lane & 15)) * STRIDE + ((lane >> 4) & 1) * 8) * 2);
    const uint32_t aoffS = sbase + (uint32_t)(((wm4 * 16 + (lane & 15)) * STRIDE + ((lane >> 4) & 1) * 8) * 2);

#define STAGE(slot, goff, bytes) stage_fn(sbase + (slot), gaddr + (goff), (bytes), tid)

    STAGE(SMW_NTC, 266240, 8192);           // ntc + mp2 frags (contiguous)
    STAGE(RING0, 0, 32768);                 // A1

    if (tid < 128) {
        BIA[tid] = g_b1[tid];          BIA[128 + tid] = p.im2b[tid];
        BIA[256 + tid] = p.mp1b[tid];  BIA[384 + tid] = p.qb[tid];
        BIA[512 + tid] = p.kb[tid];    BIA[640 + tid] = p.vb[tid];
        BIA[768 + tid] = p.outb[tid] + p.ctob[tid];
    }
    if (tid < 16) { BIA[896 + tid] = p.mp2b[tid]; BIA[912 + tid] = p.ntcb[tid]; }
    {   // geometric-product sign table (MSB-first bit convention)
        int i = tid >> 4, j = tid & 15;
        float s = 1.f;
#pragma unroll
        for (int k = 0; k < 4; ++k)
            if ((j >> (3 - k)) & 1)
                if (__popc(i >> (4 - k)) & 1) s = -s;
        GST[tid] = s;
    }
    convert_tile(SM, TSH, TSL, p.src  + (size_t)row0 * 128, rows, tid);
    convert_tile(SM, TXH, TXL, p.edge + (size_t)row0 * 128, rows, tid);
    convert_tile(SM, TDH, TDL, p.dst  + (size_t)row0 * 128, rows, tid);
    cp_wait<1>();
    __syncthreads();                        // small weights + tiles ready

    // ---- sc (wn2=0) / dc (wn2=1): 128->16, 2-pass ----
    {
        float a2[2][4] = {};
        const uint32_t aH = aoffS + ((wn2 == 0) ? TSH : TDH);
        const uint32_t aL = aoffS + ((wn2 == 0) ? TSL : TDL);
        small_pass(a2, aH, SM + SMW_NTC, lane);
        small_pass(a2, aL, SM + SMW_NTC, lane);
        store_small(a2, (float*)(SM + ((wn2 == 0) ? SCS_B : DCS_B)), BIA + 912, false, wm4, lane);
    }

    float acc[2][4][4];
    zero24(acc);
    // ---- G1: h1 = relu(src@A1 + edge@A2 + b1) ----
    STAGE(RING1, 32768, 32768);  cp_wait<1>(); __syncthreads();
    gemm_f<8>(acc, aoff + TSH, aoff + TSL, SM + RING0, wn, lane);
    __syncthreads();
    STAGE(RING0, 65536, 32768);  cp_wait<1>(); __syncthreads();
    gemm_f<8>(acc, aoff + TXH, aoff + TXL, SM + RING1, wn, lane);
    __syncthreads();
    store_tile(acc, SM, TXH, TXL, BIA + 0, true, wm, wn, lane);
    __syncthreads();

    // ---- G2: h2 = relu(h1@im2) ----
    zero24(acc);
    STAGE(RING1, 98304, 32768);  cp_wait<1>(); __syncthreads();
    gemm_f<8>(acc, aoff + TXH, aoff + TXL, SM + RING0, wn, lane);
    __syncthreads();
    store_tile(acc, SM, TXH, TXL, BIA + 128, true, wm, wn, lane);
    __syncthreads();

    // ---- G3: h3 = relu(h2@mp1) ----
    zero24(acc);
    STAGE(RING0, 131072, 32768); cp_wait<1>(); __syncthreads();
    gemm_f<8>(acc, aoff + TXH, aoff + TXL, SM + RING1, wn, lane);
    __syncthreads();
    store_tile(acc, SM, TXH, TXL, BIA + 256, true, wm, wn, lane);
    __syncthreads();

    // ---- m16 = tanh(h3@mp2 + b) (wn2=0 warps), 2-pass ----
    if (wn2 == 0) {
        float a2[2][4] = {};
        small_pass(a2, aoffS + TXH, SM + SMW_MP2, lane);
        small_pass(a2, aoffS + TXL, SM + SMW_MP2, lane);
        store_small(a2, (float*)(SM + M16_B), BIA + 896, true, wm4, lane);
    }
    __syncthreads();

    // ---- clifford: metric + adapted inner product -> ip into TX cols 128..143 ----
    if (tid < 64) {
        const float* M16 = (float*)(SM + M16_B);
        const float* SCS = (float*)(SM + SCS_B);
        const float* DCS = (float*)(SM + DCS_B);
        int r = tid;
        float m[16], s[16], d[16];
#pragma unroll
        for (int k = 0; k < 16; ++k) {
            m[k] = M16[r * 16 + k];
            s[k] = SCS[r * 16 + k];
            d[k] = DCS[r * 16 + k];
        }
        float L[4][4];
#pragma unroll
        for (int a = 0; a < 4; ++a)
#pragma unroll
            for (int b = 0; b < 4; ++b) {
                float mv = m[a * 4 + b];
                L[a][b] = (a > b) ? mv : (a == b) ? (log1pf(expf(mv)) + 1e-6f) : 0.f;
            }
        float met[4][4];
#pragma unroll
        for (int a = 0; a < 4; ++a)
#pragma unroll
            for (int b = 0; b < 4; ++b) {
                float q = 0.f;
#pragma unroll
                for (int c = 0; c < 4; ++c) q = fmaf(L[a][c], L[b][c], q);
                met[a][b] = q;
            }
        const int VI[4] = {1, 2, 4, 8};
        float sv[4], dv[4];
#pragma unroll
        for (int a = 0; a < 4; ++a) {
            float qs = 0.f, qd = 0.f;
#pragma unroll
            for (int b = 0; b < 4; ++b) {
                qs = fmaf(met[a][b], s[VI[b]], qs);
                qd = fmaf(met[a][b], d[VI[b]], qd);
            }
            sv[a] = qs; dv[a] = qd;
        }
#pragma unroll
        for (int a = 0; a < 4; ++a) { s[VI[a]] = sv[a]; d[VI[a]] = dv[a]; }
#pragma unroll
        for (int k = 0; k < 16; ++k) {
            float q = 0.f;
#pragma unroll
            for (int i = 0; i < 16; ++i) {
                int j = i ^ k;
                q = fmaf(GST[i * 16 + j], fmaf(s[i], d[j], d[i] * s[j]), q);
            }
            float ip = 0.5f * q, h, l;
            split_h(ip, h, l);
            *(__half*)(SM + TXH + (r * STRIDE + 128 + k) * 2) = __float2half_rn(h);
            *(__half*)(SM + TXL + (r * STRIDE + 128 + k) * 2) = __float2half_rn(l);
        }
    }
    __syncthreads();

    // ---- Q = src@qW (kept in registers) ----
    float accQ[2][4][4];
    zero24(accQ);
    STAGE(RING1, 163840, 32768); cp_wait<1>(); __syncthreads();
    gemm_f<8>(accQ, aoff + TSH, aoff + TSL, SM + RING0, wn, lane);
    __syncthreads();

    // ---- K = dst@kW ----
    float accK[2][4][4];
    zero24(accK);
    STAGE(RING0, 196608, 32768); cp_wait<1>(); __syncthreads();
    gemm_f<8>(accK, aoff + TDH, aoff + TDL, SM + RING1, wn, lane);

    // ---- scores = (Q+qb).(K+kb)/4 per head (enh cancels in softmax) ----
    {
        const int rb = wm * 32 + (lane >> 2);
        const int m = lane & 3, m2 = m * 2;
#pragma unroll
        for (int e = 0; e < 2; ++e) {
            float pr[4];
#pragma unroll
            for (int t = 0; t < 2; ++t) {
                float pa = 0.f, pb = 0.f;
#pragma unroll
                for (int u = 0; u < 2; ++u) {
                    int nt = 2 * e + u, cb = wn * 32 + nt * 8 + m2;
                    float qb0 = BIA[384 + cb], qb1 = BIA[384 + cb + 1];
                    float kb0 = BIA[512 + cb], kb1 = BIA[512 + cb + 1];
                    pa += (accQ[t][nt][0] + qb0) * (accK[t][nt][0] + kb0)
                        + (accQ[t][nt][1] + qb1) * (accK[t][nt][1] + kb1);
                    pb += (accQ[t][nt][2] + qb0) * (accK[t][nt][2] + kb0)
                        + (accQ[t][nt][3] + qb1) * (accK[t][nt][3] + kb1);
                }
                pr[t * 2] = pa; pr[t * 2 + 1] = pb;
            }
#pragma unroll
            for (int j = 0; j < 4; ++j) {
                pr[j] += __shfl_xor_sync(0xFFFFFFFFu, pr[j], 1);
                pr[j] += __shfl_xor_sync(0xFFFFFFFFu, pr[j], 2);
            }
            if (m == 0) {
                int h = wn * 2 + e;
                SCO[rb * 8 + h]        = 0.25f * pr[0];
                SCO[(rb + 8) * 8 + h]  = 0.25f * pr[1];
                SCO[(rb + 16) * 8 + h] = 0.25f * pr[2];
                SCO[(rb + 24) * 8 + h] = 0.25f * pr[3];
            }
        }
    }
    __syncthreads();
    if (tid < 64) {
        float s0[8], mx = -1e30f;
#pragma unroll
        for (int h = 0; h < 8; ++h) { s0[h] = SCO[tid * 8 + h]; mx = fmaxf(mx, s0[h]); }
        float sum = 0.f;
#pragma unroll
        for (int h = 0; h < 8; ++h) { s0[h] = expf(s0[h] - mx); sum += s0[h]; }
        float inv = 1.f / sum;
#pragma unroll
        for (int h = 0; h < 8; ++h) SCO[tid * 8 + h] = s0[h] * inv;
    }
    __syncthreads();

    // ---- V = dst@vW ; att = w8*(V+vb) -> TX ----
    zero24(acc);
    STAGE(RING1, 229376, 36864); cp_wait<1>(); __syncthreads();
    gemm_f<8>(acc, aoff + TDH, aoff + TDL, SM + RING0, wn, lane);
    __syncthreads();
    {
        const int rb = wm * 32 + (lane >> 2);
        const int m2 = (lane & 3) * 2;
#pragma unroll
        for (int t = 0; t < 2; ++t) {
            const int r1 = rb + t * 16, r2 = r1 + 8;
#pragma unroll
            for (int nt = 0; nt < 4; ++nt) {
                int cb = wn * 32 + nt * 8 + m2;
                int h = wn * 2 + (nt >> 1);
                float w1 = SCO[r1 * 8 + h], w2 = SCO[r2 * 8 + h];
                float b0 = BIA[640 + cb], b1 = BIA[640 + cb + 1];
                float v0 = (acc[t][nt][0] + b0) * w1, v1 = (acc[t][nt][1] + b1) * w1;
                float v2 = (acc[t][nt][2] + b0) * w2, v3 = (acc[t][nt][3] + b1) * w2;
                float h0, l0, h1, l1;
                split_h(v0, h0, l0); split_h(v1, h1, l1);
                *(uint32_t*)(SM + TXH + (r1 * STRIDE + cb) * 2) = pack_h2(h0, h1);
                *(uint32_t*)(SM + TXL + (r1 * STRIDE + cb) * 2) = pack_h2(l0, l1);
                split_h(v2, h0, l0); split_h(v3, h1, l1);
                *(uint32_t*)(SM + TXH + (r2 * STRIDE + cb) * 2) = pack_h2(h0, h1);
                *(uint32_t*)(SM + TXL + (r2 * STRIDE + cb) * 2) = pack_h2(l0, l1);
            }
        }
    }
    __syncthreads();

    // ---- out = [att|ip]@[outW;ctoW] + (outb+ctob), 9 k-tiles ----
    zero24(acc);
    cp_wait<0>(); __syncthreads();
    gemm_f<9>(acc, aoff + TXH, aoff + TXL, SM + RING1, wn, lane);
    {
        const int rb = wm * 32 + (lane >> 2);
        const int m2 = (lane & 3) * 2;
#pragma unroll
        for (int t = 0; t < 2; ++t) {
            const int r1 = rb + t * 16, r2 = r1 + 8;
#pragma unroll
            for (int nt = 0; nt < 4; ++nt) {
                int cb = wn * 32 + nt * 8 + m2;
                float b0 = BIA[768 + cb], b1 = BIA[768 + cb + 1];
                if (r1 < rows)
                    *(float2*)(p.out + (size_t)(row0 + r1) * 128 + cb) =
                        make_float2(acc[t][nt][0] + b0, acc[t][nt][1] + b1);
                if (r2 < rows)
                    *(float2*)(p.out + (size_t)(row0 + r2) * 128 + cb) =
                        make_float2(acc[t][nt][2] + b0, acc[t][nt][3] + b1);
            }
        }
    }
}

// ---------- launch ----------
extern "C" void kernel_launch(void* const* d_in, const int* in_sizes, int n_in,
                              void* d_out, int out_size)
{
    Params p;
    p.src = (const float*)d_in[0];
    p.dst = (const float*)d_in[1];
    p.edge = (const float*)d_in[2];
    p.im2b = (const float*)d_in[10];
    p.mp1b = (const float*)d_in[12];
    p.mp2b = (const float*)d_in[14];
    p.qb   = (const float*)d_in[16];
    p.kb   = (const float*)d_in[18];
    p.vb   = (const float*)d_in[20];
    p.ntcb = (const float*)d_in[22];
    p.ctob = (const float*)d_in[24];
    p.outb = (const float*)d_in[26];
    p.out = (float*)d_out;
    p.B = in_sizes[0] / 128;

    PrepPtrs pp;
    pp.im2W = (const float*)d_in[9];
    pp.mp1W = (const float*)d_in[11];
    pp.qW   = (const float*)d_in[15];
    pp.kW   = (const float*)d_in[17];
    pp.vW   = (const float*)d_in[19];
    pp.outW = (const float*)d_in[25];
    pp.ctoW = (const float*)d_in[23];
    pp.mp2W = (const float*)d_in[13];
    pp.ntcW = (const float*)d_in[21];

    cudaFuncSetAttribute(fused_kernel, cudaFuncAttributeMaxDynamicSharedMemorySize, SMEM_BYTES);

    prep1<<<128, 512>>>((const float*)d_in[3], (const float*)d_in[4],
                        (const float*)d_in[5], (const float*)d_in[6],
                        (const float*)d_in[7], (const float*)d_in[8]);
    prep2<<<10, 256>>>(pp);
    fused_kernel<<<(p.B + 63) / 64, 256, SMEM_BYTES>>>(p);
}

// round 12
// speedup vs baseline: 5.1105x; 1.0001x over previous
#include <cuda_runtime.h>
#include <cuda_fp16.h>
#include <math.h>
#include <stdint.h>

#define STRIDE 152                  // fp16 elems per tile row (incl. ip cols + pad)
// ---- smem byte offsets ----
#define TSH 0
#define TSL 19456
#define TDH 38912
#define TDL 58368
#define TXH 77824
#define TXL 97280
#define RING0 116736
#define RING1 153600
#define SMW_NTC 190464              // ntc frag hi (4096)
#define SMW_MP2 194560              // mp2 frag hi (4096)
#define BIA_B 207872                // 928 floats
#define SCO_B 211584                // 64x8 f32
#define GST_B 213632                // 256 f32
#define SCS_B 214656                // 64x16 f32
#define DCS_B 218752
#define M16_B 222848
#define SMEM_BYTES 226944

// ---- gmem weight buffer layout (fp16 hi-only fragments) ----
// slots 0..6 (A1,A2,im2,mp1,qW,kW,vW): b*32768
// slot 7 (outW|ctoW, 9 ktiles): 229376 (36864)
// ntc: 266240 (4096); mp2: 270336 (4096)
__device__ float g_A1[128 * 128];
__device__ float g_A2[128 * 128];
__device__ float g_b1[128];
__device__ __align__(128) unsigned char g_wb[274432];

// ---------- helpers ----------
__device__ __forceinline__ uint32_t smem_u32(const void* p) {
    uint32_t a;
    asm("{ .reg .u64 t; cvta.to.shared.u64 t, %1; cvt.u32.u64 %0, t; }" : "=r"(a) : "l"(p));
    return a;
}
template<int N> __device__ __forceinline__ void cp_wait() {
    asm volatile("cp.async.wait_group %0;" :: "n"(N));
}
__device__ __forceinline__ void stage_fn(uint32_t dsm, uint64_t gsrc, int bytes, int tid) {
    for (int o = tid * 16; o < bytes; o += 4096)
        asm volatile("cp.async.cg.shared.global [%0], [%1], 16;" :: "r"(dsm + o), "l"(gsrc + o) : "memory");
    asm volatile("cp.async.commit_group;" ::: "memory");
}
__device__ __forceinline__ void mma16816(float* c, uint32_t a0, uint32_t a1, uint32_t a2, uint32_t a3,
                                         uint32_t b0, uint32_t b1) {
    asm volatile("mma.sync.aligned.m16n8k16.row.col.f32.f16.f16.f32 "
                 "{%0,%1,%2,%3}, {%4,%5,%6,%7}, {%8,%9}, {%0,%1,%2,%3};"
                 : "+f"(c[0]), "+f"(c[1]), "+f"(c[2]), "+f"(c[3])
                 : "r"(a0), "r"(a1), "r"(a2), "r"(a3), "r"(b0), "r"(b1));
}
#define LDSM4(r0, r1, r2, r3, addr) \
    asm volatile("ldmatrix.sync.aligned.m8n8.x4.shared.b16 {%0,%1,%2,%3}, [%4];" \
                 : "=r"(r0), "=r"(r1), "=r"(r2), "=r"(r3) : "r"(addr))

__device__ __host__ __forceinline__ uint32_t frag_off(int k, int n, int ntiles) {
    int kt = k >> 4, kk = k & 15;
    int reg = kk >> 3, r8 = kk & 7, m = r8 >> 1, half = r8 & 1;
    int nt = n >> 3, ln = (n & 7) * 4 + m;
    return (uint32_t)((kt * ntiles + nt) * 32 + ln) * 8u + (uint32_t)reg * 4u + (uint32_t)half * 2u;
}
__device__ __forceinline__ uint32_t pack_h2(float a, float b) {
    __half2 t;
    t.x = __float2half_rn(a);
    t.y = __float2half_rn(b);
    return *(uint32_t*)&t;
}
__device__ __forceinline__ void split_h(float v, float& hi, float& lo) {
    __half h = __float2half_rn(v);
    hi = __half2float(h);
    lo = v - hi;
}

// ---------- prep kernels ----------
__global__ void prep1(const float* __restrict__ npW, const float* __restrict__ npb,
                      const float* __restrict__ epW, const float* __restrict__ epb,
                      const float* __restrict__ im1W, const float* __restrict__ im1b)
{
    __shared__ float red[1024];
    const int i = blockIdx.x;
    const int o = threadIdx.x & 127, q = threadIdx.x >> 7;   // 4-way h split
    float s1 = 0.f, s2 = 0.f;
#pragma unroll 8
    for (int h = q * 32; h < q * 32 + 32; ++h) {
        s1 = fmaf(__ldg(npW + i * 128 + h), __ldg(im1W + h * 128 + o), s1);
        s2 = fmaf(__ldg(epW + i * 128 + h), __ldg(im1W + (128 + h) * 128 + o), s2);
    }
    red[q * 128 + o] = s1;
    red[512 + q * 128 + o] = s2;
    __syncthreads();
    if (q == 0) {
        g_A1[i * 128 + o] = red[o] + red[128 + o] + red[256 + o] + red[384 + o];
        g_A2[i * 128 + o] = red[512 + o] + red[640 + o] + red[768 + o] + red[896 + o];
        if (i == 0) {
            float sb = im1b[o];
#pragma unroll 8
            for (int h = 0; h < 128; ++h)
                sb += npb[h] * im1W[h * 128 + o] + epb[h] * im1W[(128 + h) * 128 + o];
            g_b1[o] = sb;
        }
    }
}

struct PrepPtrs { const float *im2W, *mp1W, *qW, *kW, *vW, *outW, *ctoW, *mp2W, *ntcW; };

__global__ void prep2(PrepPtrs pp)
{
    const int b = blockIdx.x;
    if (b < 7) {
        const float* W = nullptr;
        switch (b) { case 2: W = pp.im2W; break; case 3: W = pp.mp1W; break;
                     case 4: W = pp.qW; break; case 5: W = pp.kW; break;
                     case 6: W = pp.vW; break; default: break; }
        unsigned char* base = g_wb + b * 32768;
        for (int idx = threadIdx.x; idx < 16384; idx += blockDim.x) {
            int k = idx >> 7, n = idx & 127;
            float v = (b == 0) ? g_A1[idx] : (b == 1) ? g_A2[idx] : W[idx];
            *(__half*)(base + frag_off(k, n, 16)) = __float2half_rn(v);
        }
    } else if (b == 7) {
        unsigned char* base = g_wb + 229376;
        for (int idx = threadIdx.x; idx < 144 * 128; idx += blockDim.x) {
            int k = idx >> 7, n = idx & 127;
            float v = (k < 128) ? pp.outW[k * 128 + n] : pp.ctoW[(k - 128) * 128 + n];
            *(__half*)(base + frag_off(k, n, 16)) = __float2half_rn(v);
        }
    } else {
        const float* W = (b == 8) ? pp.ntcW : pp.mp2W;
        unsigned char* base = g_wb + ((b == 8) ? 266240 : 270336);
        for (int idx = threadIdx.x; idx < 2048; idx += blockDim.x) {
            int k = idx >> 4, n = idx & 15;
            *(__half*)(base + frag_off(k, n, 2)) = __float2half_rn(W[idx]);
        }
    }
}

// ---------- GEMM pieces (warp tile 32x32; wm in {0,1}, wn in {0..3}) ----------
// fused 2-pass: A-hi and A-lo share each B fragment; A via ldmatrix.x4
template<int NKT>
__device__ __forceinline__ void gemm_f(float (&acc)[2][4][4], uint32_t aH, uint32_t aL,
                                       const char* slot, int wn, int lane)
{
#pragma unroll
    for (int kt = 0; kt < NKT; ++kt) {
        uint32_t ah[2][4], al[2][4];
#pragma unroll
        for (int t = 0; t < 2; ++t) {
            LDSM4(ah[t][0], ah[t][1], ah[t][2], ah[t][3], aH + t * (16 * STRIDE * 2) + kt * 32);
            LDSM4(al[t][0], al[t][1], al[t][2], al[t][3], aL + t * (16 * STRIDE * 2) + kt * 32);
        }
        const char* Bp = slot + ((kt * 16 + wn * 4) * 32 + lane) * 8;
#pragma unroll
        for (int nt = 0; nt < 4; ++nt) {
            uint2 b = *(const uint2*)(Bp + nt * 256);
#pragma unroll
            for (int t = 0; t < 2; ++t) {
                mma16816(acc[t][nt], ah[t][0], ah[t][1], ah[t][2], ah[t][3], b.x, b.y);
                mma16816(acc[t][nt], al[t][0], al[t][1], al[t][2], al[t][3], b.x, b.y);
            }
        }
    }
}
__device__ __forceinline__ void small_pass(float (&acc)[2][4], uint32_t aaddr, const char* slot,
                                           int lane)
{
#pragma unroll
    for (int kt = 0; kt < 8; ++kt) {
        uint32_t a0, a1, a2, a3;
        LDSM4(a0, a1, a2, a3, aaddr + kt * 32);
        const char* Bp = slot + (kt * 2 * 32 + lane) * 8;
#pragma unroll
        for (int nt = 0; nt < 2; ++nt) {
            uint2 b = *(const uint2*)(Bp + nt * 256);
            mma16816(acc[nt], a0, a1, a2, a3, b.x, b.y);
        }
    }
}
__device__ __forceinline__ void zero24(float (&a)[2][4][4]) {
#pragma unroll
    for (int t = 0; t < 2; ++t)
#pragma unroll
        for (int i = 0; i < 4; ++i)
#pragma unroll
            for (int j = 0; j < 4; ++j) a[t][i][j] = 0.f;
}
__device__ __forceinline__ void store_tile(const float (&acc)[2][4][4], char* SM, int tH, int tL,
                                           const float* bias, bool relu, int wm, int wn, int lane)
{
    const int rb = wm * 32 + (lane >> 2);
    const int m2 = (lane & 3) * 2;
#pragma unroll
    for (int t = 0; t < 2; ++t) {
        const int r1 = rb + t * 16, r2 = r1 + 8;
#pragma unroll
        for (int nt = 0; nt < 4; ++nt) {
            int cb = wn * 32 + nt * 8 + m2;
            float b0 = bias[cb], b1 = bias[cb + 1];
            float v0 = acc[t][nt][0] + b0, v1 = acc[t][nt][1] + b1;
            float v2 = acc[t][nt][2] + b0, v3 = acc[t][nt][3] + b1;
            if (relu) { v0 = fmaxf(v0, 0.f); v1 = fmaxf(v1, 0.f); v2 = fmaxf(v2, 0.f); v3 = fmaxf(v3, 0.f); }
            float h0, l0, h1, l1;
            split_h(v0, h0, l0); split_h(v1, h1, l1);
            *(uint32_t*)(SM + tH + (r1 * STRIDE + cb) * 2) = pack_h2(h0, h1);
            *(uint32_t*)(SM + tL + (r1 * STRIDE + cb) * 2) = pack_h2(l0, l1);
            split_h(v2, h0, l0); split_h(v3, h1, l1);
            *(uint32_t*)(SM + tH + (r2 * STRIDE + cb) * 2) = pack_h2(h0, h1);
            *(uint32_t*)(SM + tL + (r2 * STRIDE + cb) * 2) = pack_h2(l0, l1);
        }
    }
}
__device__ __forceinline__ void store_small(const float (&acc)[2][4], float* out,
                                            const float* bias, bool dot, int wm4, int lane)
{
    const int r1 = wm4 * 16 + (lane >> 2), r2 = r1 + 8;
    const int m2 = (lane & 3) * 2;
#pragma unroll
    for (int nt = 0; nt < 2; ++nt) {
        int c = nt * 8 + m2;
        float b0 = bias[c], b1 = bias[c + 1];
        float v0 = acc[nt][0] + b0, v1 = acc[nt][1] + b1;
        float v2 = acc[nt][2] + b0, v3 = acc[nt][3] + b1;
        if (dot) { v0 = tanhf(v0); v1 = tanhf(v1); v2 = tanhf(v2); v3 = tanhf(v3); }
        *(float2*)(out + r1 * 16 + c) = make_float2(v0, v1);
        *(float2*)(out + r2 * 16 + c) = make_float2(v2, v3);
    }
}
__device__ __forceinline__ void convert_tile(char* SM, int tH, int tL,
                                             const float* __restrict__ g, int rows, int tid)
{
#pragma unroll
    for (int i = 0; i < 8; ++i) {
        int f4 = tid + i * 256;
        int r = f4 >> 5, c4 = (f4 & 31) << 2;
        float4 v = make_float4(0.f, 0.f, 0.f, 0.f);
        if (r < rows) v = *(const float4*)(g + (size_t)r * 128 + c4);
        float h0, l0, h1, l1, h2, l2, h3, l3;
        split_h(v.x, h0, l0); split_h(v.y, h1, l1);
        split_h(v.z, h2, l2); split_h(v.w, h3, l3);
        uint2 uh, ul;
        uh.x = pack_h2(h0, h1); uh.y = pack_h2(h2, h3);
        ul.x = pack_h2(l0, l1); ul.y = pack_h2(l2, l3);
        *(uint2*)(SM + tH + (r * STRIDE + c4) * 2) = uh;
        *(uint2*)(SM + tL + (r * STRIDE + c4) * 2) = ul;
    }
}

struct Params {
    const float *src, *dst, *edge;
    const float *im2b, *mp1b, *mp2b, *qb, *kb, *vb, *ntcb, *ctob, *outb;
    float* out;
    int B;
};

__global__ __launch_bounds__(256, 1) void fused_kernel(Params p)
{
    extern __shared__ __align__(16) char SM[];
    const int tid = threadIdx.x, lane = tid & 31, wid = tid >> 5;
    const int wm = wid & 1, wn = wid >> 1;          // big-GEMM mapping
    const int wm4 = wid & 3, wn2 = wid >> 2;        // small-GEMM mapping
    const int row0 = blockIdx.x * 64;
    const int rows = min(64, p.B - row0);
    const uint32_t sbase = smem_u32(SM);
    const uint64_t gaddr = (uint64_t)__cvta_generic_to_global((void*)g_wb);
    float* BIA = (float*)(SM + BIA_B);
    float* SCO = (float*)(SM + SCO_B);
    float* GST = (float*)(SM + GST_B);

    // per-thread ldmatrix base offsets (row = lane&15, col-half = lane>>4)
    const uint32_t aoff  = sbase + (uint32_t)(((wm * 32 + (lane & 15)) * STRIDE + ((lane >> 4) & 1) * 8) * 2);
    const uint32_t aoffS = sbase + (uint32_t)(((wm4 * 16 + (lane & 15)) * STRIDE + ((lane >> 4) & 1) * 8) * 2);

#define STAGE(slot, goff, bytes) stage_fn(sbase + (slot), gaddr + (goff), (bytes), tid)

    STAGE(SMW_NTC, 266240, 8192);           // ntc + mp2 frags (contiguous)
    STAGE(RING0, 0, 32768);                 // A1

    if (tid < 128) {
        BIA[tid] = g_b1[tid];          BIA[128 + tid] = p.im2b[tid];
        BIA[256 + tid] = p.mp1b[tid];  BIA[384 + tid] = p.qb[tid];
        BIA[512 + tid] = p.kb[tid];    BIA[640 + tid] = p.vb[tid];
        BIA[768 + tid] = p.outb[tid] + p.ctob[tid];
    }
    if (tid < 16) { BIA[896 + tid] = p.mp2b[tid]; BIA[912 + tid] = p.ntcb[tid]; }
    {   // geometric-product sign table (MSB-first bit convention)
        int i = tid >> 4, j = tid & 15;
        float s = 1.f;
#pragma unroll
        for (int k = 0; k < 4; ++k)
            if ((j >> (3 - k)) & 1)
                if (__popc(i >> (4 - k)) & 1) s = -s;
        GST[tid] = s;
    }
    convert_tile(SM, TSH, TSL, p.src  + (size_t)row0 * 128, rows, tid);
    convert_tile(SM, TXH, TXL, p.edge + (size_t)row0 * 128, rows, tid);
    convert_tile(SM, TDH, TDL, p.dst  + (size_t)row0 * 128, rows, tid);
    cp_wait<1>();
    __syncthreads();                        // small weights + tiles ready

    // ---- sc (wn2=0) / dc (wn2=1): 128->16, 2-pass ----
    {
        float a2[2][4] = {};
        const uint32_t aH = aoffS + ((wn2 == 0) ? TSH : TDH);
        const uint32_t aL = aoffS + ((wn2 == 0) ? TSL : TDL);
        small_pass(a2, aH, SM + SMW_NTC, lane);
        small_pass(a2, aL, SM + SMW_NTC, lane);
        store_small(a2, (float*)(SM + ((wn2 == 0) ? SCS_B : DCS_B)), BIA + 912, false, wm4, lane);
    }

    float acc[2][4][4];
    zero24(acc);
    // ---- G1: h1 = relu(src@A1 + edge@A2 + b1) ----
    STAGE(RING1, 32768, 32768);  cp_wait<1>(); __syncthreads();
    gemm_f<8>(acc, aoff + TSH, aoff + TSL, SM + RING0, wn, lane);
    __syncthreads();
    STAGE(RING0, 65536, 32768);  cp_wait<1>(); __syncthreads();
    gemm_f<8>(acc, aoff + TXH, aoff + TXL, SM + RING1, wn, lane);
    __syncthreads();
    store_tile(acc, SM, TXH, TXL, BIA + 0, true, wm, wn, lane);
    __syncthreads();

    // ---- G2: h2 = relu(h1@im2) ----
    zero24(acc);
    STAGE(RING1, 98304, 32768);  cp_wait<1>(); __syncthreads();
    gemm_f<8>(acc, aoff + TXH, aoff + TXL, SM + RING0, wn, lane);
    __syncthreads();
    store_tile(acc, SM, TXH, TXL, BIA + 128, true, wm, wn, lane);
    __syncthreads();

    // ---- G3: h3 = relu(h2@mp1) ----
    zero24(acc);
    STAGE(RING0, 131072, 32768); cp_wait<1>(); __syncthreads();
    gemm_f<8>(acc, aoff + TXH, aoff + TXL, SM + RING1, wn, lane);
    __syncthreads();
    store_tile(acc, SM, TXH, TXL, BIA + 256, true, wm, wn, lane);
    __syncthreads();

    // ---- m16 = tanh(h3@mp2 + b) (wn2=0 warps), 2-pass ----
    if (wn2 == 0) {
        float a2[2][4] = {};
        small_pass(a2, aoffS + TXH, SM + SMW_MP2, lane);
        small_pass(a2, aoffS + TXL, SM + SMW_MP2, lane);
        store_small(a2, (float*)(SM + M16_B), BIA + 896, true, wm4, lane);
    }
    __syncthreads();

    // ---- clifford: metric + adapted inner product -> ip into TX cols 128..143 ----
    if (tid < 64) {
        const float* M16 = (float*)(SM + M16_B);
        const float* SCS = (float*)(SM + SCS_B);
        const float* DCS = (float*)(SM + DCS_B);
        int r = tid;
        float m[16], s[16], d[16];
#pragma unroll
        for (int k = 0; k < 16; ++k) {
            m[k] = M16[r * 16 + k];
            s[k] = SCS[r * 16 + k];
            d[k] = DCS[r * 16 + k];
        }
        float L[4][4];
#pragma unroll
        for (int a = 0; a < 4; ++a)
#pragma unroll
            for (int b = 0; b < 4; ++b) {
                float mv = m[a * 4 + b];
                L[a][b] = (a > b) ? mv : (a == b) ? (log1pf(expf(mv)) + 1e-6f) : 0.f;
            }
        float met[4][4];
#pragma unroll
        for (int a = 0; a < 4; ++a)
#pragma unroll
            for (int b = 0; b < 4; ++b) {
                float q = 0.f;
#pragma unroll
                for (int c = 0; c < 4; ++c) q = fmaf(L[a][c], L[b][c], q);
                met[a][b] = q;
            }
        const int VI[4] = {1, 2, 4, 8};
        float sv[4], dv[4];
#pragma unroll
        for (int a = 0; a < 4; ++a) {
            float qs = 0.f, qd = 0.f;
#pragma unroll
            for (int b = 0; b < 4; ++b) {
                qs = fmaf(met[a][b], s[VI[b]], qs);
                qd = fmaf(met[a][b], d[VI[b]], qd);
            }
            sv[a] = qs; dv[a] = qd;
        }
#pragma unroll
        for (int a = 0; a < 4; ++a) { s[VI[a]] = sv[a]; d[VI[a]] = dv[a]; }
#pragma unroll
        for (int k = 0; k < 16; ++k) {
            float q = 0.f;
#pragma unroll
            for (int i = 0; i < 16; ++i) {
                int j = i ^ k;
                q = fmaf(GST[i * 16 + j], fmaf(s[i], d[j], d[i] * s[j]), q);
            }
            float ip = 0.5f * q, h, l;
            split_h(ip, h, l);
            *(__half*)(SM + TXH + (r * STRIDE + 128 + k) * 2) = __float2half_rn(h);
            *(__half*)(SM + TXL + (r * STRIDE + 128 + k) * 2) = __float2half_rn(l);
        }
    }
    __syncthreads();

    // ---- Q = src@qW (kept in registers) ----
    float accQ[2][4][4];
    zero24(accQ);
    STAGE(RING1, 163840, 32768); cp_wait<1>(); __syncthreads();
    gemm_f<8>(accQ, aoff + TSH, aoff + TSL, SM + RING0, wn, lane);
    __syncthreads();

    // ---- K = dst@kW ----
    float accK[2][4][4];
    zero24(accK);
    STAGE(RING0, 196608, 32768); cp_wait<1>(); __syncthreads();
    gemm_f<8>(accK, aoff + TDH, aoff + TDL, SM + RING1, wn, lane);

    // ---- scores = (Q+qb).(K+kb)/4 per head (enh cancels in softmax) ----
    {
        const int rb = wm * 32 + (lane >> 2);
        const int m = lane & 3, m2 = m * 2;
#pragma unroll
        for (int e = 0; e < 2; ++e) {
            float pr[4];
#pragma unroll
            for (int t = 0; t < 2; ++t) {
                float pa = 0.f, pb = 0.f;
#pragma unroll
                for (int u = 0; u < 2; ++u) {
                    int nt = 2 * e + u, cb = wn * 32 + nt * 8 + m2;
                    float qb0 = BIA[384 + cb], qb1 = BIA[384 + cb + 1];
                    float kb0 = BIA[512 + cb], kb1 = BIA[512 + cb + 1];
                    pa += (accQ[t][nt][0] + qb0) * (accK[t][nt][0] + kb0)
                        + (accQ[t][nt][1] + qb1) * (accK[t][nt][1] + kb1);
                    pb += (accQ[t][nt][2] + qb0) * (accK[t][nt][2] + kb0)
                        + (accQ[t][nt][3] + qb1) * (accK[t][nt][3] + kb1);
                }
                pr[t * 2] = pa; pr[t * 2 + 1] = pb;
            }
#pragma unroll
            for (int j = 0; j < 4; ++j) {
                pr[j] += __shfl_xor_sync(0xFFFFFFFFu, pr[j], 1);
                pr[j] += __shfl_xor_sync(0xFFFFFFFFu, pr[j], 2);
            }
            if (m == 0) {
                int h = wn * 2 + e;
                SCO[rb * 8 + h]        = 0.25f * pr[0];
                SCO[(rb + 8) * 8 + h]  = 0.25f * pr[1];
                SCO[(rb + 16) * 8 + h] = 0.25f * pr[2];
                SCO[(rb + 24) * 8 + h] = 0.25f * pr[3];
            }
        }
    }
    __syncthreads();
    if (tid < 64) {
        float s0[8], mx = -1e30f;
#pragma unroll
        for (int h = 0; h < 8; ++h) { s0[h] = SCO[tid * 8 + h]; mx = fmaxf(mx, s0[h]); }
        float sum = 0.f;
#pragma unroll
        for (int h = 0; h < 8; ++h) { s0[h] = expf(s0[h] - mx); sum += s0[h]; }
        float inv = 1.f / sum;
#pragma unroll
        for (int h = 0; h < 8; ++h) SCO[tid * 8 + h] = s0[h] * inv;
    }
    __syncthreads();

    // ---- V = dst@vW ; att = w8*(V+vb) -> TX ----
    zero24(acc);
    STAGE(RING1, 229376, 36864); cp_wait<1>(); __syncthreads();
    gemm_f<8>(acc, aoff + TDH, aoff + TDL, SM + RING0, wn, lane);
    __syncthreads();
    {
        const int rb = wm * 32 + (lane >> 2);
        const int m2 = (lane & 3) * 2;
#pragma unroll
        for (int t = 0; t < 2; ++t) {
            const int r1 = rb + t * 16, r2 = r1 + 8;
#pragma unroll
            for (int nt = 0; nt < 4; ++nt) {
                int cb = wn * 32 + nt * 8 + m2;
                int h = wn * 2 + (nt >> 1);
                float w1 = SCO[r1 * 8 + h], w2 = SCO[r2 * 8 + h];
                float b0 = BIA[640 + cb], b1 = BIA[640 + cb + 1];
                float v0 = (acc[t][nt][0] + b0) * w1, v1 = (acc[t][nt][1] + b1) * w1;
                float v2 = (acc[t][nt][2] + b0) * w2, v3 = (acc[t][nt][3] + b1) * w2;
                float h0, l0, h1, l1;
                split_h(v0, h0, l0); split_h(v1, h1, l1);
                *(uint32_t*)(SM + TXH + (r1 * STRIDE + cb) * 2) = pack_h2(h0, h1);
                *(uint32_t*)(SM + TXL + (r1 * STRIDE + cb) * 2) = pack_h2(l0, l1);
                split_h(v2, h0, l0); split_h(v3, h1, l1);
                *(uint32_t*)(SM + TXH + (r2 * STRIDE + cb) * 2) = pack_h2(h0, h1);
                *(uint32_t*)(SM + TXL + (r2 * STRIDE + cb) * 2) = pack_h2(l0, l1);
            }
        }
    }
    __syncthreads();

    // ---- out = [att|ip]@[outW;ctoW] + (outb+ctob), 9 k-tiles ----
    zero24(acc);
    cp_wait<0>(); __syncthreads();
    gemm_f<9>(acc, aoff + TXH, aoff + TXL, SM + RING1, wn, lane);
    {
        const int rb = wm * 32 + (lane >> 2);
        const int m2 = (lane & 3) * 2;
#pragma unroll
        for (int t = 0; t < 2; ++t) {
            const int r1 = rb + t * 16, r2 = r1 + 8;
#pragma unroll
            for (int nt = 0; nt < 4; ++nt) {
                int cb = wn * 32 + nt * 8 + m2;
                float b0 = BIA[768 + cb], b1 = BIA[768 + cb + 1];
                if (r1 < rows)
                    *(float2*)(p.out + (size_t)(row0 + r1) * 128 + cb) =
                        make_float2(acc[t][nt][0] + b0, acc[t][nt][1] + b1);
                if (r2 < rows)
                    *(float2*)(p.out + (size_t)(row0 + r2) * 128 + cb) =
                        make_float2(acc[t][nt][2] + b0, acc[t][nt][3] + b1);
            }
        }
    }
}

// ---------- launch ----------
extern "C" void kernel_launch(void* const* d_in, const int* in_sizes, int n_in,
                              void* d_out, int out_size)
{
    Params p;
    p.src = (const float*)d_in[0];
    p.dst = (const float*)d_in[1];
    p.edge = (const float*)d_in[2];
    p.im2b = (const float*)d_in[10];
    p.mp1b = (const float*)d_in[12];
    p.mp2b = (const float*)d_in[14];
    p.qb   = (const float*)d_in[16];
    p.kb   = (const float*)d_in[18];
    p.vb   = (const float*)d_in[20];
    p.ntcb = (const float*)d_in[22];
    p.ctob = (const float*)d_in[24];
    p.outb = (const float*)d_in[26];
    p.out = (float*)d_out;
    p.B = in_sizes[0] / 128;

    PrepPtrs pp;
    pp.im2W = (const float*)d_in[9];
    pp.mp1W = (const float*)d_in[11];
    pp.qW   = (const float*)d_in[15];
    pp.kW   = (const float*)d_in[17];
    pp.vW   = (const float*)d_in[19];
    pp.outW = (const float*)d_in[25];
    pp.ctoW = (const float*)d_in[23];
    pp.mp2W = (const float*)d_in[13];
    pp.ntcW = (const float*)d_in[21];

    cudaFuncSetAttribute(fused_kernel, cudaFuncAttributeMaxDynamicSharedMemorySize, SMEM_BYTES);

    prep1<<<128, 512>>>((const float*)d_in[3], (const float*)d_in[4],
                        (const float*)d_in[5], (const float*)d_in[6],
                        (const float*)d_in[7], (const float*)d_in[8]);
    prep2<<<10, 256>>>(pp);
    fused_kernel<<<(p.B + 63) / 64, 256, SMEM_BYTES>>>(p);
}

// round 13
// speedup vs baseline: 5.5288x; 1.0819x over previous
#include <cuda_runtime.h>
#include <cuda_fp16.h>
#include <math.h>
#include <stdint.h>

#define STRIDE 152                  // fp16 elems per tile row (incl. ip cols + pad)
// ---- smem byte offsets ----
#define TSH 0
#define TSL 19456
#define TDH 38912
#define TDL 58368
#define TXH 77824
#define TXL 97280
#define RING0 116736
#define RING1 153600
#define SMW_NTC 190464              // ntc frag hi (4096)
#define SMW_MP2 194560              // mp2 frag hi (4096)
#define BIA_B 207872                // 928 floats
#define SCO_B 211584                // 64x8 f32
#define GST_B 213632                // 256 f32
#define SCS_B 214656                // 64x16 f32
#define DCS_B 218752
#define M16_B 222848
#define SMEM_BYTES 226944

// ---- gmem weight buffer layout (fp16 hi-only fragments) ----
// slots 0..6 (A1,A2,im2,mp1,qW,kW,vW): b*32768
// slot 7 (outW|ctoW, 9 ktiles): 229376 (36864)
// ntc: 266240 (4096); mp2: 270336 (4096)
__device__ float g_A1[128 * 128];
__device__ float g_A2[128 * 128];
__device__ float g_b1[128];
__device__ __align__(128) unsigned char g_wb[274432];

// ---------- helpers ----------
__device__ __forceinline__ uint32_t smem_u32(const void* p) {
    uint32_t a;
    asm("{ .reg .u64 t; cvta.to.shared.u64 t, %1; cvt.u32.u64 %0, t; }" : "=r"(a) : "l"(p));
    return a;
}
template<int N> __device__ __forceinline__ void cp_wait() {
    asm volatile("cp.async.wait_group %0;" :: "n"(N));
}
__device__ __forceinline__ void stage_fn(uint32_t dsm, uint64_t gsrc, int bytes, int tid) {
    for (int o = tid * 16; o < bytes; o += 4096)
        asm volatile("cp.async.cg.shared.global [%0], [%1], 16;" :: "r"(dsm + o), "l"(gsrc + o) : "memory");
    asm volatile("cp.async.commit_group;" ::: "memory");
}
__device__ __forceinline__ void mma16816(float* c, uint32_t a0, uint32_t a1, uint32_t a2, uint32_t a3,
                                         uint32_t b0, uint32_t b1) {
    asm volatile("mma.sync.aligned.m16n8k16.row.col.f32.f16.f16.f32 "
                 "{%0,%1,%2,%3}, {%4,%5,%6,%7}, {%8,%9}, {%0,%1,%2,%3};"
                 : "+f"(c[0]), "+f"(c[1]), "+f"(c[2]), "+f"(c[3])
                 : "r"(a0), "r"(a1), "r"(a2), "r"(a3), "r"(b0), "r"(b1));
}
#define LDSM4(r0, r1, r2, r3, addr) \
    asm volatile("ldmatrix.sync.aligned.m8n8.x4.shared.b16 {%0,%1,%2,%3}, [%4];" \
                 : "=r"(r0), "=r"(r1), "=r"(r2), "=r"(r3) : "r"(addr))

__device__ __host__ __forceinline__ uint32_t frag_off(int k, int n, int ntiles) {
    int kt = k >> 4, kk = k & 15;
    int reg = kk >> 3, r8 = kk & 7, m = r8 >> 1, half = r8 & 1;
    int nt = n >> 3, ln = (n & 7) * 4 + m;
    return (uint32_t)((kt * ntiles + nt) * 32 + ln) * 8u + (uint32_t)reg * 4u + (uint32_t)half * 2u;
}
__device__ __forceinline__ uint32_t pack_h2(float a, float b) {
    __half2 t;
    t.x = __float2half_rn(a);
    t.y = __float2half_rn(b);
    return *(uint32_t*)&t;
}
__device__ __forceinline__ void split_h(float v, float& hi, float& lo) {
    __half h = __float2half_rn(v);
    hi = __half2float(h);
    lo = v - hi;
}

// ---------- prep kernels ----------
__global__ void prep1(const float* __restrict__ npW, const float* __restrict__ npb,
                      const float* __restrict__ epW, const float* __restrict__ epb,
                      const float* __restrict__ im1W, const float* __restrict__ im1b)
{
    __shared__ float red[1024];
    const int i = blockIdx.x;
    const int o = threadIdx.x & 127, q = threadIdx.x >> 7;   // 4-way h split
    float s1 = 0.f, s2 = 0.f;
#pragma unroll 8
    for (int h = q * 32; h < q * 32 + 32; ++h) {
        s1 = fmaf(__ldg(npW + i * 128 + h), __ldg(im1W + h * 128 + o), s1);
        s2 = fmaf(__ldg(epW + i * 128 + h), __ldg(im1W + (128 + h) * 128 + o), s2);
    }
    red[q * 128 + o] = s1;
    red[512 + q * 128 + o] = s2;
    __syncthreads();
    if (q == 0) {
        g_A1[i * 128 + o] = red[o] + red[128 + o] + red[256 + o] + red[384 + o];
        g_A2[i * 128 + o] = red[512 + o] + red[640 + o] + red[768 + o] + red[896 + o];
        if (i == 0) {
            float sb = im1b[o];
#pragma unroll 8
            for (int h = 0; h < 128; ++h)
                sb += npb[h] * im1W[h * 128 + o] + epb[h] * im1W[(128 + h) * 128 + o];
            g_b1[o] = sb;
        }
    }
}

struct PrepPtrs { const float *im2W, *mp1W, *qW, *kW, *vW, *outW, *ctoW, *mp2W, *ntcW; };

__global__ void prep2(PrepPtrs pp)
{
    const int b = blockIdx.x;
    if (b < 7) {
        const float* W = nullptr;
        switch (b) { case 2: W = pp.im2W; break; case 3: W = pp.mp1W; break;
                     case 4: W = pp.qW; break; case 5: W = pp.kW; break;
                     case 6: W = pp.vW; break; default: break; }
        unsigned char* base = g_wb + b * 32768;
        for (int idx = threadIdx.x; idx < 16384; idx += blockDim.x) {
            int k = idx >> 7, n = idx & 127;
            float v = (b == 0) ? g_A1[idx] : (b == 1) ? g_A2[idx] : W[idx];
            *(__half*)(base + frag_off(k, n, 16)) = __float2half_rn(v);
        }
    } else if (b == 7) {
        unsigned char* base = g_wb + 229376;
        for (int idx = threadIdx.x; idx < 144 * 128; idx += blockDim.x) {
            int k = idx >> 7, n = idx & 127;
            float v = (k < 128) ? pp.outW[k * 128 + n] : pp.ctoW[(k - 128) * 128 + n];
            *(__half*)(base + frag_off(k, n, 16)) = __float2half_rn(v);
        }
    } else {
        const float* W = (b == 8) ? pp.ntcW : pp.mp2W;
        unsigned char* base = g_wb + ((b == 8) ? 266240 : 270336);
        for (int idx = threadIdx.x; idx < 2048; idx += blockDim.x) {
            int k = idx >> 4, n = idx & 15;
            *(__half*)(base + frag_off(k, n, 2)) = __float2half_rn(W[idx]);
        }
    }
}

// ---------- GEMM pieces (warp tile 32x32; wm in {0,1}, wn in {0..3}) ----------
// fused 2-pass: A-hi and A-lo share each B fragment; A via ldmatrix.x4
template<int NKT>
__device__ __forceinline__ void gemm_f(float (&acc)[2][4][4], uint32_t aH, uint32_t aL,
                                       const char* slot, int wn, int lane)
{
#pragma unroll
    for (int kt = 0; kt < NKT; ++kt) {
        uint32_t ah[2][4], al[2][4];
#pragma unroll
        for (int t = 0; t < 2; ++t) {
            LDSM4(ah[t][0], ah[t][1], ah[t][2], ah[t][3], aH + t * (16 * STRIDE * 2) + kt * 32);
            LDSM4(al[t][0], al[t][1], al[t][2], al[t][3], aL + t * (16 * STRIDE * 2) + kt * 32);
        }
        const char* Bp = slot + ((kt * 16 + wn * 4) * 32 + lane) * 8;
#pragma unroll
        for (int nt = 0; nt < 4; ++nt) {
            uint2 b = *(const uint2*)(Bp + nt * 256);
#pragma unroll
            for (int t = 0; t < 2; ++t) {
                mma16816(acc[t][nt], ah[t][0], ah[t][1], ah[t][2], ah[t][3], b.x, b.y);
                mma16816(acc[t][nt], al[t][0], al[t][1], al[t][2], al[t][3], b.x, b.y);
            }
        }
    }
}
// 1-pass (A-hi only) — used on the error-damped metric chain (G1..G3)
template<int NKT>
__device__ __forceinline__ void gemm_1(float (&acc)[2][4][4], uint32_t aH,
                                       const char* slot, int wn, int lane)
{
#pragma unroll
    for (int kt = 0; kt < NKT; ++kt) {
        uint32_t ah[2][4];
#pragma unroll
        for (int t = 0; t < 2; ++t)
            LDSM4(ah[t][0], ah[t][1], ah[t][2], ah[t][3], aH + t * (16 * STRIDE * 2) + kt * 32);
        const char* Bp = slot + ((kt * 16 + wn * 4) * 32 + lane) * 8;
#pragma unroll
        for (int nt = 0; nt < 4; ++nt) {
            uint2 b = *(const uint2*)(Bp + nt * 256);
#pragma unroll
            for (int t = 0; t < 2; ++t)
                mma16816(acc[t][nt], ah[t][0], ah[t][1], ah[t][2], ah[t][3], b.x, b.y);
        }
    }
}
__device__ __forceinline__ void small_pass(float (&acc)[2][4], uint32_t aaddr, const char* slot,
                                           int lane)
{
#pragma unroll
    for (int kt = 0; kt < 8; ++kt) {
        uint32_t a0, a1, a2, a3;
        LDSM4(a0, a1, a2, a3, aaddr + kt * 32);
        const char* Bp = slot + (kt * 2 * 32 + lane) * 8;
#pragma unroll
        for (int nt = 0; nt < 2; ++nt) {
            uint2 b = *(const uint2*)(Bp + nt * 256);
            mma16816(acc[nt], a0, a1, a2, a3, b.x, b.y);
        }
    }
}
__device__ __forceinline__ void zero24(float (&a)[2][4][4]) {
#pragma unroll
    for (int t = 0; t < 2; ++t)
#pragma unroll
        for (int i = 0; i < 4; ++i)
#pragma unroll
            for (int j = 0; j < 4; ++j) a[t][i][j] = 0.f;
}
__device__ __forceinline__ void store_tile(const float (&acc)[2][4][4], char* SM, int tH, int tL,
                                           const float* bias, bool relu, int wm, int wn, int lane)
{
    const int rb = wm * 32 + (lane >> 2);
    const int m2 = (lane & 3) * 2;
#pragma unroll
    for (int t = 0; t < 2; ++t) {
        const int r1 = rb + t * 16, r2 = r1 + 8;
#pragma unroll
        for (int nt = 0; nt < 4; ++nt) {
            int cb = wn * 32 + nt * 8 + m2;
            float b0 = bias[cb], b1 = bias[cb + 1];
            float v0 = acc[t][nt][0] + b0, v1 = acc[t][nt][1] + b1;
            float v2 = acc[t][nt][2] + b0, v3 = acc[t][nt][3] + b1;
            if (relu) { v0 = fmaxf(v0, 0.f); v1 = fmaxf(v1, 0.f); v2 = fmaxf(v2, 0.f); v3 = fmaxf(v3, 0.f); }
            float h0, l0, h1, l1;
            split_h(v0, h0, l0); split_h(v1, h1, l1);
            *(uint32_t*)(SM + tH + (r1 * STRIDE + cb) * 2) = pack_h2(h0, h1);
            *(uint32_t*)(SM + tL + (r1 * STRIDE + cb) * 2) = pack_h2(l0, l1);
            split_h(v2, h0, l0); split_h(v3, h1, l1);
            *(uint32_t*)(SM + tH + (r2 * STRIDE + cb) * 2) = pack_h2(h0, h1);
            *(uint32_t*)(SM + tL + (r2 * STRIDE + cb) * 2) = pack_h2(l0, l1);
        }
    }
}
__device__ __forceinline__ void store_small(const float (&acc)[2][4], float* out,
                                            const float* bias, bool dot, int wm4, int lane)
{
    const int r1 = wm4 * 16 + (lane >> 2), r2 = r1 + 8;
    const int m2 = (lane & 3) * 2;
#pragma unroll
    for (int nt = 0; nt < 2; ++nt) {
        int c = nt * 8 + m2;
        float b0 = bias[c], b1 = bias[c + 1];
        float v0 = acc[nt][0] + b0, v1 = acc[nt][1] + b1;
        float v2 = acc[nt][2] + b0, v3 = acc[nt][3] + b1;
        if (dot) { v0 = tanhf(v0); v1 = tanhf(v1); v2 = tanhf(v2); v3 = tanhf(v3); }
        *(float2*)(out + r1 * 16 + c) = make_float2(v0, v1);
        *(float2*)(out + r2 * 16 + c) = make_float2(v2, v3);
    }
}
__device__ __forceinline__ void convert_tile(char* SM, int tH, int tL,
                                             const float* __restrict__ g, int rows, int tid)
{
#pragma unroll
    for (int i = 0; i < 8; ++i) {
        int f4 = tid + i * 256;
        int r = f4 >> 5, c4 = (f4 & 31) << 2;
        float4 v = make_float4(0.f, 0.f, 0.f, 0.f);
        if (r < rows) v = *(const float4*)(g + (size_t)r * 128 + c4);
        float h0, l0, h1, l1, h2, l2, h3, l3;
        split_h(v.x, h0, l0); split_h(v.y, h1, l1);
        split_h(v.z, h2, l2); split_h(v.w, h3, l3);
        uint2 uh, ul;
        uh.x = pack_h2(h0, h1); uh.y = pack_h2(h2, h3);
        ul.x = pack_h2(l0, l1); ul.y = pack_h2(l2, l3);
        *(uint2*)(SM + tH + (r * STRIDE + c4) * 2) = uh;
        *(uint2*)(SM + tL + (r * STRIDE + c4) * 2) = ul;
    }
}

struct Params {
    const float *src, *dst, *edge;
    const float *im2b, *mp1b, *mp2b, *qb, *kb, *vb, *ntcb, *ctob, *outb;
    float* out;
    int B;
};

__global__ __launch_bounds__(256, 1) void fused_kernel(Params p)
{
    extern __shared__ __align__(16) char SM[];
    const int tid = threadIdx.x, lane = tid & 31, wid = tid >> 5;
    const int wm = wid & 1, wn = wid >> 1;          // big-GEMM mapping
    const int wm4 = wid & 3, wn2 = wid >> 2;        // small-GEMM mapping
    const int row0 = blockIdx.x * 64;
    const int rows = min(64, p.B - row0);
    const uint32_t sbase = smem_u32(SM);
    const uint64_t gaddr = (uint64_t)__cvta_generic_to_global((void*)g_wb);
    float* BIA = (float*)(SM + BIA_B);
    float* SCO = (float*)(SM + SCO_B);
    float* GST = (float*)(SM + GST_B);

    // per-thread ldmatrix base offsets (row = lane&15, col-half = lane>>4)
    const uint32_t aoff  = sbase + (uint32_t)(((wm * 32 + (lane & 15)) * STRIDE + ((lane >> 4) & 1) * 8) * 2);
    const uint32_t aoffS = sbase + (uint32_t)(((wm4 * 16 + (lane & 15)) * STRIDE + ((lane >> 4) & 1) * 8) * 2);

#define STAGE(slot, goff, bytes) stage_fn(sbase + (slot), gaddr + (goff), (bytes), tid)

    STAGE(SMW_NTC, 266240, 8192);           // ntc + mp2 frags (contiguous)
    STAGE(RING0, 0, 32768);                 // A1

    if (tid < 128) {
        BIA[tid] = g_b1[tid];          BIA[128 + tid] = p.im2b[tid];
        BIA[256 + tid] = p.mp1b[tid];  BIA[384 + tid] = p.qb[tid];
        BIA[512 + tid] = p.kb[tid];    BIA[640 + tid] = p.vb[tid];
        BIA[768 + tid] = p.outb[tid] + p.ctob[tid];
    }
    if (tid < 16) { BIA[896 + tid] = p.mp2b[tid]; BIA[912 + tid] = p.ntcb[tid]; }
    {   // geometric-product sign table (MSB-first bit convention)
        int i = tid >> 4, j = tid & 15;
        float s = 1.f;
#pragma unroll
        for (int k = 0; k < 4; ++k)
            if ((j >> (3 - k)) & 1)
                if (__popc(i >> (4 - k)) & 1) s = -s;
        GST[tid] = s;
    }
    convert_tile(SM, TSH, TSL, p.src  + (size_t)row0 * 128, rows, tid);
    convert_tile(SM, TXH, TXL, p.edge + (size_t)row0 * 128, rows, tid);
    convert_tile(SM, TDH, TDL, p.dst  + (size_t)row0 * 128, rows, tid);
    cp_wait<1>();
    __syncthreads();                        // small weights + tiles ready

    // ---- sc (wn2=0) / dc (wn2=1): 128->16, 2-pass ----
    {
        float a2[2][4] = {};
        const uint32_t aH = aoffS + ((wn2 == 0) ? TSH : TDH);
        const uint32_t aL = aoffS + ((wn2 == 0) ? TSL : TDL);
        small_pass(a2, aH, SM + SMW_NTC, lane);
        small_pass(a2, aL, SM + SMW_NTC, lane);
        store_small(a2, (float*)(SM + ((wn2 == 0) ? SCS_B : DCS_B)), BIA + 912, false, wm4, lane);
    }

    float acc[2][4][4];
    zero24(acc);
    // ---- G1: h1 = relu(src@A1 + edge@A2 + b1) — 1-pass (damped metric chain) ----
    STAGE(RING1, 32768, 32768);  cp_wait<1>(); __syncthreads();
    gemm_1<8>(acc, aoff + TSH, SM + RING0, wn, lane);
    __syncthreads();
    STAGE(RING0, 65536, 32768);  cp_wait<1>(); __syncthreads();
    gemm_1<8>(acc, aoff + TXH, SM + RING1, wn, lane);
    __syncthreads();
    store_tile(acc, SM, TXH, TXL, BIA + 0, true, wm, wn, lane);
    __syncthreads();

    // ---- G2: h2 = relu(h1@im2) — 1-pass ----
    zero24(acc);
    STAGE(RING1, 98304, 32768);  cp_wait<1>(); __syncthreads();
    gemm_1<8>(acc, aoff + TXH, SM + RING0, wn, lane);
    __syncthreads();
    store_tile(acc, SM, TXH, TXL, BIA + 128, true, wm, wn, lane);
    __syncthreads();

    // ---- G3: h3 = relu(h2@mp1) — 1-pass ----
    zero24(acc);
    STAGE(RING0, 131072, 32768); cp_wait<1>(); __syncthreads();
    gemm_1<8>(acc, aoff + TXH, SM + RING1, wn, lane);
    __syncthreads();
    store_tile(acc, SM, TXH, TXL, BIA + 256, true, wm, wn, lane);
    __syncthreads();

    // ---- m16 = tanh(h3@mp2 + b) (wn2=0 warps), 2-pass ----
    if (wn2 == 0) {
        float a2[2][4] = {};
        small_pass(a2, aoffS + TXH, SM + SMW_MP2, lane);
        small_pass(a2, aoffS + TXL, SM + SMW_MP2, lane);
        store_small(a2, (float*)(SM + M16_B), BIA + 896, true, wm4, lane);
    }
    __syncthreads();

    // ---- clifford: metric + adapted inner product -> ip into TX cols 128..143 ----
    if (tid < 64) {
        const float* M16 = (float*)(SM + M16_B);
        const float* SCS = (float*)(SM + SCS_B);
        const float* DCS = (float*)(SM + DCS_B);
        int r = tid;
        float m[16], s[16], d[16];
#pragma unroll
        for (int k = 0; k < 16; ++k) {
            m[k] = M16[r * 16 + k];
            s[k] = SCS[r * 16 + k];
            d[k] = DCS[r * 16 + k];
        }
        float L[4][4];
#pragma unroll
        for (int a = 0; a < 4; ++a)
#pragma unroll
            for (int b = 0; b < 4; ++b) {
                float mv = m[a * 4 + b];
                L[a][b] = (a > b) ? mv : (a == b) ? (log1pf(expf(mv)) + 1e-6f) : 0.f;
            }
        float met[4][4];
#pragma unroll
        for (int a = 0; a < 4; ++a)
#pragma unroll
            for (int b = 0; b < 4; ++b) {
                float q = 0.f;
#pragma unroll
                for (int c = 0; c < 4; ++c) q = fmaf(L[a][c], L[b][c], q);
                met[a][b] = q;
            }
        const int VI[4] = {1, 2, 4, 8};
        float sv[4], dv[4];
#pragma unroll
        for (int a = 0; a < 4; ++a) {
            float qs = 0.f, qd = 0.f;
#pragma unroll
            for (int b = 0; b < 4; ++b) {
                qs = fmaf(met[a][b], s[VI[b]], qs);
                qd = fmaf(met[a][b], d[VI[b]], qd);
            }
            sv[a] = qs; dv[a] = qd;
        }
#pragma unroll
        for (int a = 0; a < 4; ++a) { s[VI[a]] = sv[a]; d[VI[a]] = dv[a]; }
#pragma unroll
        for (int k = 0; k < 16; ++k) {
            float q = 0.f;
#pragma unroll
            for (int i = 0; i < 16; ++i) {
                int j = i ^ k;
                q = fmaf(GST[i * 16 + j], fmaf(s[i], d[j], d[i] * s[j]), q);
            }
            float ip = 0.5f * q, h, l;
            split_h(ip, h, l);
            *(__half*)(SM + TXH + (r * STRIDE + 128 + k) * 2) = __float2half_rn(h);
            *(__half*)(SM + TXL + (r * STRIDE + 128 + k) * 2) = __float2half_rn(l);
        }
    }
    __syncthreads();

    // ---- Q = src@qW (kept in registers), 2-pass ----
    float accQ[2][4][4];
    zero24(accQ);
    STAGE(RING1, 163840, 32768); cp_wait<1>(); __syncthreads();
    gemm_f<8>(accQ, aoff + TSH, aoff + TSL, SM + RING0, wn, lane);
    __syncthreads();

    // ---- K = dst@kW, 2-pass ----
    float accK[2][4][4];
    zero24(accK);
    STAGE(RING0, 196608, 32768); cp_wait<1>(); __syncthreads();
    gemm_f<8>(accK, aoff + TDH, aoff + TDL, SM + RING1, wn, lane);

    // ---- scores = (Q+qb).(K+kb)/4 per head (enh cancels in softmax) ----
    {
        const int rb = wm * 32 + (lane >> 2);
        const int m = lane & 3, m2 = m * 2;
#pragma unroll
        for (int e = 0; e < 2; ++e) {
            float pr[4];
#pragma unroll
            for (int t = 0; t < 2; ++t) {
                float pa = 0.f, pb = 0.f;
#pragma unroll
                for (int u = 0; u < 2; ++u) {
                    int nt = 2 * e + u, cb = wn * 32 + nt * 8 + m2;
                    float qb0 = BIA[384 + cb], qb1 = BIA[384 + cb + 1];
                    float kb0 = BIA[512 + cb], kb1 = BIA[512 + cb + 1];
                    pa += (accQ[t][nt][0] + qb0) * (accK[t][nt][0] + kb0)
                        + (accQ[t][nt][1] + qb1) * (accK[t][nt][1] + kb1);
                    pb += (accQ[t][nt][2] + qb0) * (accK[t][nt][2] + kb0)
                        + (accQ[t][nt][3] + qb1) * (accK[t][nt][3] + kb1);
                }
                pr[t * 2] = pa; pr[t * 2 + 1] = pb;
            }
#pragma unroll
            for (int j = 0; j < 4; ++j) {
                pr[j] += __shfl_xor_sync(0xFFFFFFFFu, pr[j], 1);
                pr[j] += __shfl_xor_sync(0xFFFFFFFFu, pr[j], 2);
            }
            if (m == 0) {
                int h = wn * 2 + e;
                SCO[rb * 8 + h]        = 0.25f * pr[0];
                SCO[(rb + 8) * 8 + h]  = 0.25f * pr[1];
                SCO[(rb + 16) * 8 + h] = 0.25f * pr[2];
                SCO[(rb + 24) * 8 + h] = 0.25f * pr[3];
            }
        }
    }
    __syncthreads();
    if (tid < 64) {
        float s0[8], mx = -1e30f;
#pragma unroll
        for (int h = 0; h < 8; ++h) { s0[h] = SCO[tid * 8 + h]; mx = fmaxf(mx, s0[h]); }
        float sum = 0.f;
#pragma unroll
        for (int h = 0; h < 8; ++h) { s0[h] = expf(s0[h] - mx); sum += s0[h]; }
        float inv = 1.f / sum;
#pragma unroll
        for (int h = 0; h < 8; ++h) SCO[tid * 8 + h] = s0[h] * inv;
    }
    __syncthreads();

    // ---- V = dst@vW ; att = w8*(V+vb) -> TX, 2-pass ----
    zero24(acc);
    STAGE(RING1, 229376, 36864); cp_wait<1>(); __syncthreads();
    gemm_f<8>(acc, aoff + TDH, aoff + TDL, SM + RING0, wn, lane);
    __syncthreads();
    {
        const int rb = wm * 32 + (lane >> 2);
        const int m2 = (lane & 3) * 2;
#pragma unroll
        for (int t = 0; t < 2; ++t) {
            const int r1 = rb + t * 16, r2 = r1 + 8;
#pragma unroll
            for (int nt = 0; nt < 4; ++nt) {
                int cb = wn * 32 + nt * 8 + m2;
                int h = wn * 2 + (nt >> 1);
                float w1 = SCO[r1 * 8 + h], w2 = SCO[r2 * 8 + h];
                float b0 = BIA[640 + cb], b1 = BIA[640 + cb + 1];
                float v0 = (acc[t][nt][0] + b0) * w1, v1 = (acc[t][nt][1] + b1) * w1;
                float v2 = (acc[t][nt][2] + b0) * w2, v3 = (acc[t][nt][3] + b1) * w2;
                float h0, l0, h1, l1;
                split_h(v0, h0, l0); split_h(v1, h1, l1);
                *(uint32_t*)(SM + TXH + (r1 * STRIDE + cb) * 2) = pack_h2(h0, h1);
                *(uint32_t*)(SM + TXL + (r1 * STRIDE + cb) * 2) = pack_h2(l0, l1);
                split_h(v2, h0, l0); split_h(v3, h1, l1);
                *(uint32_t*)(SM + TXH + (r2 * STRIDE + cb) * 2) = pack_h2(h0, h1);
                *(uint32_t*)(SM + TXL + (r2 * STRIDE + cb) * 2) = pack_h2(l0, l1);
            }
        }
    }
    __syncthreads();

    // ---- out = [att|ip]@[outW;ctoW] + (outb+ctob), 9 k-tiles, 2-pass ----
    zero24(acc);
    cp_wait<0>(); __syncthreads();
    gemm_f<9>(acc, aoff + TXH, aoff + TXL, SM + RING1, wn, lane);
    {
        const int rb = wm * 32 + (lane >> 2);
        const int m2 = (lane & 3) * 2;
#pragma unroll
        for (int t = 0; t < 2; ++t) {
            const int r1 = rb + t * 16, r2 = r1 + 8;
#pragma unroll
            for (int nt = 0; nt < 4; ++nt) {
                int cb = wn * 32 + nt * 8 + m2;
                float b0 = BIA[768 + cb], b1 = BIA[768 + cb + 1];
                if (r1 < rows)
                    *(float2*)(p.out + (size_t)(row0 + r1) * 128 + cb) =
                        make_float2(acc[t][nt][0] + b0, acc[t][nt][1] + b1);
                if (r2 < rows)
                    *(float2*)(p.out + (size_t)(row0 + r2) * 128 + cb) =
                        make_float2(acc[t][nt][2] + b0, acc[t][nt][3] + b1);
            }
        }
    }
}

// ---------- launch ----------
extern "C" void kernel_launch(void* const* d_in, const int* in_sizes, int n_in,
                              void* d_out, int out_size)
{
    Params p;
    p.src = (const float*)d_in[0];
    p.dst = (const float*)d_in[1];
    p.edge = (const float*)d_in[2];
    p.im2b = (const float*)d_in[10];
    p.mp1b = (const float*)d_in[12];
    p.mp2b = (const float*)d_in[14];
    p.qb   = (const float*)d_in[16];
    p.kb   = (const float*)d_in[18];
    p.vb   = (const float*)d_in[20];
    p.ntcb = (const float*)d_in[22];
    p.ctob = (const float*)d_in[24];
    p.outb = (const float*)d_in[26];
    p.out = (float*)d_out;
    p.B = in_sizes[0] / 128;

    PrepPtrs pp;
    pp.im2W = (const float*)d_in[9];
    pp.mp1W = (const float*)d_in[11];
    pp.qW   = (const float*)d_in[15];
    pp.kW   = (const float*)d_in[17];
    pp.vW   = (const float*)d_in[19];
    pp.outW = (const float*)d_in[25];
    pp.ctoW = (const float*)d_in[23];
    pp.mp2W = (const float*)d_in[13];
    pp.ntcW = (const float*)d_in[21];

    cudaFuncSetAttribute(fused_kernel, cudaFuncAttributeMaxDynamicSharedMemorySize, SMEM_BYTES);

    prep1<<<128, 512>>>((const float*)d_in[3], (const float*)d_in[4],
                        (const float*)d_in[5], (const float*)d_in[6],
                        (const float*)d_in[7], (const float*)d_in[8]);
    prep2<<<10, 256>>>(pp);
    fused_kernel<<<(p.B + 63) / 64, 256, SMEM_BYTES>>>(p);
}

// round 15
// speedup vs baseline: 5.7932x; 1.0478x over previous
#include <cuda_runtime.h>
#include <cuda_fp16.h>
#include <math.h>
#include <stdint.h>

#define STRIDE 152                  // fp16 elems per tile row (incl. ip cols + pad)
// ---- smem byte offsets ----
#define TSH 0
#define TSL 19456
#define TDH 38912
#define TDL 58368
#define TXH 77824
#define TXL 97280
#define RING0 116736
#define RING1 153600
#define SMW_NTC 190464              // ntc frag hi (4096)
#define SMW_MP2 194560              // mp2 frag hi (4096)
#define BIA_B 207872                // 928 floats
#define SCO_B 211584                // 64x8 f32
#define GST_B 213632                // 256 f32
#define SCS_B 214656                // 64x16 f32
#define DCS_B 218752
#define M16_B 222848
#define SMEM_BYTES 226944

// ---- gmem weight buffer layout (fp16 hi-only fragments) ----
// slots 0..6 (A1,A2,im2,mp1,qW,kW,vW): b*32768
// slot 7 (outW|ctoW, 9 ktiles): 229376 (36864)
// ntc: 266240 (4096); mp2: 270336 (4096)
__device__ float g_b1[128];
__device__ __align__(128) unsigned char g_wb[274432];

// ---------- helpers ----------
__device__ __forceinline__ uint32_t smem_u32(const void* p) {
    uint32_t a;
    asm("{ .reg .u64 t; cvta.to.shared.u64 t, %1; cvt.u32.u64 %0, t; }" : "=r"(a) : "l"(p));
    return a;
}
template<int N> __device__ __forceinline__ void cp_wait() {
    asm volatile("cp.async.wait_group %0;" :: "n"(N));
}
__device__ __forceinline__ void stage_fn(uint32_t dsm, uint64_t gsrc, int bytes, int tid) {
    for (int o = tid * 16; o < bytes; o += 4096)
        asm volatile("cp.async.cg.shared.global [%0], [%1], 16;" :: "r"(dsm + o), "l"(gsrc + o) : "memory");
    asm volatile("cp.async.commit_group;" ::: "memory");
}
__device__ __forceinline__ void mma16816(float* c, uint32_t a0, uint32_t a1, uint32_t a2, uint32_t a3,
                                         uint32_t b0, uint32_t b1) {
    asm volatile("mma.sync.aligned.m16n8k16.row.col.f32.f16.f16.f32 "
                 "{%0,%1,%2,%3}, {%4,%5,%6,%7}, {%8,%9}, {%0,%1,%2,%3};"
                 : "+f"(c[0]), "+f"(c[1]), "+f"(c[2]), "+f"(c[3])
                 : "r"(a0), "r"(a1), "r"(a2), "r"(a3), "r"(b0), "r"(b1));
}
#define LDSM4(r0, r1, r2, r3, addr) \
    asm volatile("ldmatrix.sync.aligned.m8n8.x4.shared.b16 {%0,%1,%2,%3}, [%4];" \
                 : "=r"(r0), "=r"(r1), "=r"(r2), "=r"(r3) : "r"(addr))

__device__ __host__ __forceinline__ uint32_t frag_off(int k, int n, int ntiles) {
    int kt = k >> 4, kk = k & 15;
    int reg = kk >> 3, r8 = kk & 7, m = r8 >> 1, half = r8 & 1;
    int nt = n >> 3, ln = (n & 7) * 4 + m;
    return (uint32_t)((kt * ntiles + nt) * 32 + ln) * 8u + (uint32_t)reg * 4u + (uint32_t)half * 2u;
}
__device__ __forceinline__ uint32_t pack_h2(float a, float b) {
    __half2 t;
    t.x = __float2half_rn(a);
    t.y = __float2half_rn(b);
    return *(uint32_t*)&t;
}
__device__ __forceinline__ void split_h(float v, float& hi, float& lo) {
    __half h = __float2half_rn(v);
    hi = __half2float(h);
    lo = v - hi;
}

// ---------- prep kernels ----------
// prep1: fold np/ep into im1 (A1, A2) and write fp16 fragments DIRECTLY to g_wb
__global__ void prep1(const float* __restrict__ npW, const float* __restrict__ npb,
                      const float* __restrict__ epW, const float* __restrict__ epb,
                      const float* __restrict__ im1W, const float* __restrict__ im1b)
{
    __shared__ float red[1024];
    const int i = blockIdx.x;
    const int o = threadIdx.x & 127, q = threadIdx.x >> 7;   // 4-way h split
    float s1 = 0.f, s2 = 0.f;
#pragma unroll 8
    for (int h = q * 32; h < q * 32 + 32; ++h) {
        s1 = fmaf(__ldg(npW + i * 128 + h), __ldg(im1W + h * 128 + o), s1);
        s2 = fmaf(__ldg(epW + i * 128 + h), __ldg(im1W + (128 + h) * 128 + o), s2);
    }
    red[q * 128 + o] = s1;
    red[512 + q * 128 + o] = s2;
    __syncthreads();
    if (q == 0) {
        float a1 = red[o] + red[128 + o] + red[256 + o] + red[384 + o];
        float a2 = red[512 + o] + red[640 + o] + red[768 + o] + red[896 + o];
        uint32_t off = frag_off(i, o, 16);      // k = i (A is [k=128, n=128])
        *(__half*)(g_wb + off)          = __float2half_rn(a1);
        *(__half*)(g_wb + 32768 + off)  = __float2half_rn(a2);
        if (i == 0) {
            float sb = im1b[o];
#pragma unroll 8
            for (int h = 0; h < 128; ++h)
                sb += npb[h] * im1W[h * 128 + o] + epb[h] * im1W[(128 + h) * 128 + o];
            g_b1[o] = sb;
        }
    }
}

struct PrepPtrs { const float *im2W, *mp1W, *qW, *kW, *vW, *outW, *ctoW, *mp2W, *ntcW; };

__global__ void prep2(PrepPtrs pp)
{
    const int b = blockIdx.x + 2;       // 2..9 (A1/A2 handled by prep1)
    if (b < 7) {
        const float* W = nullptr;
        switch (b) { case 2: W = pp.im2W; break; case 3: W = pp.mp1W; break;
                     case 4: W = pp.qW; break; case 5: W = pp.kW; break;
                     case 6: W = pp.vW; break; default: break; }
        unsigned char* base = g_wb + b * 32768;
        for (int idx = threadIdx.x; idx < 16384; idx += blockDim.x) {
            int k = idx >> 7, n = idx & 127;
            *(__half*)(base + frag_off(k, n, 16)) = __float2half_rn(W[idx]);
        }
    } else if (b == 7) {
        unsigned char* base = g_wb + 229376;
        for (int idx = threadIdx.x; idx < 144 * 128; idx += blockDim.x) {
            int k = idx >> 7, n = idx & 127;
            float v = (k < 128) ? pp.outW[k * 128 + n] : pp.ctoW[(k - 128) * 128 + n];
            *(__half*)(base + frag_off(k, n, 16)) = __float2half_rn(v);
        }
    } else {
        const float* W = (b == 8) ? pp.ntcW : pp.mp2W;
        unsigned char* base = g_wb + ((b == 8) ? 266240 : 270336);
        for (int idx = threadIdx.x; idx < 2048; idx += blockDim.x) {
            int k = idx >> 4, n = idx & 15;
            *(__half*)(base + frag_off(k, n, 2)) = __float2half_rn(W[idx]);
        }
    }
}

// ---------- GEMM pieces (warp tile 32x32; wm in {0,1}, wn in {0..3}) ----------
// fused 2-pass: A-hi and A-lo share each B fragment; A via ldmatrix.x4
template<int NKT>
__device__ __forceinline__ void gemm_f(float (&acc)[2][4][4], uint32_t aH, uint32_t aL,
                                       const char* slot, int wn, int lane)
{
#pragma unroll
    for (int kt = 0; kt < NKT; ++kt) {
        uint32_t ah[2][4], al[2][4];
#pragma unroll
        for (int t = 0; t < 2; ++t) {
            LDSM4(ah[t][0], ah[t][1], ah[t][2], ah[t][3], aH + t * (16 * STRIDE * 2) + kt * 32);
            LDSM4(al[t][0], al[t][1], al[t][2], al[t][3], aL + t * (16 * STRIDE * 2) + kt * 32);
        }
        const char* Bp = slot + ((kt * 16 + wn * 4) * 32 + lane) * 8;
#pragma unroll
        for (int nt = 0; nt < 4; ++nt) {
            uint2 b = *(const uint2*)(Bp + nt * 256);
#pragma unroll
            for (int t = 0; t < 2; ++t) {
                mma16816(acc[t][nt], ah[t][0], ah[t][1], ah[t][2], ah[t][3], b.x, b.y);
                mma16816(acc[t][nt], al[t][0], al[t][1], al[t][2], al[t][3], b.x, b.y);
            }
        }
    }
}
// 1-pass (A-hi only) — used on damped paths (metric chain, Q, K)
template<int NKT>
__device__ __forceinline__ void gemm_1(float (&acc)[2][4][4], uint32_t aH,
                                       const char* slot, int wn, int lane)
{
#pragma unroll
    for (int kt = 0; kt < NKT; ++kt) {
        uint32_t ah[2][4];
#pragma unroll
        for (int t = 0; t < 2; ++t)
            LDSM4(ah[t][0], ah[t][1], ah[t][2], ah[t][3], aH + t * (16 * STRIDE * 2) + kt * 32);
        const char* Bp = slot + ((kt * 16 + wn * 4) * 32 + lane) * 8;
#pragma unroll
        for (int nt = 0; nt < 4; ++nt) {
            uint2 b = *(const uint2*)(Bp + nt * 256);
#pragma unroll
            for (int t = 0; t < 2; ++t)
                mma16816(acc[t][nt], ah[t][0], ah[t][1], ah[t][2], ah[t][3], b.x, b.y);
        }
    }
}
__device__ __forceinline__ void small_pass(float (&acc)[2][4], uint32_t aaddr, const char* slot,
                                           int lane)
{
#pragma unroll
    for (int kt = 0; kt < 8; ++kt) {
        uint32_t a0, a1, a2, a3;
        LDSM4(a0, a1, a2, a3, aaddr + kt * 32);
        const char* Bp = slot + (kt * 2 * 32 + lane) * 8;
#pragma unroll
        for (int nt = 0; nt < 2; ++nt) {
            uint2 b = *(const uint2*)(Bp + nt * 256);
            mma16816(acc[nt], a0, a1, a2, a3, b.x, b.y);
        }
    }
}
__device__ __forceinline__ void zero24(float (&a)[2][4][4]) {
#pragma unroll
    for (int t = 0; t < 2; ++t)
#pragma unroll
        for (int i = 0; i < 4; ++i)
#pragma unroll
            for (int j = 0; j < 4; ++j) a[t][i][j] = 0.f;
}
__device__ __forceinline__ void store_tile(const float (&acc)[2][4][4], char* SM, int tH, int tL,
                                           const float* bias, bool relu, int wm, int wn, int lane)
{
    const int rb = wm * 32 + (lane >> 2);
    const int m2 = (lane & 3) * 2;
#pragma unroll
    for (int t = 0; t < 2; ++t) {
        const int r1 = rb + t * 16, r2 = r1 + 8;
#pragma unroll
        for (int nt = 0; nt < 4; ++nt) {
            int cb = wn * 32 + nt * 8 + m2;
            float b0 = bias[cb], b1 = bias[cb + 1];
            float v0 = acc[t][nt][0] + b0, v1 = acc[t][nt][1] + b1;
            float v2 = acc[t][nt][2] + b0, v3 = acc[t][nt][3] + b1;
            if (relu) { v0 = fmaxf(v0, 0.f); v1 = fmaxf(v1, 0.f); v2 = fmaxf(v2, 0.f); v3 = fmaxf(v3, 0.f); }
            float h0, l0, h1, l1;
            split_h(v0, h0, l0); split_h(v1, h1, l1);
            *(uint32_t*)(SM + tH + (r1 * STRIDE + cb) * 2) = pack_h2(h0, h1);
            *(uint32_t*)(SM + tL + (r1 * STRIDE + cb) * 2) = pack_h2(l0, l1);
            split_h(v2, h0, l0); split_h(v3, h1, l1);
            *(uint32_t*)(SM + tH + (r2 * STRIDE + cb) * 2) = pack_h2(h0, h1);
            *(uint32_t*)(SM + tL + (r2 * STRIDE + cb) * 2) = pack_h2(l0, l1);
        }
    }
}
__device__ __forceinline__ void store_small(const float (&acc)[2][4], float* out,
                                            const float* bias, bool dot, int wm4, int lane)
{
    const int r1 = wm4 * 16 + (lane >> 2), r2 = r1 + 8;
    const int m2 = (lane & 3) * 2;
#pragma unroll
    for (int nt = 0; nt < 2; ++nt) {
        int c = nt * 8 + m2;
        float b0 = bias[c], b1 = bias[c + 1];
        float v0 = acc[nt][0] + b0, v1 = acc[nt][1] + b1;
        float v2 = acc[nt][2] + b0, v3 = acc[nt][3] + b1;
        if (dot) { v0 = tanhf(v0); v1 = tanhf(v1); v2 = tanhf(v2); v3 = tanhf(v3); }
        *(float2*)(out + r1 * 16 + c) = make_float2(v0, v1);
        *(float2*)(out + r2 * 16 + c) = make_float2(v2, v3);
    }
}
__device__ __forceinline__ void convert_tile(char* SM, int tH, int tL,
                                             const float* __restrict__ g, int rows, int tid)
{
#pragma unroll
    for (int i = 0; i < 8; ++i) {
        int f4 = tid + i * 256;
        int r = f4 >> 5, c4 = (f4 & 31) << 2;
        float4 v = make_float4(0.f, 0.f, 0.f, 0.f);
        if (r < rows) v = *(const float4*)(g + (size_t)r * 128 + c4);
        float h0, l0, h1, l1, h2, l2, h3, l3;
        split_h(v.x, h0, l0); split_h(v.y, h1, l1);
        split_h(v.z, h2, l2); split_h(v.w, h3, l3);
        uint2 uh, ul;
        uh.x = pack_h2(h0, h1); uh.y = pack_h2(h2, h3);
        ul.x = pack_h2(l0, l1); ul.y = pack_h2(l2, l3);
        *(uint2*)(SM + tH + (r * STRIDE + c4) * 2) = uh;
        *(uint2*)(SM + tL + (r * STRIDE + c4) * 2) = ul;
    }
}

struct Params {
    const float *src, *dst, *edge;
    const float *im2b, *mp1b, *mp2b, *qb, *kb, *vb, *ntcb, *ctob, *outb;
    float* out;
    int B;
};

__global__ __launch_bounds__(256, 1) void fused_kernel(Params p)
{
    extern __shared__ __align__(16) char SM[];
    const int tid = threadIdx.x, lane = tid & 31, wid = tid >> 5;
    const int wm = wid & 1, wn = wid >> 1;          // big-GEMM mapping
    const int wm4 = wid & 3, wn2 = wid >> 2;        // small-GEMM mapping
    const int row0 = blockIdx.x * 64;
    const int rows = min(64, p.B - row0);
    const uint32_t sbase = smem_u32(SM);
    const uint64_t gaddr = (uint64_t)__cvta_generic_to_global((void*)g_wb);
    float* BIA = (float*)(SM + BIA_B);
    float* SCO = (float*)(SM + SCO_B);
    float* GST = (float*)(SM + GST_B);

    // per-thread ldmatrix base offsets (row = lane&15, col-half = lane>>4)
    const uint32_t aoff  = sbase + (uint32_t)(((wm * 32 + (lane & 15)) * STRIDE + ((lane >> 4) & 1) * 8) * 2);
    const uint32_t aoffS = sbase + (uint32_t)(((wm4 * 16 + (lane & 15)) * STRIDE + ((lane >> 4) & 1) * 8) * 2);

#define STAGE(slot, goff, bytes) stage_fn(sbase + (slot), gaddr + (goff), (bytes), tid)

    STAGE(SMW_NTC, 266240, 8192);           // ntc + mp2 frags (contiguous)
    STAGE(RING0, 0, 32768);                 // A1

    if (tid < 128) {
        BIA[tid] = g_b1[tid];          BIA[128 + tid] = p.im2b[tid];
        BIA[256 + tid] = p.mp1b[tid];  BIA[384 + tid] = p.qb[tid];
        BIA[512 + tid] = p.kb[tid];    BIA[640 + tid] = p.vb[tid];
        BIA[768 + tid] = p.outb[tid] + p.ctob[tid];
    }
    if (tid < 16) { BIA[896 + tid] = p.mp2b[tid]; BIA[912 + tid] = p.ntcb[tid]; }
    {   // geometric-product sign table (MSB-first bit convention)
        int i = tid >> 4, j = tid & 15;
        float s = 1.f;
#pragma unroll
        for (int k = 0; k < 4; ++k)
            if ((j >> (3 - k)) & 1)
                if (__popc(i >> (4 - k)) & 1) s = -s;
        GST[tid] = s;
    }
    convert_tile(SM, TSH, TSL, p.src  + (size_t)row0 * 128, rows, tid);
    convert_tile(SM, TXH, TXL, p.edge + (size_t)row0 * 128, rows, tid);
    convert_tile(SM, TDH, TDL, p.dst  + (size_t)row0 * 128, rows, tid);
    cp_wait<1>();
    __syncthreads();                        // small weights + tiles ready

    // ---- sc (wn2=0) / dc (wn2=1): 128->16, 2-pass ----
    {
        float a2[2][4] = {};
        const uint32_t aH = aoffS + ((wn2 == 0) ? TSH : TDH);
        const uint32_t aL = aoffS + ((wn2 == 0) ? TSL : TDL);
        small_pass(a2, aH, SM + SMW_NTC, lane);
        small_pass(a2, aL, SM + SMW_NTC, lane);
        store_small(a2, (float*)(SM + ((wn2 == 0) ? SCS_B : DCS_B)), BIA + 912, false, wm4, lane);
    }

    float acc[2][4][4];
    zero24(acc);
    // ---- G1: h1 = relu(src@A1 + edge@A2 + b1) — 1-pass (damped metric chain) ----
    STAGE(RING1, 32768, 32768);  cp_wait<1>(); __syncthreads();
    gemm_1<8>(acc, aoff + TSH, SM + RING0, wn, lane);
    __syncthreads();
    STAGE(RING0, 65536, 32768);  cp_wait<1>(); __syncthreads();
    gemm_1<8>(acc, aoff + TXH, SM + RING1, wn, lane);
    __syncthreads();
    store_tile(acc, SM, TXH, TXL, BIA + 0, true, wm, wn, lane);
    __syncthreads();

    // ---- G2: h2 = relu(h1@im2) — 1-pass ----
    zero24(acc);
    STAGE(RING1, 98304, 32768);  cp_wait<1>(); __syncthreads();
    gemm_1<8>(acc, aoff + TXH, SM + RING0, wn, lane);
    __syncthreads();
    store_tile(acc, SM, TXH, TXL, BIA + 128, true, wm, wn, lane);
    __syncthreads();

    // ---- G3: h3 = relu(h2@mp1) — 1-pass ----
    zero24(acc);
    STAGE(RING0, 131072, 32768); cp_wait<1>(); __syncthreads();
    gemm_1<8>(acc, aoff + TXH, SM + RING1, wn, lane);
    __syncthreads();
    store_tile(acc, SM, TXH, TXL, BIA + 256, true, wm, wn, lane);
    __syncthreads();

    // ---- m16 = tanh(h3@mp2 + b) (wn2=0 warps), 2-pass ----
    if (wn2 == 0) {
        float a2[2][4] = {};
        small_pass(a2, aoffS + TXH, SM + SMW_MP2, lane);
        small_pass(a2, aoffS + TXL, SM + SMW_MP2, lane);
        store_small(a2, (float*)(SM + M16_B), BIA + 896, true, wm4, lane);
    }
    __syncthreads();

    // ---- clifford: metric + adapted inner product -> ip into TX cols 128..143 ----
    if (tid < 64) {
        const float* M16 = (float*)(SM + M16_B);
        const float* SCS = (float*)(SM + SCS_B);
        const float* DCS = (float*)(SM + DCS_B);
        int r = tid;
        float m[16], s[16], d[16];
#pragma unroll
        for (int k = 0; k < 16; ++k) {
            m[k] = M16[r * 16 + k];
            s[k] = SCS[r * 16 + k];
            d[k] = DCS[r * 16 + k];
        }
        float L[4][4];
#pragma unroll
        for (int a = 0; a < 4; ++a)
#pragma unroll
            for (int b = 0; b < 4; ++b) {
                float mv = m[a * 4 + b];
                L[a][b] = (a > b) ? mv : (a == b) ? (log1pf(expf(mv)) + 1e-6f) : 0.f;
            }
        float met[4][4];
#pragma unroll
        for (int a = 0; a < 4; ++a)
#pragma unroll
            for (int b = 0; b < 4; ++b) {
                float q = 0.f;
#pragma unroll
                for (int c = 0; c < 4; ++c) q = fmaf(L[a][c], L[b][c], q);
                met[a][b] = q;
            }
        const int VI[4] = {1, 2, 4, 8};
        float sv[4], dv[4];
#pragma unroll
        for (int a = 0; a < 4; ++a) {
            float qs = 0.f, qd = 0.f;
#pragma unroll
            for (int b = 0; b < 4; ++b) {
                qs = fmaf(met[a][b], s[VI[b]], qs);
                qd = fmaf(met[a][b], d[VI[b]], qd);
            }
            sv[a] = qs; dv[a] = qd;
        }
#pragma unroll
        for (int a = 0; a < 4; ++a) { s[VI[a]] = sv[a]; d[VI[a]] = dv[a]; }
#pragma unroll
        for (int k = 0; k < 16; ++k) {
            float q = 0.f;
#pragma unroll
            for (int i = 0; i < 16; ++i) {
                int j = i ^ k;
                q = fmaf(GST[i * 16 + j], fmaf(s[i], d[j], d[i] * s[j]), q);
            }
            float ip = 0.5f * q, h, l;
            split_h(ip, h, l);
            *(__half*)(SM + TXH + (r * STRIDE + 128 + k) * 2) = __float2half_rn(h);
            *(__half*)(SM + TXL + (r * STRIDE + 128 + k) * 2) = __float2half_rn(l);
        }
    }
    __syncthreads();

    // ---- Q = src@qW (kept in registers), 1-pass (softmax-damped) ----
    float accQ[2][4][4];
    zero24(accQ);
    STAGE(RING1, 163840, 32768); cp_wait<1>(); __syncthreads();
    gemm_1<8>(accQ, aoff + TSH, SM + RING0, wn, lane);
    __syncthreads();

    // ---- K = dst@kW, 1-pass (softmax-damped) ----
    float accK[2][4][4];
    zero24(accK);
    STAGE(RING0, 196608, 32768); cp_wait<1>(); __syncthreads();
    gemm_1<8>(accK, aoff + TDH, SM + RING1, wn, lane);

    // ---- scores = (Q+qb).(K+kb)/4 per head (enh cancels in softmax) ----
    {
        const int rb = wm * 32 + (lane >> 2);
        const int m = lane & 3, m2 = m * 2;
#pragma unroll
        for (int e = 0; e < 2; ++e) {
            float pr[4];
#pragma unroll
            for (int t = 0; t < 2; ++t) {
                float pa = 0.f, pb = 0.f;
#pragma unroll
                for (int u = 0; u < 2; ++u) {
                    int nt = 2 * e + u, cb = wn * 32 + nt * 8 + m2;
                    float qb0 = BIA[384 + cb], qb1 = BIA[384 + cb + 1];
                    float kb0 = BIA[512 + cb], kb1 = BIA[512 + cb + 1];
                    pa += (accQ[t][nt][0] + qb0) * (accK[t][nt][0] + kb0)
                        + (accQ[t][nt][1] + qb1) * (accK[t][nt][1] + kb1);
                    pb += (accQ[t][nt][2] + qb0) * (accK[t][nt][2] + kb0)
                        + (accQ[t][nt][3] + qb1) * (accK[t][nt][3] + kb1);
                }
                pr[t * 2] = pa; pr[t * 2 + 1] = pb;
            }
#pragma unroll
            for (int j = 0; j < 4; ++j) {
                pr[j] += __shfl_xor_sync(0xFFFFFFFFu, pr[j], 1);
                pr[j] += __shfl_xor_sync(0xFFFFFFFFu, pr[j], 2);
            }
            if (m == 0) {
                int h = wn * 2 + e;
                SCO[rb * 8 + h]        = 0.25f * pr[0];
                SCO[(rb + 8) * 8 + h]  = 0.25f * pr[1];
                SCO[(rb + 16) * 8 + h] = 0.25f * pr[2];
                SCO[(rb + 24) * 8 + h] = 0.25f * pr[3];
            }
        }
    }
    __syncthreads();
    if (tid < 64) {
        float s0[8], mx = -1e30f;
#pragma unroll
        for (int h = 0; h < 8; ++h) { s0[h] = SCO[tid * 8 + h]; mx = fmaxf(mx, s0[h]); }
        float sum = 0.f;
#pragma unroll
        for (int h = 0; h < 8; ++h) { s0[h] = expf(s0[h] - mx); sum += s0[h]; }
        float inv = 1.f / sum;
#pragma unroll
        for (int h = 0; h < 8; ++h) SCO[tid * 8 + h] = s0[h] * inv;
    }
    __syncthreads();

    // ---- V = dst@vW ; att = w8*(V+vb) -> TX, 2-pass (direct path) ----
    zero24(acc);
    STAGE(RING1, 229376, 36864); cp_wait<1>(); __syncthreads();
    gemm_f<8>(acc, aoff + TDH, aoff + TDL, SM + RING0, wn, lane);
    __syncthreads();
    {
        const int rb = wm * 32 + (lane >> 2);
        const int m2 = (lane & 3) * 2;
#pragma unroll
        for (int t = 0; t < 2; ++t) {
            const int r1 = rb + t * 16, r2 = r1 + 8;
#pragma unroll
            for (int nt = 0; nt < 4; ++nt) {
                int cb = wn * 32 + nt * 8 + m2;
                int h = wn * 2 + (nt >> 1);
                float w1 = SCO[r1 * 8 + h], w2 = SCO[r2 * 8 + h];
                float b0 = BIA[640 + cb], b1 = BIA[640 + cb + 1];
                float v0 = (acc[t][nt][0] + b0) * w1, v1 = (acc[t][nt][1] + b1) * w1;
                float v2 = (acc[t][nt][2] + b0) * w2, v3 = (acc[t][nt][3] + b1) * w2;
                float h0, l0, h1, l1;
                split_h(v0, h0, l0); split_h(v1, h1, l1);
                *(uint32_t*)(SM + TXH + (r1 * STRIDE + cb) * 2) = pack_h2(h0, h1);
                *(uint32_t*)(SM + TXL + (r1 * STRIDE + cb) * 2) = pack_h2(l0, l1);
                split_h(v2, h0, l0); split_h(v3, h1, l1);
                *(uint32_t*)(SM + TXH + (r2 * STRIDE + cb) * 2) = pack_h2(h0, h1);
                *(uint32_t*)(SM + TXL + (r2 * STRIDE + cb) * 2) = pack_h2(l0, l1);
            }
        }
    }
    __syncthreads();

    // ---- out = [att|ip]@[outW;ctoW] + (outb+ctob), 9 k-tiles, 2-pass ----
    zero24(acc);
    cp_wait<0>(); __syncthreads();
    gemm_f<9>(acc, aoff + TXH, aoff + TXL, SM + RING1, wn, lane);
    {
        const int rb = wm * 32 + (lane >> 2);
        const int m2 = (lane & 3) * 2;
#pragma unroll
        for (int t = 0; t < 2; ++t) {
            const int r1 = rb + t * 16, r2 = r1 + 8;
#pragma unroll
            for (int nt = 0; nt < 4; ++nt) {
                int cb = wn * 32 + nt * 8 + m2;
                float b0 = BIA[768 + cb], b1 = BIA[768 + cb + 1];
                if (r1 < rows)
                    *(float2*)(p.out + (size_t)(row0 + r1) * 128 + cb) =
                        make_float2(acc[t][nt][0] + b0, acc[t][nt][1] + b1);
                if (r2 < rows)
                    *(float2*)(p.out + (size_t)(row0 + r2) * 128 + cb) =
                        make_float2(acc[t][nt][2] + b0, acc[t][nt][3] + b1);
            }
        }
    }
}

// ---------- launch ----------
extern "C" void kernel_launch(void* const* d_in, const int* in_sizes, int n_in,
                              void* d_out, int out_size)
{
    Params p;
    p.src = (const float*)d_in[0];
    p.dst = (const float*)d_in[1];
    p.edge = (const float*)d_in[2];
    p.im2b = (const float*)d_in[10];
    p.mp1b = (const float*)d_in[12];
    p.mp2b = (const float*)d_in[14];
    p.qb   = (const float*)d_in[16];
    p.kb   = (const float*)d_in[18];
    p.vb   = (const float*)d_in[20];
    p.ntcb = (const float*)d_in[22];
    p.ctob = (const float*)d_in[24];
    p.outb = (const float*)d_in[26];
    p.out = (float*)d_out;
    p.B = in_sizes[0] / 128;

    PrepPtrs pp;
    pp.im2W = (const float*)d_in[9];
    pp.mp1W = (const float*)d_in[11];
    pp.qW   = (const float*)d_in[15];
    pp.kW   = (const float*)d_in[17];
    pp.vW   = (const float*)d_in[19];
    pp.outW = (const float*)d_in[25];
    pp.ctoW = (const float*)d_in[23];
    pp.mp2W = (const float*)d_in[13];
    pp.ntcW = (const float*)d_in[21];

    cudaFuncSetAttribute(fused_kernel, cudaFuncAttributeMaxDynamicSharedMemorySize, SMEM_BYTES);

    prep1<<<128, 512>>>((const float*)d_in[3], (const float*)d_in[4],
                        (const float*)d_in[5], (const float*)d_in[6],
                        (const float*)d_in[7], (const float*)d_in[8]);
    prep2<<<8, 256>>>(pp);
    fused_kernel<<<(p.B + 63) / 64, 256, SMEM_BYTES>>>(p);
}

// round 16
// speedup vs baseline: 6.2534x; 1.0794x over previous
#include <cuda_runtime.h>
#include <cuda_fp16.h>
#include <math.h>
#include <stdint.h>

#define STRIDE 152                  // fp16 elems per tile row (incl. ip cols + pad)
// ---- smem byte offsets ----
#define TSH 0
#define TSL 19456
#define TDH 38912
#define TDL 58368
#define TXH 77824
#define TXL 97280
#define RING0 116736
#define RING1 153600
#define SMW_NTC 190464              // ntc frag hi (4096)
#define SMW_MP2 194560              // mp2 frag hi (4096)
#define BIA_B 207872                // 928 floats
#define SCO_B 211584                // 64x8 f32
#define GST_B 213632                // 256 f32
#define SCS_B 214656                // 64x16 f32
#define DCS_B 218752
#define M16_B 222848
#define SMEM_BYTES 226944

// ---- gmem weight buffer layout (fp16 hi-only fragments) ----
// slots 0..6 (A1,A2,im2,mp1,qW,kW,vW): b*32768
// slot 7 (outW|ctoW, 9 ktiles): 229376 (36864)
// ntc: 266240 (4096); mp2: 270336 (4096)
__device__ float g_b1[128];
__device__ __align__(128) unsigned char g_wb[274432];

// ---------- helpers ----------
__device__ __forceinline__ uint32_t smem_u32(const void* p) {
    uint32_t a;
    asm("{ .reg .u64 t; cvta.to.shared.u64 t, %1; cvt.u32.u64 %0, t; }" : "=r"(a) : "l"(p));
    return a;
}
template<int N> __device__ __forceinline__ void cp_wait() {
    asm volatile("cp.async.wait_group %0;" :: "n"(N));
}
__device__ __forceinline__ void stage_fn(uint32_t dsm, uint64_t gsrc, int bytes, int tid) {
    for (int o = tid * 16; o < bytes; o += 4096)
        asm volatile("cp.async.cg.shared.global [%0], [%1], 16;" :: "r"(dsm + o), "l"(gsrc + o) : "memory");
    asm volatile("cp.async.commit_group;" ::: "memory");
}
__device__ __forceinline__ void mma16816(float* c, uint32_t a0, uint32_t a1, uint32_t a2, uint32_t a3,
                                         uint32_t b0, uint32_t b1) {
    asm volatile("mma.sync.aligned.m16n8k16.row.col.f32.f16.f16.f32 "
                 "{%0,%1,%2,%3}, {%4,%5,%6,%7}, {%8,%9}, {%0,%1,%2,%3};"
                 : "+f"(c[0]), "+f"(c[1]), "+f"(c[2]), "+f"(c[3])
                 : "r"(a0), "r"(a1), "r"(a2), "r"(a3), "r"(b0), "r"(b1));
}
#define LDSM4(r0, r1, r2, r3, addr) \
    asm volatile("ldmatrix.sync.aligned.m8n8.x4.shared.b16 {%0,%1,%2,%3}, [%4];" \
                 : "=r"(r0), "=r"(r1), "=r"(r2), "=r"(r3) : "r"(addr))

__device__ __host__ __forceinline__ uint32_t frag_off(int k, int n, int ntiles) {
    int kt = k >> 4, kk = k & 15;
    int reg = kk >> 3, r8 = kk & 7, m = r8 >> 1, half = r8 & 1;
    int nt = n >> 3, ln = (n & 7) * 4 + m;
    return (uint32_t)((kt * ntiles + nt) * 32 + ln) * 8u + (uint32_t)reg * 4u + (uint32_t)half * 2u;
}
__device__ __forceinline__ uint32_t pack_h2(float a, float b) {
    __half2 t;
    t.x = __float2half_rn(a);
    t.y = __float2half_rn(b);
    return *(uint32_t*)&t;
}
__device__ __forceinline__ void split_h(float v, float& hi, float& lo) {
    __half h = __float2half_rn(v);
    hi = __half2float(h);
    lo = v - hi;
}

// ---------- merged prep kernel ----------
// blocks 0..127: fold np/ep into im1 (A1, A2), write fp16 frags directly.
// blocks 128..135: convert remaining weights (b = 2..9). Independent of blocks 0..127.
struct PrepAll {
    const float *npW, *npb, *epW, *epb, *im1W, *im1b;
    const float *im2W, *mp1W, *qW, *kW, *vW, *outW, *ctoW, *mp2W, *ntcW;
};

__global__ void prep_all(PrepAll pp)
{
    __shared__ float red[1024];
    if (blockIdx.x < 128) {
        const int i = blockIdx.x;
        const int o = threadIdx.x & 127, q = threadIdx.x >> 7;   // 4-way h split
        float s1 = 0.f, s2 = 0.f;
#pragma unroll 8
        for (int h = q * 32; h < q * 32 + 32; ++h) {
            s1 = fmaf(__ldg(pp.npW + i * 128 + h), __ldg(pp.im1W + h * 128 + o), s1);
            s2 = fmaf(__ldg(pp.epW + i * 128 + h), __ldg(pp.im1W + (128 + h) * 128 + o), s2);
        }
        red[q * 128 + o] = s1;
        red[512 + q * 128 + o] = s2;
        __syncthreads();
        if (q == 0) {
            float a1 = red[o] + red[128 + o] + red[256 + o] + red[384 + o];
            float a2 = red[512 + o] + red[640 + o] + red[768 + o] + red[896 + o];
            uint32_t off = frag_off(i, o, 16);      // k = i
            *(__half*)(g_wb + off)          = __float2half_rn(a1);
            *(__half*)(g_wb + 32768 + off)  = __float2half_rn(a2);
            if (i == 0) {
                float sb = pp.im1b[o];
#pragma unroll 8
                for (int h = 0; h < 128; ++h)
                    sb += pp.npb[h] * pp.im1W[h * 128 + o] + pp.epb[h] * pp.im1W[(128 + h) * 128 + o];
                g_b1[o] = sb;
            }
        }
        return;
    }
    const int b = blockIdx.x - 126;       // 2..9
    if (b < 7) {
        const float* W = nullptr;
        switch (b) { case 2: W = pp.im2W; break; case 3: W = pp.mp1W; break;
                     case 4: W = pp.qW; break; case 5: W = pp.kW; break;
                     case 6: W = pp.vW; break; default: break; }
        unsigned char* base = g_wb + b * 32768;
        for (int idx = threadIdx.x; idx < 16384; idx += blockDim.x) {
            int k = idx >> 7, n = idx & 127;
            *(__half*)(base + frag_off(k, n, 16)) = __float2half_rn(W[idx]);
        }
    } else if (b == 7) {
        unsigned char* base = g_wb + 229376;
        for (int idx = threadIdx.x; idx < 144 * 128; idx += blockDim.x) {
            int k = idx >> 7, n = idx & 127;
            float v = (k < 128) ? pp.outW[k * 128 + n] : pp.ctoW[(k - 128) * 128 + n];
            *(__half*)(base + frag_off(k, n, 16)) = __float2half_rn(v);
        }
    } else {
        const float* W = (b == 8) ? pp.ntcW : pp.mp2W;
        unsigned char* base = g_wb + ((b == 8) ? 266240 : 270336);
        for (int idx = threadIdx.x; idx < 2048; idx += blockDim.x) {
            int k = idx >> 4, n = idx & 15;
            *(__half*)(base + frag_off(k, n, 2)) = __float2half_rn(W[idx]);
        }
    }
}

// ---------- GEMM pieces (warp tile 32x32; wm in {0,1}, wn in {0..3}) ----------
// fused 2-pass: A-hi and A-lo share each B fragment; A via ldmatrix.x4
template<int NKT>
__device__ __forceinline__ void gemm_f(float (&acc)[2][4][4], uint32_t aH, uint32_t aL,
                                       const char* slot, int wn, int lane)
{
#pragma unroll
    for (int kt = 0; kt < NKT; ++kt) {
        uint32_t ah[2][4], al[2][4];
#pragma unroll
        for (int t = 0; t < 2; ++t) {
            LDSM4(ah[t][0], ah[t][1], ah[t][2], ah[t][3], aH + t * (16 * STRIDE * 2) + kt * 32);
            LDSM4(al[t][0], al[t][1], al[t][2], al[t][3], aL + t * (16 * STRIDE * 2) + kt * 32);
        }
        const char* Bp = slot + ((kt * 16 + wn * 4) * 32 + lane) * 8;
#pragma unroll
        for (int nt = 0; nt < 4; ++nt) {
            uint2 b = *(const uint2*)(Bp + nt * 256);
#pragma unroll
            for (int t = 0; t < 2; ++t) {
                mma16816(acc[t][nt], ah[t][0], ah[t][1], ah[t][2], ah[t][3], b.x, b.y);
                mma16816(acc[t][nt], al[t][0], al[t][1], al[t][2], al[t][3], b.x, b.y);
            }
        }
    }
}
// 1-pass (A-hi only) — damped paths (metric chain, Q, K)
template<int NKT>
__device__ __forceinline__ void gemm_1(float (&acc)[2][4][4], uint32_t aH,
                                       const char* slot, int wn, int lane)
{
#pragma unroll
    for (int kt = 0; kt < NKT; ++kt) {
        uint32_t ah[2][4];
#pragma unroll
        for (int t = 0; t < 2; ++t)
            LDSM4(ah[t][0], ah[t][1], ah[t][2], ah[t][3], aH + t * (16 * STRIDE * 2) + kt * 32);
        const char* Bp = slot + ((kt * 16 + wn * 4) * 32 + lane) * 8;
#pragma unroll
        for (int nt = 0; nt < 4; ++nt) {
            uint2 b = *(const uint2*)(Bp + nt * 256);
#pragma unroll
            for (int t = 0; t < 2; ++t)
                mma16816(acc[t][nt], ah[t][0], ah[t][1], ah[t][2], ah[t][3], b.x, b.y);
        }
    }
}
__device__ __forceinline__ void small_pass(float (&acc)[2][4], uint32_t aaddr, const char* slot,
                                           int lane)
{
#pragma unroll
    for (int kt = 0; kt < 8; ++kt) {
        uint32_t a0, a1, a2, a3;
        LDSM4(a0, a1, a2, a3, aaddr + kt * 32);
        const char* Bp = slot + (kt * 2 * 32 + lane) * 8;
#pragma unroll
        for (int nt = 0; nt < 2; ++nt) {
            uint2 b = *(const uint2*)(Bp + nt * 256);
            mma16816(acc[nt], a0, a1, a2, a3, b.x, b.y);
        }
    }
}
__device__ __forceinline__ void zero24(float (&a)[2][4][4]) {
#pragma unroll
    for (int t = 0; t < 2; ++t)
#pragma unroll
        for (int i = 0; i < 4; ++i)
#pragma unroll
            for (int j = 0; j < 4; ++j) a[t][i][j] = 0.f;
}
// hi-only activation store (consumers are 1-pass)
__device__ __forceinline__ void store_tile_h(const float (&acc)[2][4][4], char* SM, int tH,
                                             const float* bias, int wm, int wn, int lane)
{
    const int rb = wm * 32 + (lane >> 2);
    const int m2 = (lane & 3) * 2;
#pragma unroll
    for (int t = 0; t < 2; ++t) {
        const int r1 = rb + t * 16, r2 = r1 + 8;
#pragma unroll
        for (int nt = 0; nt < 4; ++nt) {
            int cb = wn * 32 + nt * 8 + m2;
            float b0 = bias[cb], b1 = bias[cb + 1];
            float v0 = fmaxf(acc[t][nt][0] + b0, 0.f), v1 = fmaxf(acc[t][nt][1] + b1, 0.f);
            float v2 = fmaxf(acc[t][nt][2] + b0, 0.f), v3 = fmaxf(acc[t][nt][3] + b1, 0.f);
            *(uint32_t*)(SM + tH + (r1 * STRIDE + cb) * 2) = pack_h2(v0, v1);
            *(uint32_t*)(SM + tH + (r2 * STRIDE + cb) * 2) = pack_h2(v2, v3);
        }
    }
}
__device__ __forceinline__ void store_small(const float (&acc)[2][4], float* out,
                                            const float* bias, bool dot, int wm4, int lane)
{
    const int r1 = wm4 * 16 + (lane >> 2), r2 = r1 + 8;
    const int m2 = (lane & 3) * 2;
#pragma unroll
    for (int nt = 0; nt < 2; ++nt) {
        int c = nt * 8 + m2;
        float b0 = bias[c], b1 = bias[c + 1];
        float v0 = acc[nt][0] + b0, v1 = acc[nt][1] + b1;
        float v2 = acc[nt][2] + b0, v3 = acc[nt][3] + b1;
        if (dot) { v0 = tanhf(v0); v1 = tanhf(v1); v2 = tanhf(v2); v3 = tanhf(v3); }
        *(float2*)(out + r1 * 16 + c) = make_float2(v0, v1);
        *(float2*)(out + r2 * 16 + c) = make_float2(v2, v3);
    }
}
__device__ __forceinline__ void convert_tile(char* SM, int tH, int tL,
                                             const float* __restrict__ g, int rows, int tid)
{
#pragma unroll
    for (int i = 0; i < 8; ++i) {
        int f4 = tid + i * 256;
        int r = f4 >> 5, c4 = (f4 & 31) << 2;
        float4 v = make_float4(0.f, 0.f, 0.f, 0.f);
        if (r < rows) v = *(const float4*)(g + (size_t)r * 128 + c4);
        float h0, l0, h1, l1, h2, l2, h3, l3;
        split_h(v.x, h0, l0); split_h(v.y, h1, l1);
        split_h(v.z, h2, l2); split_h(v.w, h3, l3);
        uint2 uh, ul;
        uh.x = pack_h2(h0, h1); uh.y = pack_h2(h2, h3);
        ul.x = pack_h2(l0, l1); ul.y = pack_h2(l2, l3);
        *(uint2*)(SM + tH + (r * STRIDE + c4) * 2) = uh;
        *(uint2*)(SM + tL + (r * STRIDE + c4) * 2) = ul;
    }
}
// hi-only convert (edge: only 1-pass consumer)
__device__ __forceinline__ void convert_tile_h(char* SM, int tH,
                                               const float* __restrict__ g, int rows, int tid)
{
#pragma unroll
    for (int i = 0; i < 8; ++i) {
        int f4 = tid + i * 256;
        int r = f4 >> 5, c4 = (f4 & 31) << 2;
        float4 v = make_float4(0.f, 0.f, 0.f, 0.f);
        if (r < rows) v = *(const float4*)(g + (size_t)r * 128 + c4);
        uint2 uh;
        uh.x = pack_h2(v.x, v.y); uh.y = pack_h2(v.z, v.w);
        *(uint2*)(SM + tH + (r * STRIDE + c4) * 2) = uh;
    }
}

struct Params {
    const float *src, *dst, *edge;
    const float *im2b, *mp1b, *mp2b, *qb, *kb, *vb, *ntcb, *ctob, *outb;
    float* out;
    int B;
};

__global__ __launch_bounds__(256, 1) void fused_kernel(Params p)
{
    extern __shared__ __align__(16) char SM[];
    const int tid = threadIdx.x, lane = tid & 31, wid = tid >> 5;
    const int wm = wid & 1, wn = wid >> 1;          // big-GEMM mapping
    const int wm4 = wid & 3, wn2 = wid >> 2;        // small-GEMM mapping
    const int row0 = blockIdx.x * 64;
    const int rows = min(64, p.B - row0);
    const uint32_t sbase = smem_u32(SM);
    const uint64_t gaddr = (uint64_t)__cvta_generic_to_global((void*)g_wb);
    float* BIA = (float*)(SM + BIA_B);
    float* SCO = (float*)(SM + SCO_B);
    float* GST = (float*)(SM + GST_B);

    // per-thread ldmatrix base offsets (row = lane&15, col-half = lane>>4)
    const uint32_t aoff  = sbase + (uint32_t)(((wm * 32 + (lane & 15)) * STRIDE + ((lane >> 4) & 1) * 8) * 2);
    const uint32_t aoffS = sbase + (uint32_t)(((wm4 * 16 + (lane & 15)) * STRIDE + ((lane >> 4) & 1) * 8) * 2);

#define STAGE(slot, goff, bytes) stage_fn(sbase + (slot), gaddr + (goff), (bytes), tid)

    STAGE(SMW_NTC, 266240, 8192);           // ntc + mp2 frags (contiguous)
    STAGE(RING0, 0, 32768);                 // A1

    if (tid < 128) {
        BIA[tid] = g_b1[tid];          BIA[128 + tid] = p.im2b[tid];
        BIA[256 + tid] = p.mp1b[tid];  BIA[384 + tid] = p.qb[tid];
        BIA[512 + tid] = p.kb[tid];    BIA[640 + tid] = p.vb[tid];
        BIA[768 + tid] = p.outb[tid] + p.ctob[tid];
    }
    if (tid < 16) { BIA[896 + tid] = p.mp2b[tid]; BIA[912 + tid] = p.ntcb[tid]; }
    {   // geometric-product sign table (MSB-first bit convention)
        int i = tid >> 4, j = tid & 15;
        float s = 1.f;
#pragma unroll
        for (int k = 0; k < 4; ++k)
            if ((j >> (3 - k)) & 1)
                if (__popc(i >> (4 - k)) & 1) s = -s;
        GST[tid] = s;
    }
    convert_tile(SM, TSH, TSL, p.src + (size_t)row0 * 128, rows, tid);
    convert_tile_h(SM, TXH, p.edge + (size_t)row0 * 128, rows, tid);
    convert_tile(SM, TDH, TDL, p.dst + (size_t)row0 * 128, rows, tid);
    cp_wait<1>();
    __syncthreads();                        // small weights + tiles ready

    // ---- sc (wn2=0) / dc (wn2=1): 128->16, 2-pass ----
    {
        float a2[2][4] = {};
        const uint32_t aH = aoffS + ((wn2 == 0) ? TSH : TDH);
        const uint32_t aL = aoffS + ((wn2 == 0) ? TSL : TDL);
        small_pass(a2, aH, SM + SMW_NTC, lane);
        small_pass(a2, aL, SM + SMW_NTC, lane);
        store_small(a2, (float*)(SM + ((wn2 == 0) ? SCS_B : DCS_B)), BIA + 912, false, wm4, lane);
    }

    float acc[2][4][4];
    zero24(acc);
    // ---- G1: h1 = relu(src@A1 + edge@A2 + b1) — 1-pass (damped metric chain) ----
    STAGE(RING1, 32768, 32768);  cp_wait<1>(); __syncthreads();
    gemm_1<8>(acc, aoff + TSH, SM + RING0, wn, lane);
    __syncthreads();
    STAGE(RING0, 65536, 32768);  cp_wait<1>(); __syncthreads();
    gemm_1<8>(acc, aoff + TXH, SM + RING1, wn, lane);
    __syncthreads();
    store_tile_h(acc, SM, TXH, BIA + 0, wm, wn, lane);
    __syncthreads();

    // ---- G2: h2 = relu(h1@im2) — 1-pass ----
    zero24(acc);
    STAGE(RING1, 98304, 32768);  cp_wait<1>(); __syncthreads();
    gemm_1<8>(acc, aoff + TXH, SM + RING0, wn, lane);
    __syncthreads();
    store_tile_h(acc, SM, TXH, BIA + 128, wm, wn, lane);
    __syncthreads();

    // ---- G3: h3 = relu(h2@mp1) — 1-pass ----
    zero24(acc);
    STAGE(RING0, 131072, 32768); cp_wait<1>(); __syncthreads();
    gemm_1<8>(acc, aoff + TXH, SM + RING1, wn, lane);
    __syncthreads();
    store_tile_h(acc, SM, TXH, BIA + 256, wm, wn, lane);
    __syncthreads();

    // ---- m16 = tanh(h3@mp2 + b) (wn2=0 warps), 1-pass (deep in damped chain) ----
    if (wn2 == 0) {
        float a2[2][4] = {};
        small_pass(a2, aoffS + TXH, SM + SMW_MP2, lane);
        store_small(a2, (float*)(SM + M16_B), BIA + 896, true, wm4, lane);
    }
    __syncthreads();

    // ---- clifford: metric + adapted inner product -> ip into TX cols 128..143 ----
    if (tid < 64) {
        const float* M16 = (float*)(SM + M16_B);
        const float* SCS = (float*)(SM + SCS_B);
        const float* DCS = (float*)(SM + DCS_B);
        int r = tid;
        float m[16], s[16], d[16];
#pragma unroll
        for (int k = 0; k < 16; ++k) {
            m[k] = M16[r * 16 + k];
            s[k] = SCS[r * 16 + k];
            d[k] = DCS[r * 16 + k];
        }
        float L[4][4];
#pragma unroll
        for (int a = 0; a < 4; ++a)
#pragma unroll
            for (int b = 0; b < 4; ++b) {
                float mv = m[a * 4 + b];
                L[a][b] = (a > b) ? mv : (a == b) ? (log1pf(expf(mv)) + 1e-6f) : 0.f;
            }
        float met[4][4];
#pragma unroll
        for (int a = 0; a < 4; ++a)
#pragma unroll
            for (int b = 0; b < 4; ++b) {
                float q = 0.f;
#pragma unroll
                for (int c = 0; c < 4; ++c) q = fmaf(L[a][c], L[b][c], q);
                met[a][b] = q;
            }
        const int VI[4] = {1, 2, 4, 8};
        float sv[4], dv[4];
#pragma unroll
        for (int a = 0; a < 4; ++a) {
            float qs = 0.f, qd = 0.f;
#pragma unroll
            for (int b = 0; b < 4; ++b) {
                qs = fmaf(met[a][b], s[VI[b]], qs);
                qd = fmaf(met[a][b], d[VI[b]], qd);
            }
            sv[a] = qs; dv[a] = qd;
        }
#pragma unroll
        for (int a = 0; a < 4; ++a) { s[VI[a]] = sv[a]; d[VI[a]] = dv[a]; }
#pragma unroll
        for (int k = 0; k < 16; ++k) {
            float q = 0.f;
#pragma unroll
            for (int i = 0; i < 16; ++i) {
                int j = i ^ k;
                q = fmaf(GST[i * 16 + j], fmaf(s[i], d[j], d[i] * s[j]), q);
            }
            float ip = 0.5f * q, h, l;
            split_h(ip, h, l);
            *(__half*)(SM + TXH + (r * STRIDE + 128 + k) * 2) = __float2half_rn(h);
            *(__half*)(SM + TXL + (r * STRIDE + 128 + k) * 2) = __float2half_rn(l);
        }
    }
    __syncthreads();

    // ---- Q = src@qW (kept in registers), 1-pass (softmax-damped) ----
    float accQ[2][4][4];
    zero24(accQ);
    STAGE(RING1, 163840, 32768); cp_wait<1>(); __syncthreads();
    gemm_1<8>(accQ, aoff + TSH, SM + RING0, wn, lane);
    __syncthreads();

    // ---- K = dst@kW, 1-pass (softmax-damped) ----
    float accK[2][4][4];
    zero24(accK);
    STAGE(RING0, 196608, 32768); cp_wait<1>(); __syncthreads();
    gemm_1<8>(accK, aoff + TDH, SM + RING1, wn, lane);

    // ---- scores = (Q+qb).(K+kb)/4 per head (enh cancels in softmax) ----
    {
        const int rb = wm * 32 + (lane >> 2);
        const int m = lane & 3, m2 = m * 2;
#pragma unroll
        for (int e = 0; e < 2; ++e) {
            float pr[4];
#pragma unroll
            for (int t = 0; t < 2; ++t) {
                float pa = 0.f, pb = 0.f;
#pragma unroll
                for (int u = 0; u < 2; ++u) {
                    int nt = 2 * e + u, cb = wn * 32 + nt * 8 + m2;
                    float qb0 = BIA[384 + cb], qb1 = BIA[384 + cb + 1];
                    float kb0 = BIA[512 + cb], kb1 = BIA[512 + cb + 1];
                    pa += (accQ[t][nt][0] + qb0) * (accK[t][nt][0] + kb0)
                        + (accQ[t][nt][1] + qb1) * (accK[t][nt][1] + kb1);
                    pb += (accQ[t][nt][2] + qb0) * (accK[t][nt][2] + kb0)
                        + (accQ[t][nt][3] + qb1) * (accK[t][nt][3] + kb1);
                }
                pr[t * 2] = pa; pr[t * 2 + 1] = pb;
            }
#pragma unroll
            for (int j = 0; j < 4; ++j) {
                pr[j] += __shfl_xor_sync(0xFFFFFFFFu, pr[j], 1);
                pr[j] += __shfl_xor_sync(0xFFFFFFFFu, pr[j], 2);
            }
            if (m == 0) {
                int h = wn * 2 + e;
                SCO[rb * 8 + h]        = 0.25f * pr[0];
                SCO[(rb + 8) * 8 + h]  = 0.25f * pr[1];
                SCO[(rb + 16) * 8 + h] = 0.25f * pr[2];
                SCO[(rb + 24) * 8 + h] = 0.25f * pr[3];
            }
        }
    }
    __syncthreads();
    if (tid < 64) {
        float s0[8], mx = -1e30f;
#pragma unroll
        for (int h = 0; h < 8; ++h) { s0[h] = SCO[tid * 8 + h]; mx = fmaxf(mx, s0[h]); }
        float sum = 0.f;
#pragma unroll
        for (int h = 0; h < 8; ++h) { s0[h] = expf(s0[h] - mx); sum += s0[h]; }
        float inv = 1.f / sum;
#pragma unroll
        for (int h = 0; h < 8; ++h) SCO[tid * 8 + h] = s0[h] * inv;
    }
    __syncthreads();

    // ---- V = dst@vW ; att = w8*(V+vb) -> TX, 2-pass (direct path) ----
    zero24(acc);
    STAGE(RING1, 229376, 36864); cp_wait<1>(); __syncthreads();
    gemm_f<8>(acc, aoff + TDH, aoff + TDL, SM + RING0, wn, lane);
    __syncthreads();
    {
        const int rb = wm * 32 + (lane >> 2);
        const int m2 = (lane & 3) * 2;
#pragma unroll
        for (int t = 0; t < 2; ++t) {
            const int r1 = rb + t * 16, r2 = r1 + 8;
#pragma unroll
            for (int nt = 0; nt < 4; ++nt) {
                int cb = wn * 32 + nt * 8 + m2;
                int h = wn * 2 + (nt >> 1);
                float w1 = SCO[r1 * 8 + h], w2 = SCO[r2 * 8 + h];
                float b0 = BIA[640 + cb], b1 = BIA[640 + cb + 1];
                float v0 = (acc[t][nt][0] + b0) * w1, v1 = (acc[t][nt][1] + b1) * w1;
                float v2 = (acc[t][nt][2] + b0) * w2, v3 = (acc[t][nt][3] + b1) * w2;
                float h0, l0, h1, l1;
                split_h(v0, h0, l0); split_h(v1, h1, l1);
                *(uint32_t*)(SM + TXH + (r1 * STRIDE + cb) * 2) = pack_h2(h0, h1);
                *(uint32_t*)(SM + TXL + (r1 * STRIDE + cb) * 2) = pack_h2(l0, l1);
                split_h(v2, h0, l0); split_h(v3, h1, l1);
                *(uint32_t*)(SM + TXH + (r2 * STRIDE + cb) * 2) = pack_h2(h0, h1);
                *(uint32_t*)(SM + TXL + (r2 * STRIDE + cb) * 2) = pack_h2(l0, l1);
            }
        }
    }
    __syncthreads();

    // ---- out = [att|ip]@[outW;ctoW] + (outb+ctob), 9 k-tiles, 2-pass ----
    zero24(acc);
    cp_wait<0>(); __syncthreads();
    gemm_f<9>(acc, aoff + TXH, aoff + TXL, SM + RING1, wn, lane);
    {
        const int rb = wm * 32 + (lane >> 2);
        const int m2 = (lane & 3) * 2;
#pragma unroll
        for (int t = 0; t < 2; ++t) {
            const int r1 = rb + t * 16, r2 = r1 + 8;
#pragma unroll
            for (int nt = 0; nt < 4; ++nt) {
                int cb = wn * 32 + nt * 8 + m2;
                float b0 = BIA[768 + cb], b1 = BIA[768 + cb + 1];
                if (r1 < rows)
                    *(float2*)(p.out + (size_t)(row0 + r1) * 128 + cb) =
                        make_float2(acc[t][nt][0] + b0, acc[t][nt][1] + b1);
                if (r2 < rows)
                    *(float2*)(p.out + (size_t)(row0 + r2) * 128 + cb) =
                        make_float2(acc[t][nt][2] + b0, acc[t][nt][3] + b1);
            }
        }
    }
}

// ---------- launch ----------
extern "C" void kernel_launch(void* const* d_in, const int* in_sizes, int n_in,
                              void* d_out, int out_size)
{
    Params p;
    p.src = (const float*)d_in[0];
    p.dst = (const float*)d_in[1];
    p.edge = (const float*)d_in[2];
    p.im2b = (const float*)d_in[10];
    p.mp1b = (const float*)d_in[12];
    p.mp2b = (const float*)d_in[14];
    p.qb   = (const float*)d_in[16];
    p.kb   = (const float*)d_in[18];
    p.vb   = (const float*)d_in[20];
    p.ntcb = (const float*)d_in[22];
    p.ctob = (const float*)d_in[24];
    p.outb = (const float*)d_in[26];
    p.out = (float*)d_out;
    p.B = in_sizes[0] / 128;

    PrepAll pa;
    pa.npW  = (const float*)d_in[3];
    pa.npb  = (const float*)d_in[4];
    pa.epW  = (const float*)d_in[5];
    pa.epb  = (const float*)d_in[6];
    pa.im1W = (const float*)d_in[7];
    pa.im1b = (const float*)d_in[8];
    pa.im2W = (const float*)d_in[9];
    pa.mp1W = (const float*)d_in[11];
    pa.qW   = (const float*)d_in[15];
    pa.kW   = (const float*)d_in[17];
    pa.vW   = (const float*)d_in[19];
    pa.outW = (const float*)d_in[25];
    pa.ctoW = (const float*)d_in[23];
    pa.mp2W = (const float*)d_in[13];
    pa.ntcW = (const float*)d_in[21];

    cudaFuncSetAttribute(fused_kernel, cudaFuncAttributeMaxDynamicSharedMemorySize, SMEM_BYTES);

    prep_all<<<136, 512>>>(pa);
    fused_kernel<<<(p.B + 63) / 64, 256, SMEM_BYTES>>>(p);
}